// round 1
// baseline (speedup 1.0000x reference)
#include <cuda_runtime.h>
#include <math.h>

// Problem constants (fixed shapes from setup_inputs)
#define T_FR   4
#define NQ     4096
#define DD     1024
#define NS     2048
#define HH     3
#define PP     256
#define CC     100
#define NH     (HH * PP)       // 768
#define NTOT   (NH + CC)       // 868
#define EPSN   1e-8f

// ---------------- scratch (device globals; no allocation allowed) ----------
__device__ float g_agg[NQ * DD];     // mean over frames        16 MB
__device__ float g_W[DD * NTOT];     // packed weights          3.5 MB
__device__ float g_bias[NTOT];       // packed bias
__device__ float g_Q[NQ * NH];       // query projections       12 MB
__device__ float g_S[NS * NH];       // support projections     6 MB

// ---------------- kernel 1: mean over T frames -----------------------------
__global__ void mean_kernel(const float* __restrict__ q) {
    int i = blockIdx.x * blockDim.x + threadIdx.x;
    const int n4 = (NQ * DD) / 4;
    if (i >= n4) return;
    const float4* p = reinterpret_cast<const float4*>(q);
    float4 a = p[i];
    float4 b = p[i + n4];
    float4 c = p[i + 2 * n4];
    float4 d = p[i + 3 * n4];
    float4 o;
    o.x = 0.25f * (a.x + b.x + c.x + d.x);
    o.y = 0.25f * (a.y + b.y + c.y + d.y);
    o.z = 0.25f * (a.z + b.z + c.z + d.z);
    o.w = 0.25f * (a.w + b.w + c.w + d.w);
    reinterpret_cast<float4*>(g_agg)[i] = o;
}

// ---------------- kernel 2: pack head_W + cls_W into [DD, NTOT] ------------
__global__ void pack_kernel(const float* __restrict__ hW,
                            const float* __restrict__ hb,
                            const float* __restrict__ cW,
                            const float* __restrict__ cb) {
    int i = blockIdx.x * blockDim.x + threadIdx.x;
    const int total = DD * NTOT;
    if (i < total) {
        int k = i / NTOT;
        int j = i - k * NTOT;
        float v;
        if (j < NH) {
            int h = j >> 8;        // j / 256
            int p = j & 255;       // j % 256
            v = hW[(h * DD + k) * PP + p];
        } else {
            v = cW[k * CC + (j - NH)];
        }
        g_W[i] = v;
    }
    if (i < NTOT) {
        g_bias[i] = (i < NH) ? hb[i] : cb[i - NH];
    }
}

// ---------------- kernel 3: SGEMM NN, C = A[M,DD] @ g_W[DD,N] + bias -------
// 128x128 tile, BK=8, 256 threads, 8x8 per thread.
// Columns < NH go to Chead (ld NH); columns >= NH go to Ccls (ld CC).
__global__ __launch_bounds__(256, 2)
void sgemm_nn_kernel(const float* __restrict__ A,
                     float* __restrict__ Chead,
                     float* __restrict__ Ccls,
                     int N) {
    __shared__ float As[8][128];
    __shared__ float Bs[8][128];

    const int tid = threadIdx.x;
    const int tx = tid & 15;         // 0..15  (n dir)
    const int ty = tid >> 4;         // 0..15  (m dir)
    const int row0 = blockIdx.y * 128;
    const int col0 = blockIdx.x * 128;

    // A loader: one float4 per thread: row = tid/2, 4 k-values
    const int aRow = tid >> 1;
    const int aq   = (tid & 1) * 4;
    // B loader: one float4 per thread: k-row = tid/32, 4 n-values
    const int bRow = tid >> 5;
    const int bc   = (tid & 31) * 4;
    const bool bvalid = (col0 + bc + 4) <= N;

    const float* Aptr = A + (size_t)(row0 + aRow) * DD + aq;
    const float* Wptr = g_W + (size_t)bRow * NTOT + col0 + bc;

    float acc[8][8];
#pragma unroll
    for (int i = 0; i < 8; ++i)
#pragma unroll
        for (int j = 0; j < 8; ++j) acc[i][j] = 0.0f;

    for (int kt = 0; kt < DD; kt += 8) {
        float4 av = *reinterpret_cast<const float4*>(Aptr + kt);
        float4 bv = make_float4(0.f, 0.f, 0.f, 0.f);
        if (bvalid) bv = *reinterpret_cast<const float4*>(Wptr + (size_t)kt * NTOT);

        As[aq + 0][aRow] = av.x;
        As[aq + 1][aRow] = av.y;
        As[aq + 2][aRow] = av.z;
        As[aq + 3][aRow] = av.w;
        *reinterpret_cast<float4*>(&Bs[bRow][bc]) = bv;
        __syncthreads();

#pragma unroll
        for (int k = 0; k < 8; ++k) {
            float a[8], b[8];
            *reinterpret_cast<float4*>(&a[0]) = *reinterpret_cast<const float4*>(&As[k][ty * 8]);
            *reinterpret_cast<float4*>(&a[4]) = *reinterpret_cast<const float4*>(&As[k][ty * 8 + 4]);
            *reinterpret_cast<float4*>(&b[0]) = *reinterpret_cast<const float4*>(&Bs[k][tx * 8]);
            *reinterpret_cast<float4*>(&b[4]) = *reinterpret_cast<const float4*>(&Bs[k][tx * 8 + 4]);
#pragma unroll
            for (int i = 0; i < 8; ++i)
#pragma unroll
                for (int j = 0; j < 8; ++j)
                    acc[i][j] = fmaf(a[i], b[j], acc[i][j]);
        }
        __syncthreads();
    }

#pragma unroll
    for (int i = 0; i < 8; ++i) {
        int row = row0 + ty * 8 + i;
#pragma unroll
        for (int j = 0; j < 8; ++j) {
            int col = col0 + tx * 8 + j;
            if (col < N) {
                float v = acc[i][j] + g_bias[col];
                if (col < NH)
                    Chead[(size_t)row * NH + col] = v;
                else
                    Ccls[(size_t)row * CC + (col - NH)] = v;
            }
        }
    }
}

// ---------------- kernel 4: per-(row, head) L2 normalize (in place) --------
// scale = extra / max(||x||, 1e-8); extra = 1/H for Q (folds mean over heads)
__global__ void normalize_kernel(float* __restrict__ X, int rows, float extra) {
    int wid = (blockIdx.x * blockDim.x + threadIdx.x) >> 5;
    int lane = threadIdx.x & 31;
    int total = rows * HH;
    if (wid >= total) return;
    int n = wid / HH;
    int h = wid - n * HH;
    float* p = X + (size_t)n * NH + h * PP;
    float4* p4 = reinterpret_cast<float4*>(p);
    float4 v0 = p4[lane];
    float4 v1 = p4[lane + 32];
    float ss = v0.x * v0.x + v0.y * v0.y + v0.z * v0.z + v0.w * v0.w
             + v1.x * v1.x + v1.y * v1.y + v1.z * v1.z + v1.w * v1.w;
#pragma unroll
    for (int off = 16; off > 0; off >>= 1)
        ss += __shfl_xor_sync(0xffffffffu, ss, off);
    float s = extra / fmaxf(sqrtf(ss), EPSN);
    v0.x *= s; v0.y *= s; v0.z *= s; v0.w *= s;
    v1.x *= s; v1.y *= s; v1.z *= s; v1.w *= s;
    p4[lane] = v0;
    p4[lane + 32] = v1;
}

// ---------------- kernel 5: SGEMM NT, C = Qn[NQ,NH] @ Sn[NS,NH]^T ----------
__global__ __launch_bounds__(256, 2)
void sgemm_nt_kernel(float* __restrict__ C) {
    __shared__ float As[8][128];
    __shared__ float Bs[8][128];

    const int tid = threadIdx.x;
    const int tx = tid & 15;
    const int ty = tid >> 4;
    const int row0 = blockIdx.y * 128;
    const int col0 = blockIdx.x * 128;

    const int lRow = tid >> 1;        // 0..127
    const int lq   = (tid & 1) * 4;   // 0 or 4

    const float* Aptr = g_Q + (size_t)(row0 + lRow) * NH + lq;
    const float* Bptr = g_S + (size_t)(col0 + lRow) * NH + lq;

    float acc[8][8];
#pragma unroll
    for (int i = 0; i < 8; ++i)
#pragma unroll
        for (int j = 0; j < 8; ++j) acc[i][j] = 0.0f;

    for (int kt = 0; kt < NH; kt += 8) {
        float4 av = *reinterpret_cast<const float4*>(Aptr + kt);
        float4 bv = *reinterpret_cast<const float4*>(Bptr + kt);

        As[lq + 0][lRow] = av.x;
        As[lq + 1][lRow] = av.y;
        As[lq + 2][lRow] = av.z;
        As[lq + 3][lRow] = av.w;
        Bs[lq + 0][lRow] = bv.x;
        Bs[lq + 1][lRow] = bv.y;
        Bs[lq + 2][lRow] = bv.z;
        Bs[lq + 3][lRow] = bv.w;
        __syncthreads();

#pragma unroll
        for (int k = 0; k < 8; ++k) {
            float a[8], b[8];
            *reinterpret_cast<float4*>(&a[0]) = *reinterpret_cast<const float4*>(&As[k][ty * 8]);
            *reinterpret_cast<float4*>(&a[4]) = *reinterpret_cast<const float4*>(&As[k][ty * 8 + 4]);
            *reinterpret_cast<float4*>(&b[0]) = *reinterpret_cast<const float4*>(&Bs[k][tx * 8]);
            *reinterpret_cast<float4*>(&b[4]) = *reinterpret_cast<const float4*>(&Bs[k][tx * 8 + 4]);
#pragma unroll
            for (int i = 0; i < 8; ++i)
#pragma unroll
                for (int j = 0; j < 8; ++j)
                    acc[i][j] = fmaf(a[i], b[j], acc[i][j]);
        }
        __syncthreads();
    }

#pragma unroll
    for (int i = 0; i < 8; ++i) {
        int row = row0 + ty * 8 + i;
        float* crow = C + (size_t)row * NS + col0 + tx * 8;
        *reinterpret_cast<float4*>(crow)     = *reinterpret_cast<float4*>(&acc[i][0]);
        *reinterpret_cast<float4*>(crow + 4) = *reinterpret_cast<float4*>(&acc[i][4]);
    }
}

// ---------------- launch ----------------------------------------------------
extern "C" void kernel_launch(void* const* d_in, const int* in_sizes, int n_in,
                              void* d_out, int out_size) {
    const float* query   = (const float*)d_in[0];  // [T, NQ, DD]
    const float* support = (const float*)d_in[1];  // [NS, DD]
    const float* head_W  = (const float*)d_in[2];  // [HH, DD, PP]
    const float* head_b  = (const float*)d_in[3];  // [HH, PP]
    const float* cls_W   = (const float*)d_in[4];  // [DD, CC]
    const float* cls_b   = (const float*)d_in[5];  // [CC]

    float* out_match = (float*)d_out;                      // [NQ, NS]
    float* out_preds = (float*)d_out + (size_t)NQ * NS;    // [NS, CC]

    float* agg; float* Q; float* S;
    cudaGetSymbolAddress((void**)&agg, g_agg);
    cudaGetSymbolAddress((void**)&Q,   g_Q);
    cudaGetSymbolAddress((void**)&S,   g_S);

    // 1) mean over frames
    {
        int n4 = (NQ * DD) / 4;
        mean_kernel<<<(n4 + 255) / 256, 256>>>(query);
    }
    // 2) pack weights + bias
    {
        int total = DD * NTOT;
        pack_kernel<<<(total + 255) / 256, 256>>>(head_W, head_b, cls_W, cls_b);
    }
    // 3) Q projection: [NQ, DD] x [DD, NH]
    {
        dim3 grid((NH + 127) / 128, NQ / 128);
        sgemm_nn_kernel<<<grid, 256>>>(agg, Q, nullptr, NH);
    }
    // 4) S projection + classifier: [NS, DD] x [DD, NTOT]
    {
        dim3 grid((NTOT + 127) / 128, NS / 128);
        sgemm_nn_kernel<<<grid, 256>>>(support, S, out_preds, NTOT);
    }
    // 5) normalize (fold 1/H into Q)
    {
        int warpsQ = NQ * HH;
        normalize_kernel<<<(warpsQ * 32 + 255) / 256, 256>>>(Q, NQ, 1.0f / (float)HH);
        int warpsS = NS * HH;
        normalize_kernel<<<(warpsS * 32 + 255) / 256, 256>>>(S, NS, 1.0f);
    }
    // 6) match GEMM: [NQ, NH] x [NS, NH]^T
    {
        dim3 grid(NS / 128, NQ / 128);
        sgemm_nt_kernel<<<grid, 256>>>(out_match);
    }
}

// round 3
// speedup vs baseline: 2.3392x; 2.3392x over previous
#include <cuda_runtime.h>
#include <cuda_bf16.h>
#include <cstdint>
#include <math.h>

// ---------------- problem constants ----------------------------------------
#define NQ     4096
#define DD     1024
#define NS     2048
#define HH     3
#define PP     256
#define CC     100
#define NH     768
#define NTOT   868
#define EPSN   1e-8f

// ---------------- GEMM tiling ----------------------------------------------
#define BM     128
#define BN     128
#define BK     32
#define PITCHB 80
#define PARTB  (BM * PITCHB)
#define STAGEB (4 * PARTB)
#define SMEMB  (2 * STAGEB)    // 81920 bytes

// ---------------- scratch --------------------------------------------------
__device__ uint16_t g_Aggh[NQ * DD], g_Aggl[NQ * DD];
__device__ uint16_t g_Suph[NS * DD], g_Supl[NS * DD];
__device__ uint16_t g_Wth[NTOT * DD], g_Wtl[NTOT * DD];
__device__ float    g_bias[NTOT];
__device__ float    g_Qf[NQ * NH];
__device__ float    g_Sf[NS * NH];
__device__ uint16_t g_Qh[NQ * NH], g_Ql[NQ * NH];
__device__ uint16_t g_Sh[NS * NH], g_Sl[NS * NH];

// ---------------- helpers ----------------------------------------------------
__device__ __forceinline__ uint32_t smem_u32_of(const void* p) {
    uint32_t a;
    asm("{ .reg .u64 t; cvta.to.shared.u64 t, %1; cvt.u32.u64 %0, t; }"
        : "=r"(a) : "l"(p));
    return a;
}

__device__ __forceinline__ uint32_t lds32(uint32_t a) {
    uint32_t v;
    asm volatile("ld.shared.b32 %0, [%1];" : "=r"(v) : "r"(a));
    return v;
}

__device__ __forceinline__ void split1(float x, uint16_t& h, uint16_t& l) {
    uint32_t b = __float_as_uint(x);
    h = (uint16_t)(b >> 16);
    float r = x - __uint_as_float(b & 0xffff0000u);
    asm("{ .reg .b16 t; cvt.rn.bf16.f32 t, %1; mov.b16 %0, t; }" : "=h"(l) : "f"(r));
}

__device__ __forceinline__ void mma_bf16(float* c, const uint32_t* a,
                                         uint32_t b0, uint32_t b1) {
    asm volatile(
        "mma.sync.aligned.m16n8k16.row.col.f32.bf16.bf16.f32 "
        "{%0,%1,%2,%3}, {%4,%5,%6,%7}, {%8,%9}, {%0,%1,%2,%3};"
        : "+f"(c[0]), "+f"(c[1]), "+f"(c[2]), "+f"(c[3])
        : "r"(a[0]), "r"(a[1]), "r"(a[2]), "r"(a[3]), "r"(b0), "r"(b1));
}

// ---------------- kernel 1: mean over frames + split -------------------------
__global__ void mean_kernel(const float* __restrict__ q) {
    int i = blockIdx.x * blockDim.x + threadIdx.x;
    const int n4 = (NQ * DD) / 4;
    if (i >= n4) return;
    const float4* p = reinterpret_cast<const float4*>(q);
    float4 a = p[i], b = p[i + n4], c = p[i + 2 * n4], d = p[i + 3 * n4];
    float v0 = 0.25f * (a.x + b.x + c.x + d.x);
    float v1 = 0.25f * (a.y + b.y + c.y + d.y);
    float v2 = 0.25f * (a.z + b.z + c.z + d.z);
    float v3 = 0.25f * (a.w + b.w + c.w + d.w);
    ushort4 hs, ls;
    split1(v0, hs.x, ls.x); split1(v1, hs.y, ls.y);
    split1(v2, hs.z, ls.z); split1(v3, hs.w, ls.w);
    reinterpret_cast<ushort4*>(g_Aggh)[i] = hs;
    reinterpret_cast<ushort4*>(g_Aggl)[i] = ls;
}

// ---------------- kernel 1b: split support ----------------------------------
__global__ void split_support_kernel(const float* __restrict__ s) {
    int i = blockIdx.x * blockDim.x + threadIdx.x;
    const int n4 = (NS * DD) / 4;
    if (i >= n4) return;
    float4 v = reinterpret_cast<const float4*>(s)[i];
    ushort4 hs, ls;
    split1(v.x, hs.x, ls.x); split1(v.y, hs.y, ls.y);
    split1(v.z, hs.z, ls.z); split1(v.w, hs.w, ls.w);
    reinterpret_cast<ushort4*>(g_Suph)[i] = hs;
    reinterpret_cast<ushort4*>(g_Supl)[i] = ls;
}

// ---------------- kernel 2: pack W^T + bias + split ---------------------------
__global__ void pack_kernel(const float* __restrict__ hW,
                            const float* __restrict__ hb,
                            const float* __restrict__ cW,
                            const float* __restrict__ cb) {
    int i = blockIdx.x * blockDim.x + threadIdx.x;
    if (i < NTOT * DD) {
        int n = i >> 10;
        int k = i & 1023;
        float v;
        if (n < NH) {
            int h = n >> 8;
            int p = n & 255;
            v = hW[((size_t)h * DD + k) * PP + p];
        } else {
            v = cW[(size_t)k * CC + (n - NH)];
        }
        uint16_t hh, ll;
        split1(v, hh, ll);
        g_Wth[i] = hh;
        g_Wtl[i] = ll;
    }
    if (i < NTOT) g_bias[i] = (i < NH) ? hb[i] : cb[i - NH];
}

// ---------------- kernel 3: bf16x3 HMMA GEMM (NT) ------------------------------
__global__ void gemm3x_kernel(const uint16_t* __restrict__ Ah,
                              const uint16_t* __restrict__ Al,
                              const uint16_t* __restrict__ Bh,
                              const uint16_t* __restrict__ Bl,
                              int K, int Ncols, const float* __restrict__ bias,
                              float* __restrict__ Chead, int ld_head,
                              float* __restrict__ Ccls, int colsplit) {
    extern __shared__ __align__(128) char smem[];
    const uint32_t smbase = smem_u32_of(smem);

    const int tid = threadIdx.x;
    const int lane = tid & 31;
    const int wid = tid >> 5;
    const int wm = wid >> 1;
    const int wn = wid & 1;
    const int g = lane >> 2;
    const int t = lane & 3;
    const int row0 = blockIdx.y * BM;
    const int col0 = blockIdx.x * BN;
    const int nchunk = K / BK;

    float acc[2][8][4];
#pragma unroll
    for (int mi = 0; mi < 2; ++mi)
#pragma unroll
        for (int ni = 0; ni < 8; ++ni)
#pragma unroll
            for (int j = 0; j < 4; ++j) acc[mi][ni][j] = 0.0f;

    auto load_chunk = [&](int c, int s) {
        const uint32_t st = smbase + (uint32_t)s * STAGEB;
        const int k0 = c * BK;
#pragma unroll
        for (int j = 0; j < 8; ++j) {
            int cidx = tid + 256 * j;
            int part = cidx >> 9;
            int within = cidx & 511;
            int r = within >> 2;
            int q = within & 3;
            uint32_t dst = st + (uint32_t)part * PARTB + r * PITCHB + q * 16;
            const uint16_t* src;
            int sz = 16;
            if (part == 0) {
                src = Ah + (size_t)(row0 + r) * K + k0 + q * 8;
            } else if (part == 1) {
                src = Al + (size_t)(row0 + r) * K + k0 + q * 8;
            } else {
                const uint16_t* base = (part == 2) ? Bh : Bl;
                int n = col0 + r;
                if (n < Ncols) {
                    src = base + (size_t)n * K + k0 + q * 8;
                } else {
                    src = base;
                    sz = 0;
                }
            }
            asm volatile("cp.async.cg.shared.global [%0], [%1], 16, %2;"
                         :: "r"(dst), "l"(src), "r"(sz) : "memory");
        }
        asm volatile("cp.async.commit_group;" ::: "memory");
    };

    load_chunk(0, 0);

    for (int c = 0; c < nchunk; ++c) {
        const int s = c & 1;
        if (c + 1 < nchunk) {
            load_chunk(c + 1, s ^ 1);
            asm volatile("cp.async.wait_group 1;" ::: "memory");
        } else {
            asm volatile("cp.async.wait_group 0;" ::: "memory");
        }
        __syncthreads();

        const uint32_t sA = smbase + (uint32_t)s * STAGEB;
        const uint32_t sAh = sA;
        const uint32_t sAl = sA + PARTB;
        const uint32_t sBh = sA + 2 * PARTB;
        const uint32_t sBl = sA + 3 * PARTB;

#pragma unroll
        for (int kk = 0; kk < 2; ++kk) {
            const uint32_t kbyte = (uint32_t)(kk * 16 + 2 * t) * 2;
            uint32_t ah[2][4], al[2][4];
#pragma unroll
            for (int mi = 0; mi < 2; ++mi) {
                uint32_t off = (uint32_t)(wm * 32 + mi * 16 + g) * PITCHB + kbyte;
                ah[mi][0] = lds32(sAh + off);
                ah[mi][1] = lds32(sAh + off + 8 * PITCHB);
                ah[mi][2] = lds32(sAh + off + 16);
                ah[mi][3] = lds32(sAh + off + 8 * PITCHB + 16);
                al[mi][0] = lds32(sAl + off);
                al[mi][1] = lds32(sAl + off + 8 * PITCHB);
                al[mi][2] = lds32(sAl + off + 16);
                al[mi][3] = lds32(sAl + off + 8 * PITCHB + 16);
            }
#pragma unroll
            for (int ni = 0; ni < 8; ++ni) {
                uint32_t boff = (uint32_t)(wn * 64 + ni * 8 + g) * PITCHB + kbyte;
                uint32_t bh0 = lds32(sBh + boff);
                uint32_t bh1 = lds32(sBh + boff + 16);
                uint32_t bl0 = lds32(sBl + boff);
                uint32_t bl1 = lds32(sBl + boff + 16);
#pragma unroll
                for (int mi = 0; mi < 2; ++mi) {
                    mma_bf16(acc[mi][ni], ah[mi], bh0, bh1);
                    mma_bf16(acc[mi][ni], ah[mi], bl0, bl1);
                    mma_bf16(acc[mi][ni], al[mi], bh0, bh1);
                }
            }
        }
        __syncthreads();
    }

    const bool has_bias = (bias != nullptr);
#pragma unroll
    for (int mi = 0; mi < 2; ++mi) {
        int r = row0 + wm * 32 + mi * 16 + g;
#pragma unroll
        for (int ni = 0; ni < 8; ++ni) {
            int cb = col0 + wn * 64 + ni * 8 + 2 * t;
            if (cb >= Ncols) continue;
            float b0 = has_bias ? bias[cb] : 0.0f;
            float b1 = (has_bias && (cb + 1) < Ncols) ? bias[cb + 1] : 0.0f;
            float v00 = acc[mi][ni][0] + b0;
            float v01 = acc[mi][ni][1] + b1;
            float v10 = acc[mi][ni][2] + b0;
            float v11 = acc[mi][ni][3] + b1;
            if (cb + 1 < colsplit) {
                float2* d0 = reinterpret_cast<float2*>(Chead + (size_t)r * ld_head + cb);
                float2* d1 = reinterpret_cast<float2*>(Chead + (size_t)(r + 8) * ld_head + cb);
                *d0 = make_float2(v00, v01);
                *d1 = make_float2(v10, v11);
            } else {
                for (int jj = 0; jj < 2; ++jj) {
                    int col = cb + jj;
                    if (col >= Ncols) break;
                    float va = (jj == 0) ? v00 : v01;
                    float vb = (jj == 0) ? v10 : v11;
                    if (col < colsplit) {
                        Chead[(size_t)r * ld_head + col] = va;
                        Chead[(size_t)(r + 8) * ld_head + col] = vb;
                    } else {
                        Ccls[(size_t)r * CC + (col - colsplit)] = va;
                        Ccls[(size_t)(r + 8) * CC + (col - colsplit)] = vb;
                    }
                }
            }
        }
    }
}

// ---------------- kernel 4: L2 normalize + split to bf16 ---------------------
__global__ void normalize_kernel(const float* __restrict__ X,
                                 uint16_t* __restrict__ Xh,
                                 uint16_t* __restrict__ Xl,
                                 int rows, float extra) {
    int wwid = (blockIdx.x * blockDim.x + threadIdx.x) >> 5;
    int lane = threadIdx.x & 31;
    int total = rows * HH;
    if (wwid >= total) return;
    int n = wwid / HH;
    int h = wwid - n * HH;
    size_t base = (size_t)n * NH + h * PP;
    const float4* p4 = reinterpret_cast<const float4*>(X + base);
    float4 v0 = p4[lane];
    float4 v1 = p4[lane + 32];
    float ss = v0.x * v0.x + v0.y * v0.y + v0.z * v0.z + v0.w * v0.w
             + v1.x * v1.x + v1.y * v1.y + v1.z * v1.z + v1.w * v1.w;
#pragma unroll
    for (int off = 16; off > 0; off >>= 1)
        ss += __shfl_xor_sync(0xffffffffu, ss, off);
    float s = extra / fmaxf(sqrtf(ss), EPSN);
    float a0 = v0.x * s, a1 = v0.y * s, a2 = v0.z * s, a3 = v0.w * s;
    float a4 = v1.x * s, a5 = v1.y * s, a6 = v1.z * s, a7 = v1.w * s;
    ushort4 h0, l0, h1, l1;
    split1(a0, h0.x, l0.x); split1(a1, h0.y, l0.y);
    split1(a2, h0.z, l0.z); split1(a3, h0.w, l0.w);
    split1(a4, h1.x, l1.x); split1(a5, h1.y, l1.y);
    split1(a6, h1.z, l1.z); split1(a7, h1.w, l1.w);
    ushort4* ph = reinterpret_cast<ushort4*>(Xh + base);
    ushort4* pl = reinterpret_cast<ushort4*>(Xl + base);
    ph[lane] = h0; ph[lane + 32] = h1;
    pl[lane] = l0; pl[lane + 32] = l1;
}

// ---------------- launch -------------------------------------------------------
extern "C" void kernel_launch(void* const* d_in, const int* in_sizes, int n_in,
                              void* d_out, int out_size) {
    const float* query   = (const float*)d_in[0];
    const float* support = (const float*)d_in[1];
    const float* head_W  = (const float*)d_in[2];
    const float* head_b  = (const float*)d_in[3];
    const float* cls_W   = (const float*)d_in[4];
    const float* cls_b   = (const float*)d_in[5];

    float* out_match = (float*)d_out;
    float* out_preds = (float*)d_out + (size_t)NQ * NS;

    uint16_t *Aggh, *Aggl, *Suph, *Supl, *Wth, *Wtl, *Qh, *Ql, *Sh, *Sl;
    float *bias, *Qf, *Sf;
    cudaGetSymbolAddress((void**)&Aggh, g_Aggh);
    cudaGetSymbolAddress((void**)&Aggl, g_Aggl);
    cudaGetSymbolAddress((void**)&Suph, g_Suph);
    cudaGetSymbolAddress((void**)&Supl, g_Supl);
    cudaGetSymbolAddress((void**)&Wth,  g_Wth);
    cudaGetSymbolAddress((void**)&Wtl,  g_Wtl);
    cudaGetSymbolAddress((void**)&bias, g_bias);
    cudaGetSymbolAddress((void**)&Qf,   g_Qf);
    cudaGetSymbolAddress((void**)&Sf,   g_Sf);
    cudaGetSymbolAddress((void**)&Qh,   g_Qh);
    cudaGetSymbolAddress((void**)&Ql,   g_Ql);
    cudaGetSymbolAddress((void**)&Sh,   g_Sh);
    cudaGetSymbolAddress((void**)&Sl,   g_Sl);

    cudaFuncSetAttribute(gemm3x_kernel,
                         cudaFuncAttributeMaxDynamicSharedMemorySize, SMEMB);

    // 1) mean over frames (+ split) and support split
    {
        int n4 = (NQ * DD) / 4;
        mean_kernel<<<(n4 + 255) / 256, 256>>>(query);
        int s4 = (NS * DD) / 4;
        split_support_kernel<<<(s4 + 255) / 256, 256>>>(support);
    }
    // 2) pack W^T + bias (+ split)
    {
        int total = NTOT * DD;
        pack_kernel<<<(total + 255) / 256, 256>>>(head_W, head_b, cls_W, cls_b);
    }
    // 3) Q projection: [4096,1024] @ Wt[0:768]^T -> g_Qf
    {
        dim3 grid(NH / BN, NQ / BM);
        gemm3x_kernel<<<grid, 256, SMEMB>>>(Aggh, Aggl, Wth, Wtl, DD, NH, bias,
                                            Qf, NH, nullptr, NH);
    }
    // 4) S projection + classifier: [2048,1024] @ Wt[0:868]^T
    {
        dim3 grid((NTOT + BN - 1) / BN, NS / BM);
        gemm3x_kernel<<<grid, 256, SMEMB>>>(Suph, Supl, Wth, Wtl, DD, NTOT, bias,
                                            Sf, NH, out_preds, NH);
    }
    // 5) normalize + split (fold 1/H into Q)
    {
        int warpsQ = NQ * HH;
        normalize_kernel<<<(warpsQ * 32 + 255) / 256, 256>>>(Qf, Qh, Ql, NQ,
                                                             1.0f / (float)HH);
        int warpsS = NS * HH;
        normalize_kernel<<<(warpsS * 32 + 255) / 256, 256>>>(Sf, Sh, Sl, NS, 1.0f);
    }
    // 6) match GEMM: [4096,768] @ [2048,768]^T -> out_match
    {
        dim3 grid(NS / BN, NQ / BM);
        gemm3x_kernel<<<grid, 256, SMEMB>>>(Qh, Ql, Sh, Sl, NH, NS, nullptr,
                                            out_match, NS, nullptr, NS);
    }
}

// round 4
// speedup vs baseline: 2.4101x; 1.0303x over previous
#include <cuda_runtime.h>
#include <cuda_bf16.h>
#include <cstdint>
#include <math.h>

// ---------------- problem constants ----------------------------------------
#define NQ     4096
#define DD     1024
#define NS     2048
#define HH     3
#define PP     256
#define CC     100
#define NH     768
#define NTOT   868
#define EPSN   1e-8f

// ---------------- GEMM tiling ----------------------------------------------
#define BM     128
#define BN     128
#define BK     32
#define PITCHB 80
#define PARTB  (BM * PITCHB)
#define STAGEB (4 * PARTB)       // Ah | Al | Bh | Bl  (40960 B)
#define NSTAGE 3
#define SMEMB  (NSTAGE * STAGEB) // 122880 B

// ---------------- scratch --------------------------------------------------
__device__ uint16_t g_Aggh[NQ * DD], g_Aggl[NQ * DD];
__device__ uint16_t g_Suph[NS * DD], g_Supl[NS * DD];
__device__ uint16_t g_Wth[NTOT * DD], g_Wtl[NTOT * DD];
__device__ float    g_bias[NTOT];
__device__ float    g_Qf[NQ * NH];
__device__ float    g_Sf[NS * NH];
__device__ uint16_t g_Qh[NQ * NH], g_Ql[NQ * NH];
__device__ uint16_t g_Sh[NS * NH], g_Sl[NS * NH];

// ---------------- helpers ----------------------------------------------------
__device__ __forceinline__ uint32_t smem_u32_of(const void* p) {
    uint32_t a;
    asm("{ .reg .u64 t; cvta.to.shared.u64 t, %1; cvt.u32.u64 %0, t; }"
        : "=r"(a) : "l"(p));
    return a;
}

__device__ __forceinline__ void ldsm4(uint32_t addr, uint32_t* r) {
    asm volatile("ldmatrix.sync.aligned.m8n8.x4.shared.b16 {%0,%1,%2,%3}, [%4];"
                 : "=r"(r[0]), "=r"(r[1]), "=r"(r[2]), "=r"(r[3]) : "r"(addr));
}

__device__ __forceinline__ void split1(float x, uint16_t& h, uint16_t& l) {
    uint32_t b = __float_as_uint(x);
    h = (uint16_t)(b >> 16);
    float r = x - __uint_as_float(b & 0xffff0000u);
    asm("{ .reg .b16 t; cvt.rn.bf16.f32 t, %1; mov.b16 %0, t; }" : "=h"(l) : "f"(r));
}

__device__ __forceinline__ void mma_bf16(float* c, const uint32_t* a,
                                         uint32_t b0, uint32_t b1) {
    asm volatile(
        "mma.sync.aligned.m16n8k16.row.col.f32.bf16.bf16.f32 "
        "{%0,%1,%2,%3}, {%4,%5,%6,%7}, {%8,%9}, {%0,%1,%2,%3};"
        : "+f"(c[0]), "+f"(c[1]), "+f"(c[2]), "+f"(c[3])
        : "r"(a[0]), "r"(a[1]), "r"(a[2]), "r"(a[3]), "r"(b0), "r"(b1));
}

// ---------------- kernel 1: mean over frames + split -------------------------
__global__ void mean_kernel(const float* __restrict__ q) {
    int i = blockIdx.x * blockDim.x + threadIdx.x;
    const int n4 = (NQ * DD) / 4;
    if (i >= n4) return;
    const float4* p = reinterpret_cast<const float4*>(q);
    float4 a = p[i], b = p[i + n4], c = p[i + 2 * n4], d = p[i + 3 * n4];
    float v0 = 0.25f * (a.x + b.x + c.x + d.x);
    float v1 = 0.25f * (a.y + b.y + c.y + d.y);
    float v2 = 0.25f * (a.z + b.z + c.z + d.z);
    float v3 = 0.25f * (a.w + b.w + c.w + d.w);
    ushort4 hs, ls;
    split1(v0, hs.x, ls.x); split1(v1, hs.y, ls.y);
    split1(v2, hs.z, ls.z); split1(v3, hs.w, ls.w);
    reinterpret_cast<ushort4*>(g_Aggh)[i] = hs;
    reinterpret_cast<ushort4*>(g_Aggl)[i] = ls;
}

// ---------------- kernel 1b: split support ----------------------------------
__global__ void split_support_kernel(const float* __restrict__ s) {
    int i = blockIdx.x * blockDim.x + threadIdx.x;
    const int n4 = (NS * DD) / 4;
    if (i >= n4) return;
    float4 v = reinterpret_cast<const float4*>(s)[i];
    ushort4 hs, ls;
    split1(v.x, hs.x, ls.x); split1(v.y, hs.y, ls.y);
    split1(v.z, hs.z, ls.z); split1(v.w, hs.w, ls.w);
    reinterpret_cast<ushort4*>(g_Suph)[i] = hs;
    reinterpret_cast<ushort4*>(g_Supl)[i] = ls;
}

// ---------------- kernel 2: pack W^T + bias + split ---------------------------
__global__ void pack_kernel(const float* __restrict__ hW,
                            const float* __restrict__ hb,
                            const float* __restrict__ cW,
                            const float* __restrict__ cb) {
    int i = blockIdx.x * blockDim.x + threadIdx.x;
    if (i < NTOT * DD) {
        int n = i >> 10;
        int k = i & 1023;
        float v;
        if (n < NH) {
            int h = n >> 8;
            int p = n & 255;
            v = hW[((size_t)h * DD + k) * PP + p];
        } else {
            v = cW[(size_t)k * CC + (n - NH)];
        }
        uint16_t hh, ll;
        split1(v, hh, ll);
        g_Wth[i] = hh;
        g_Wtl[i] = ll;
    }
    if (i < NTOT) g_bias[i] = (i < NH) ? hb[i] : cb[i - NH];
}

// ---------------- kernel 3: bf16x3 HMMA GEMM (NT), ldmatrix + 3-stage ---------
__global__ void __launch_bounds__(256)
gemm3x_kernel(const uint16_t* __restrict__ Ah,
              const uint16_t* __restrict__ Al,
              const uint16_t* __restrict__ Bh,
              const uint16_t* __restrict__ Bl,
              int K, int Ncols, const float* __restrict__ bias,
              float* __restrict__ Chead, int ld_head,
              float* __restrict__ Ccls, int colsplit) {
    extern __shared__ __align__(128) char smem[];
    const uint32_t smbase = smem_u32_of(smem);

    const int tid = threadIdx.x;
    const int lane = tid & 31;
    const int wid = tid >> 5;
    const int wm = wid >> 1;
    const int wn = wid & 1;
    const int g = lane >> 2;
    const int t = lane & 3;
    const int row0 = blockIdx.y * BM;
    const int col0 = blockIdx.x * BN;
    const int nchunk = K / BK;

    float acc[2][8][4];
#pragma unroll
    for (int mi = 0; mi < 2; ++mi)
#pragma unroll
        for (int ni = 0; ni < 8; ++ni)
#pragma unroll
            for (int j = 0; j < 4; ++j) acc[mi][ni][j] = 0.0f;

    // per-thread loader geometry (fixed): q = 16B slot, rows rA (even j) rB (odd j)
    const int qv = tid & 3;
    const int rA = tid >> 2;
    const int rB = rA + 64;

    auto load_chunk = [&](int c, int s) {
        const uint32_t st = smbase + (uint32_t)s * STAGEB;
        const int k0 = c * BK;
#pragma unroll
        for (int j = 0; j < 8; ++j) {
            const int part = j >> 1;
            const int r = (j & 1) ? rB : rA;
            uint32_t dst = st + (uint32_t)part * PARTB + r * PITCHB + qv * 16;
            const uint16_t* src;
            int sz = 16;
            if (part == 0) {
                src = Ah + (size_t)(row0 + r) * K + k0 + qv * 8;
            } else if (part == 1) {
                src = Al + (size_t)(row0 + r) * K + k0 + qv * 8;
            } else {
                const uint16_t* base = (part == 2) ? Bh : Bl;
                int n = col0 + r;
                if (n < Ncols) {
                    src = base + (size_t)n * K + k0 + qv * 8;
                } else {
                    src = base;
                    sz = 0;
                }
            }
            asm volatile("cp.async.cg.shared.global [%0], [%1], 16, %2;"
                         :: "r"(dst), "l"(src), "r"(sz) : "memory");
        }
        asm volatile("cp.async.commit_group;" ::: "memory");
    };

    load_chunk(0, 0);
    load_chunk(1, 1);

    // ldmatrix lane addressing (constant per thread)
    const uint32_t aRowOff = (uint32_t)(lane & 15) * PITCHB;
    const uint32_t aByte   = (uint32_t)((lane >> 4) << 4);
    const uint32_t bRowOff = (uint32_t)(((lane >> 4) & 1) * 8 + (lane & 7)) * PITCHB;
    const uint32_t bByte   = (uint32_t)(((lane >> 3) & 1) << 4);

    int s = 0;
    for (int c = 0; c < nchunk; ++c) {
        if (c + 2 < nchunk) {
            load_chunk(c + 2, (s + 2 >= NSTAGE) ? (s + 2 - NSTAGE) : (s + 2));
            asm volatile("cp.async.wait_group 2;" ::: "memory");
        } else if (c + 1 < nchunk) {
            asm volatile("cp.async.wait_group 1;" ::: "memory");
        } else {
            asm volatile("cp.async.wait_group 0;" ::: "memory");
        }
        __syncthreads();

        const uint32_t st  = smbase + (uint32_t)s * STAGEB;
        const uint32_t sAh = st;
        const uint32_t sAl = st + PARTB;
        const uint32_t sBh = st + 2 * PARTB;
        const uint32_t sBl = st + 3 * PARTB;

#pragma unroll
        for (int kk = 0; kk < 2; ++kk) {
            const uint32_t kb = (uint32_t)kk * 32;
            uint32_t ah[2][4], al[2][4];
#pragma unroll
            for (int mi = 0; mi < 2; ++mi) {
                uint32_t abase = (uint32_t)(wm * 32 + mi * 16) * PITCHB + aRowOff + kb + aByte;
                ldsm4(sAh + abase, ah[mi]);
                ldsm4(sAl + abase, al[mi]);
            }
#pragma unroll
            for (int p = 0; p < 4; ++p) {
                uint32_t bbase = (uint32_t)(wn * 64 + p * 16) * PITCHB + bRowOff + kb + bByte;
                uint32_t bh[4], bl[4];
                ldsm4(sBh + bbase, bh);
                ldsm4(sBl + bbase, bl);
#pragma unroll
                for (int mi = 0; mi < 2; ++mi) {
                    mma_bf16(acc[mi][2 * p],     ah[mi], bh[0], bh[1]);
                    mma_bf16(acc[mi][2 * p],     ah[mi], bl[0], bl[1]);
                    mma_bf16(acc[mi][2 * p],     al[mi], bh[0], bh[1]);
                    mma_bf16(acc[mi][2 * p + 1], ah[mi], bh[2], bh[3]);
                    mma_bf16(acc[mi][2 * p + 1], ah[mi], bl[2], bl[3]);
                    mma_bf16(acc[mi][2 * p + 1], al[mi], bh[2], bh[3]);
                }
            }
        }
        __syncthreads();
        ++s;
        if (s == NSTAGE) s = 0;
    }

    // ---- epilogue ----
    const bool has_bias = (bias != nullptr);
#pragma unroll
    for (int mi = 0; mi < 2; ++mi) {
        int r = row0 + wm * 32 + mi * 16 + g;
#pragma unroll
        for (int ni = 0; ni < 8; ++ni) {
            int cb = col0 + wn * 64 + ni * 8 + 2 * t;
            if (cb >= Ncols) continue;
            float b0 = has_bias ? bias[cb] : 0.0f;
            float b1 = (has_bias && (cb + 1) < Ncols) ? bias[cb + 1] : 0.0f;
            float v00 = acc[mi][ni][0] + b0;
            float v01 = acc[mi][ni][1] + b1;
            float v10 = acc[mi][ni][2] + b0;
            float v11 = acc[mi][ni][3] + b1;
            if (cb + 1 < colsplit) {
                float2* d0 = reinterpret_cast<float2*>(Chead + (size_t)r * ld_head + cb);
                float2* d1 = reinterpret_cast<float2*>(Chead + (size_t)(r + 8) * ld_head + cb);
                *d0 = make_float2(v00, v01);
                *d1 = make_float2(v10, v11);
            } else {
                for (int jj = 0; jj < 2; ++jj) {
                    int col = cb + jj;
                    if (col >= Ncols) break;
                    float va = (jj == 0) ? v00 : v01;
                    float vb = (jj == 0) ? v10 : v11;
                    if (col < colsplit) {
                        Chead[(size_t)r * ld_head + col] = va;
                        Chead[(size_t)(r + 8) * ld_head + col] = vb;
                    } else {
                        Ccls[(size_t)r * CC + (col - colsplit)] = va;
                        Ccls[(size_t)(r + 8) * CC + (col - colsplit)] = vb;
                    }
                }
            }
        }
    }
}

// ---------------- kernel 4: L2 normalize + split to bf16 ---------------------
__global__ void normalize_kernel(const float* __restrict__ X,
                                 uint16_t* __restrict__ Xh,
                                 uint16_t* __restrict__ Xl,
                                 int rows, float extra) {
    int wwid = (blockIdx.x * blockDim.x + threadIdx.x) >> 5;
    int lane = threadIdx.x & 31;
    int total = rows * HH;
    if (wwid >= total) return;
    int n = wwid / HH;
    int h = wwid - n * HH;
    size_t base = (size_t)n * NH + h * PP;
    const float4* p4 = reinterpret_cast<const float4*>(X + base);
    float4 v0 = p4[lane];
    float4 v1 = p4[lane + 32];
    float ss = v0.x * v0.x + v0.y * v0.y + v0.z * v0.z + v0.w * v0.w
             + v1.x * v1.x + v1.y * v1.y + v1.z * v1.z + v1.w * v1.w;
#pragma unroll
    for (int off = 16; off > 0; off >>= 1)
        ss += __shfl_xor_sync(0xffffffffu, ss, off);
    float sc = extra / fmaxf(sqrtf(ss), EPSN);
    float a0 = v0.x * sc, a1 = v0.y * sc, a2 = v0.z * sc, a3 = v0.w * sc;
    float a4 = v1.x * sc, a5 = v1.y * sc, a6 = v1.z * sc, a7 = v1.w * sc;
    ushort4 h0, l0, h1, l1;
    split1(a0, h0.x, l0.x); split1(a1, h0.y, l0.y);
    split1(a2, h0.z, l0.z); split1(a3, h0.w, l0.w);
    split1(a4, h1.x, l1.x); split1(a5, h1.y, l1.y);
    split1(a6, h1.z, l1.z); split1(a7, h1.w, l1.w);
    ushort4* ph = reinterpret_cast<ushort4*>(Xh + base);
    ushort4* pl = reinterpret_cast<ushort4*>(Xl + base);
    ph[lane] = h0; ph[lane + 32] = h1;
    pl[lane] = l0; pl[lane + 32] = l1;
}

// ---------------- launch -------------------------------------------------------
extern "C" void kernel_launch(void* const* d_in, const int* in_sizes, int n_in,
                              void* d_out, int out_size) {
    const float* query   = (const float*)d_in[0];
    const float* support = (const float*)d_in[1];
    const float* head_W  = (const float*)d_in[2];
    const float* head_b  = (const float*)d_in[3];
    const float* cls_W   = (const float*)d_in[4];
    const float* cls_b   = (const float*)d_in[5];

    float* out_match = (float*)d_out;
    float* out_preds = (float*)d_out + (size_t)NQ * NS;

    uint16_t *Aggh, *Aggl, *Suph, *Supl, *Wth, *Wtl, *Qh, *Ql, *Sh, *Sl;
    float *bias, *Qf, *Sf;
    cudaGetSymbolAddress((void**)&Aggh, g_Aggh);
    cudaGetSymbolAddress((void**)&Aggl, g_Aggl);
    cudaGetSymbolAddress((void**)&Suph, g_Suph);
    cudaGetSymbolAddress((void**)&Supl, g_Supl);
    cudaGetSymbolAddress((void**)&Wth,  g_Wth);
    cudaGetSymbolAddress((void**)&Wtl,  g_Wtl);
    cudaGetSymbolAddress((void**)&bias, g_bias);
    cudaGetSymbolAddress((void**)&Qf,   g_Qf);
    cudaGetSymbolAddress((void**)&Sf,   g_Sf);
    cudaGetSymbolAddress((void**)&Qh,   g_Qh);
    cudaGetSymbolAddress((void**)&Ql,   g_Ql);
    cudaGetSymbolAddress((void**)&Sh,   g_Sh);
    cudaGetSymbolAddress((void**)&Sl,   g_Sl);

    cudaFuncSetAttribute(gemm3x_kernel,
                         cudaFuncAttributeMaxDynamicSharedMemorySize, SMEMB);

    {
        int n4 = (NQ * DD) / 4;
        mean_kernel<<<(n4 + 255) / 256, 256>>>(query);
        int s4 = (NS * DD) / 4;
        split_support_kernel<<<(s4 + 255) / 256, 256>>>(support);
    }
    {
        int total = NTOT * DD;
        pack_kernel<<<(total + 255) / 256, 256>>>(head_W, head_b, cls_W, cls_b);
    }
    {
        dim3 grid(NH / BN, NQ / BM);
        gemm3x_kernel<<<grid, 256, SMEMB>>>(Aggh, Aggl, Wth, Wtl, DD, NH, bias,
                                            Qf, NH, nullptr, NH);
    }
    {
        dim3 grid((NTOT + BN - 1) / BN, NS / BM);
        gemm3x_kernel<<<grid, 256, SMEMB>>>(Suph, Supl, Wth, Wtl, DD, NTOT, bias,
                                            Sf, NH, out_preds, NH);
    }
    {
        int warpsQ = NQ * HH;
        normalize_kernel<<<(warpsQ * 32 + 255) / 256, 256>>>(Qf, Qh, Ql, NQ,
                                                             1.0f / (float)HH);
        int warpsS = NS * HH;
        normalize_kernel<<<(warpsS * 32 + 255) / 256, 256>>>(Sf, Sh, Sl, NS, 1.0f);
    }
    {
        dim3 grid(NS / BN, NQ / BM);
        gemm3x_kernel<<<grid, 256, SMEMB>>>(Qh, Ql, Sh, Sl, NH, NS, nullptr,
                                            out_match, NS, nullptr, NS);
    }
}

// round 5
// speedup vs baseline: 2.6879x; 1.1152x over previous
#include <cuda_runtime.h>
#include <cuda_bf16.h>
#include <cstdint>
#include <math.h>

// ---------------- problem constants ----------------------------------------
#define NQ     4096
#define DD     1024
#define NS     2048
#define HH     3
#define PP     256
#define CC     100
#define NH     768
#define NTOT   868
#define EPSN   1e-8f

// ---------------- GEMM tiling ----------------------------------------------
#define BM     128
#define BN     128
#define BK     32
#define PITCHB 80
#define PARTB  (BM * PITCHB)
#define STAGEB (4 * PARTB)       // Ah | Al | Bh | Bl  (40960 B)
#define NSTAGE 2
#define SMEMB  (NSTAGE * STAGEB) // 81920 B  -> 2 CTAs/SM

// ---------------- scratch --------------------------------------------------
__device__ uint16_t g_Aggh[NQ * DD], g_Aggl[NQ * DD];
__device__ uint16_t g_Suph[NS * DD], g_Supl[NS * DD];
__device__ uint16_t g_Wth[NTOT * DD], g_Wtl[NTOT * DD];
__device__ float    g_bias[NTOT];
__device__ float    g_Qf[NQ * NH];
__device__ float    g_Sf[NS * NH];
__device__ uint16_t g_Qh[NQ * NH], g_Ql[NQ * NH];
__device__ uint16_t g_Sh[NS * NH], g_Sl[NS * NH];

// ---------------- helpers ----------------------------------------------------
__device__ __forceinline__ uint32_t smem_u32_of(const void* p) {
    uint32_t a;
    asm("{ .reg .u64 t; cvta.to.shared.u64 t, %1; cvt.u32.u64 %0, t; }"
        : "=r"(a) : "l"(p));
    return a;
}

__device__ __forceinline__ void ldsm4(uint32_t addr, uint32_t* r) {
    asm volatile("ldmatrix.sync.aligned.m8n8.x4.shared.b16 {%0,%1,%2,%3}, [%4];"
                 : "=r"(r[0]), "=r"(r[1]), "=r"(r[2]), "=r"(r[3]) : "r"(addr));
}

__device__ __forceinline__ void split1(float x, uint16_t& h, uint16_t& l) {
    uint32_t b = __float_as_uint(x);
    h = (uint16_t)(b >> 16);
    float r = x - __uint_as_float(b & 0xffff0000u);
    asm("{ .reg .b16 t; cvt.rn.bf16.f32 t, %1; mov.b16 %0, t; }" : "=h"(l) : "f"(r));
}

__device__ __forceinline__ void mma_bf16(float* c, const uint32_t* a,
                                         uint32_t b0, uint32_t b1) {
    asm volatile(
        "mma.sync.aligned.m16n8k16.row.col.f32.bf16.bf16.f32 "
        "{%0,%1,%2,%3}, {%4,%5,%6,%7}, {%8,%9}, {%0,%1,%2,%3};"
        : "+f"(c[0]), "+f"(c[1]), "+f"(c[2]), "+f"(c[3])
        : "r"(a[0]), "r"(a[1]), "r"(a[2]), "r"(a[3]), "r"(b0), "r"(b1));
}

// ---------------- kernel 1: mean over frames + split -------------------------
__global__ void mean_kernel(const float* __restrict__ q) {
    int i = blockIdx.x * blockDim.x + threadIdx.x;
    const int n4 = (NQ * DD) / 4;
    if (i >= n4) return;
    const float4* p = reinterpret_cast<const float4*>(q);
    float4 a = p[i], b = p[i + n4], c = p[i + 2 * n4], d = p[i + 3 * n4];
    float v0 = 0.25f * (a.x + b.x + c.x + d.x);
    float v1 = 0.25f * (a.y + b.y + c.y + d.y);
    float v2 = 0.25f * (a.z + b.z + c.z + d.z);
    float v3 = 0.25f * (a.w + b.w + c.w + d.w);
    ushort4 hs, ls;
    split1(v0, hs.x, ls.x); split1(v1, hs.y, ls.y);
    split1(v2, hs.z, ls.z); split1(v3, hs.w, ls.w);
    reinterpret_cast<ushort4*>(g_Aggh)[i] = hs;
    reinterpret_cast<ushort4*>(g_Aggl)[i] = ls;
}

// ---------------- kernel 1b: split support ----------------------------------
__global__ void split_support_kernel(const float* __restrict__ s) {
    int i = blockIdx.x * blockDim.x + threadIdx.x;
    const int n4 = (NS * DD) / 4;
    if (i >= n4) return;
    float4 v = reinterpret_cast<const float4*>(s)[i];
    ushort4 hs, ls;
    split1(v.x, hs.x, ls.x); split1(v.y, hs.y, ls.y);
    split1(v.z, hs.z, ls.z); split1(v.w, hs.w, ls.w);
    reinterpret_cast<ushort4*>(g_Suph)[i] = hs;
    reinterpret_cast<ushort4*>(g_Supl)[i] = ls;
}

// ---------------- kernel 2: pack W^T + bias + split ---------------------------
__global__ void pack_kernel(const float* __restrict__ hW,
                            const float* __restrict__ hb,
                            const float* __restrict__ cW,
                            const float* __restrict__ cb) {
    int i = blockIdx.x * blockDim.x + threadIdx.x;
    if (i < NTOT * DD) {
        int n = i >> 10;
        int k = i & 1023;
        float v;
        if (n < NH) {
            int h = n >> 8;
            int p = n & 255;
            v = hW[((size_t)h * DD + k) * PP + p];
        } else {
            v = cW[(size_t)k * CC + (n - NH)];
        }
        uint16_t hh, ll;
        split1(v, hh, ll);
        g_Wth[i] = hh;
        g_Wtl[i] = ll;
    }
    if (i < NTOT) g_bias[i] = (i < NH) ? hb[i] : cb[i - NH];
}

// ---------------- kernel 3: bf16x3 HMMA GEMM (NT), 2 CTAs/SM ------------------
__global__ void __launch_bounds__(256, 2)
gemm3x_kernel(const uint16_t* __restrict__ Ah,
              const uint16_t* __restrict__ Al,
              const uint16_t* __restrict__ Bh,
              const uint16_t* __restrict__ Bl,
              int K, int Ncols, const float* __restrict__ bias,
              float* __restrict__ Chead, int ld_head,
              float* __restrict__ Ccls, int colsplit) {
    extern __shared__ __align__(128) char smem[];
    const uint32_t smbase = smem_u32_of(smem);

    const int tid = threadIdx.x;
    const int lane = tid & 31;
    const int wid = tid >> 5;
    const int wm = wid >> 1;
    const int wn = wid & 1;
    const int g = lane >> 2;
    const int t = lane & 3;
    const int row0 = blockIdx.y * BM;
    const int col0 = blockIdx.x * BN;
    const int nchunk = K / BK;

    float acc[2][8][4];
#pragma unroll
    for (int mi = 0; mi < 2; ++mi)
#pragma unroll
        for (int ni = 0; ni < 8; ++ni)
#pragma unroll
            for (int j = 0; j < 4; ++j) acc[mi][ni][j] = 0.0f;

    const int qv = tid & 3;
    const int rA = tid >> 2;
    const int rB = rA + 64;

    auto load_chunk = [&](int c, int s) {
        const uint32_t st = smbase + (uint32_t)s * STAGEB;
        const int k0 = c * BK;
#pragma unroll
        for (int j = 0; j < 8; ++j) {
            const int part = j >> 1;
            const int r = (j & 1) ? rB : rA;
            uint32_t dst = st + (uint32_t)part * PARTB + r * PITCHB + qv * 16;
            const uint16_t* src;
            int sz = 16;
            if (part == 0) {
                src = Ah + (size_t)(row0 + r) * K + k0 + qv * 8;
            } else if (part == 1) {
                src = Al + (size_t)(row0 + r) * K + k0 + qv * 8;
            } else {
                const uint16_t* base = (part == 2) ? Bh : Bl;
                int n = col0 + r;
                if (n < Ncols) {
                    src = base + (size_t)n * K + k0 + qv * 8;
                } else {
                    src = base;
                    sz = 0;
                }
            }
            asm volatile("cp.async.cg.shared.global [%0], [%1], 16, %2;"
                         :: "r"(dst), "l"(src), "r"(sz) : "memory");
        }
        asm volatile("cp.async.commit_group;" ::: "memory");
    };

    load_chunk(0, 0);

    const uint32_t aRowOff = (uint32_t)(lane & 15) * PITCHB;
    const uint32_t aByte   = (uint32_t)((lane >> 4) << 4);
    const uint32_t bRowOff = (uint32_t)(((lane >> 4) & 1) * 8 + (lane & 7)) * PITCHB;
    const uint32_t bByte   = (uint32_t)(((lane >> 3) & 1) << 4);

    for (int c = 0; c < nchunk; ++c) {
        const int s = c & 1;
        if (c + 1 < nchunk) {
            load_chunk(c + 1, s ^ 1);
            asm volatile("cp.async.wait_group 1;" ::: "memory");
        } else {
            asm volatile("cp.async.wait_group 0;" ::: "memory");
        }
        __syncthreads();

        const uint32_t st  = smbase + (uint32_t)s * STAGEB;
        const uint32_t sAh = st;
        const uint32_t sAl = st + PARTB;
        const uint32_t sBh = st + 2 * PARTB;
        const uint32_t sBl = st + 3 * PARTB;

#pragma unroll
        for (int kk = 0; kk < 2; ++kk) {
            const uint32_t kb = (uint32_t)kk * 32;
            uint32_t ah[2][4], al[2][4];
#pragma unroll
            for (int mi = 0; mi < 2; ++mi) {
                uint32_t abase = (uint32_t)(wm * 32 + mi * 16) * PITCHB + aRowOff + kb + aByte;
                ldsm4(sAh + abase, ah[mi]);
                ldsm4(sAl + abase, al[mi]);
            }
#pragma unroll
            for (int p = 0; p < 4; ++p) {
                uint32_t bbase = (uint32_t)(wn * 64 + p * 16) * PITCHB + bRowOff + kb + bByte;
                uint32_t bh[4], bl[4];
                ldsm4(sBh + bbase, bh);
                ldsm4(sBl + bbase, bl);
                // term-major ordering: same-accumulator mmas are 4 apart
#pragma unroll
                for (int mi = 0; mi < 2; ++mi) {
                    mma_bf16(acc[mi][2 * p],     ah[mi], bh[0], bh[1]);
                    mma_bf16(acc[mi][2 * p + 1], ah[mi], bh[2], bh[3]);
                }
#pragma unroll
                for (int mi = 0; mi < 2; ++mi) {
                    mma_bf16(acc[mi][2 * p],     ah[mi], bl[0], bl[1]);
                    mma_bf16(acc[mi][2 * p + 1], ah[mi], bl[2], bl[3]);
                }
#pragma unroll
                for (int mi = 0; mi < 2; ++mi) {
                    mma_bf16(acc[mi][2 * p],     al[mi], bh[0], bh[1]);
                    mma_bf16(acc[mi][2 * p + 1], al[mi], bh[2], bh[3]);
                }
            }
        }
        __syncthreads();
    }

    // ---- epilogue ----
    const bool has_bias = (bias != nullptr);
#pragma unroll
    for (int mi = 0; mi < 2; ++mi) {
        int r = row0 + wm * 32 + mi * 16 + g;
#pragma unroll
        for (int ni = 0; ni < 8; ++ni) {
            int cb = col0 + wn * 64 + ni * 8 + 2 * t;
            if (cb >= Ncols) continue;
            float b0 = has_bias ? bias[cb] : 0.0f;
            float b1 = (has_bias && (cb + 1) < Ncols) ? bias[cb + 1] : 0.0f;
            float v00 = acc[mi][ni][0] + b0;
            float v01 = acc[mi][ni][1] + b1;
            float v10 = acc[mi][ni][2] + b0;
            float v11 = acc[mi][ni][3] + b1;
            if (cb + 1 < colsplit) {
                float2* d0 = reinterpret_cast<float2*>(Chead + (size_t)r * ld_head + cb);
                float2* d1 = reinterpret_cast<float2*>(Chead + (size_t)(r + 8) * ld_head + cb);
                *d0 = make_float2(v00, v01);
                *d1 = make_float2(v10, v11);
            } else {
                for (int jj = 0; jj < 2; ++jj) {
                    int col = cb + jj;
                    if (col >= Ncols) break;
                    float va = (jj == 0) ? v00 : v01;
                    float vb = (jj == 0) ? v10 : v11;
                    if (col < colsplit) {
                        Chead[(size_t)r * ld_head + col] = va;
                        Chead[(size_t)(r + 8) * ld_head + col] = vb;
                    } else {
                        Ccls[(size_t)r * CC + (col - colsplit)] = va;
                        Ccls[(size_t)(r + 8) * CC + (col - colsplit)] = vb;
                    }
                }
            }
        }
    }
}

// ---------------- kernel 4: L2 normalize + split to bf16 ---------------------
__global__ void normalize_kernel(const float* __restrict__ X,
                                 uint16_t* __restrict__ Xh,
                                 uint16_t* __restrict__ Xl,
                                 int rows, float extra) {
    int wwid = (blockIdx.x * blockDim.x + threadIdx.x) >> 5;
    int lane = threadIdx.x & 31;
    int total = rows * HH;
    if (wwid >= total) return;
    int n = wwid / HH;
    int h = wwid - n * HH;
    size_t base = (size_t)n * NH + h * PP;
    const float4* p4 = reinterpret_cast<const float4*>(X + base);
    float4 v0 = p4[lane];
    float4 v1 = p4[lane + 32];
    float ss = v0.x * v0.x + v0.y * v0.y + v0.z * v0.z + v0.w * v0.w
             + v1.x * v1.x + v1.y * v1.y + v1.z * v1.z + v1.w * v1.w;
#pragma unroll
    for (int off = 16; off > 0; off >>= 1)
        ss += __shfl_xor_sync(0xffffffffu, ss, off);
    float sc = extra / fmaxf(sqrtf(ss), EPSN);
    float a0 = v0.x * sc, a1 = v0.y * sc, a2 = v0.z * sc, a3 = v0.w * sc;
    float a4 = v1.x * sc, a5 = v1.y * sc, a6 = v1.z * sc, a7 = v1.w * sc;
    ushort4 h0, l0, h1, l1;
    split1(a0, h0.x, l0.x); split1(a1, h0.y, l0.y);
    split1(a2, h0.z, l0.z); split1(a3, h0.w, l0.w);
    split1(a4, h1.x, l1.x); split1(a5, h1.y, l1.y);
    split1(a6, h1.z, l1.z); split1(a7, h1.w, l1.w);
    ushort4* ph = reinterpret_cast<ushort4*>(Xh + base);
    ushort4* pl = reinterpret_cast<ushort4*>(Xl + base);
    ph[lane] = h0; ph[lane + 32] = h1;
    pl[lane] = l0; pl[lane + 32] = l1;
}

// ---------------- launch -------------------------------------------------------
extern "C" void kernel_launch(void* const* d_in, const int* in_sizes, int n_in,
                              void* d_out, int out_size) {
    const float* query   = (const float*)d_in[0];
    const float* support = (const float*)d_in[1];
    const float* head_W  = (const float*)d_in[2];
    const float* head_b  = (const float*)d_in[3];
    const float* cls_W   = (const float*)d_in[4];
    const float* cls_b   = (const float*)d_in[5];

    float* out_match = (float*)d_out;
    float* out_preds = (float*)d_out + (size_t)NQ * NS;

    uint16_t *Aggh, *Aggl, *Suph, *Supl, *Wth, *Wtl, *Qh, *Ql, *Sh, *Sl;
    float *bias, *Qf, *Sf;
    cudaGetSymbolAddress((void**)&Aggh, g_Aggh);
    cudaGetSymbolAddress((void**)&Aggl, g_Aggl);
    cudaGetSymbolAddress((void**)&Suph, g_Suph);
    cudaGetSymbolAddress((void**)&Supl, g_Supl);
    cudaGetSymbolAddress((void**)&Wth,  g_Wth);
    cudaGetSymbolAddress((void**)&Wtl,  g_Wtl);
    cudaGetSymbolAddress((void**)&bias, g_bias);
    cudaGetSymbolAddress((void**)&Qf,   g_Qf);
    cudaGetSymbolAddress((void**)&Sf,   g_Sf);
    cudaGetSymbolAddress((void**)&Qh,   g_Qh);
    cudaGetSymbolAddress((void**)&Ql,   g_Ql);
    cudaGetSymbolAddress((void**)&Sh,   g_Sh);
    cudaGetSymbolAddress((void**)&Sl,   g_Sl);

    cudaFuncSetAttribute(gemm3x_kernel,
                         cudaFuncAttributeMaxDynamicSharedMemorySize, SMEMB);

    {
        int n4 = (NQ * DD) / 4;
        mean_kernel<<<(n4 + 255) / 256, 256>>>(query);
        int s4 = (NS * DD) / 4;
        split_support_kernel<<<(s4 + 255) / 256, 256>>>(support);
    }
    {
        int total = NTOT * DD;
        pack_kernel<<<(total + 255) / 256, 256>>>(head_W, head_b, cls_W, cls_b);
    }
    {
        dim3 grid(NH / BN, NQ / BM);
        gemm3x_kernel<<<grid, 256, SMEMB>>>(Aggh, Aggl, Wth, Wtl, DD, NH, bias,
                                            Qf, NH, nullptr, NH);
    }
    {
        dim3 grid((NTOT + BN - 1) / BN, NS / BM);
        gemm3x_kernel<<<grid, 256, SMEMB>>>(Suph, Supl, Wth, Wtl, DD, NTOT, bias,
                                            Sf, NH, out_preds, NH);
    }
    {
        int warpsQ = NQ * HH;
        normalize_kernel<<<(warpsQ * 32 + 255) / 256, 256>>>(Qf, Qh, Ql, NQ,
                                                             1.0f / (float)HH);
        int warpsS = NS * HH;
        normalize_kernel<<<(warpsS * 32 + 255) / 256, 256>>>(Sf, Sh, Sl, NS, 1.0f);
    }
    {
        dim3 grid(NS / BN, NQ / BM);
        gemm3x_kernel<<<grid, 256, SMEMB>>>(Qh, Ql, Sh, Sl, NH, NS, nullptr,
                                            out_match, NS, nullptr, NS);
    }
}

// round 6
// speedup vs baseline: 3.5418x; 1.3177x over previous
#include <cuda_runtime.h>
#include <cuda_fp16.h>
#include <cstdint>
#include <math.h>

// ---------------- problem constants ----------------------------------------
#define NQ     4096
#define DD     1024
#define NS     2048
#define HH     3
#define PP     256
#define CC     100
#define NH     768
#define NTOT   868
#define EPSN   1e-8f

// ---------------- GEMM tiling ----------------------------------------------
#define BM     128
#define BN     128
#define BK     32
#define PITCHB 80
#define PARTB  (BM * PITCHB)     // 10240 B
#define STAGEB (3 * PARTB)       // Ah | Al | B  (30720 B)
#define NSTAGE 3
#define SMEMB  (NSTAGE * STAGEB) // 92160 B -> 2 CTAs/SM

// ---------------- scratch --------------------------------------------------
__device__ uint16_t g_Aggh[NQ * DD], g_Aggl[NQ * DD];   // fp16 split of mean(query)
__device__ uint16_t g_Suph[NS * DD], g_Supl[NS * DD];   // fp16 split of support
__device__ uint16_t g_Wt[NTOT * DD];                    // single fp16 W^T
__device__ float    g_bias[NTOT];
__device__ float    g_Qf[NQ * NH];
__device__ float    g_Sf[NS * NH];
__device__ uint16_t g_Qh[NQ * NH], g_Ql[NQ * NH];       // fp16 split of normalized Q
__device__ uint16_t g_Sn[NS * NH];                      // single fp16 normalized S

// ---------------- helpers ----------------------------------------------------
__device__ __forceinline__ uint32_t smem_u32_of(const void* p) {
    uint32_t a;
    asm("{ .reg .u64 t; cvta.to.shared.u64 t, %1; cvt.u32.u64 %0, t; }"
        : "=r"(a) : "l"(p));
    return a;
}

__device__ __forceinline__ void ldsm4(uint32_t addr, uint32_t* r) {
    asm volatile("ldmatrix.sync.aligned.m8n8.x4.shared.b16 {%0,%1,%2,%3}, [%4];"
                 : "=r"(r[0]), "=r"(r[1]), "=r"(r[2]), "=r"(r[3]) : "r"(addr));
}

// fp16 split: h = rn(x), l = rn(x - h)   (x - h exact in fp32)
__device__ __forceinline__ void split1(float x, uint16_t& h, uint16_t& l) {
    __half hh = __float2half_rn(x);
    float r = x - __half2float(hh);
    __half ll = __float2half_rn(r);
    h = __half_as_ushort(hh);
    l = __half_as_ushort(ll);
}

__device__ __forceinline__ uint16_t tohalf(float x) {
    return __half_as_ushort(__float2half_rn(x));
}

__device__ __forceinline__ void mma_f16(float* c, const uint32_t* a,
                                        uint32_t b0, uint32_t b1) {
    asm volatile(
        "mma.sync.aligned.m16n8k16.row.col.f32.f16.f16.f32 "
        "{%0,%1,%2,%3}, {%4,%5,%6,%7}, {%8,%9}, {%0,%1,%2,%3};"
        : "+f"(c[0]), "+f"(c[1]), "+f"(c[2]), "+f"(c[3])
        : "r"(a[0]), "r"(a[1]), "r"(a[2]), "r"(a[3]), "r"(b0), "r"(b1));
}

// ---------------- kernel 1: mean over frames + fp16 split --------------------
__global__ void mean_kernel(const float* __restrict__ q) {
    int i = blockIdx.x * blockDim.x + threadIdx.x;
    const int n4 = (NQ * DD) / 4;
    if (i >= n4) return;
    const float4* p = reinterpret_cast<const float4*>(q);
    float4 a = p[i], b = p[i + n4], c = p[i + 2 * n4], d = p[i + 3 * n4];
    float v0 = 0.25f * (a.x + b.x + c.x + d.x);
    float v1 = 0.25f * (a.y + b.y + c.y + d.y);
    float v2 = 0.25f * (a.z + b.z + c.z + d.z);
    float v3 = 0.25f * (a.w + b.w + c.w + d.w);
    ushort4 hs, ls;
    split1(v0, hs.x, ls.x); split1(v1, hs.y, ls.y);
    split1(v2, hs.z, ls.z); split1(v3, hs.w, ls.w);
    reinterpret_cast<ushort4*>(g_Aggh)[i] = hs;
    reinterpret_cast<ushort4*>(g_Aggl)[i] = ls;
}

// ---------------- kernel 1b: split support ----------------------------------
__global__ void split_support_kernel(const float* __restrict__ s) {
    int i = blockIdx.x * blockDim.x + threadIdx.x;
    const int n4 = (NS * DD) / 4;
    if (i >= n4) return;
    float4 v = reinterpret_cast<const float4*>(s)[i];
    ushort4 hs, ls;
    split1(v.x, hs.x, ls.x); split1(v.y, hs.y, ls.y);
    split1(v.z, hs.z, ls.z); split1(v.w, hs.w, ls.w);
    reinterpret_cast<ushort4*>(g_Suph)[i] = hs;
    reinterpret_cast<ushort4*>(g_Supl)[i] = ls;
}

// ---------------- kernel 2: pack W^T + bias (single fp16) ---------------------
__global__ void pack_kernel(const float* __restrict__ hW,
                            const float* __restrict__ hb,
                            const float* __restrict__ cW,
                            const float* __restrict__ cb) {
    int i = blockIdx.x * blockDim.x + threadIdx.x;
    if (i < NTOT * DD) {
        int n = i >> 10;
        int k = i & 1023;
        float v;
        if (n < NH) {
            int h = n >> 8;
            int p = n & 255;
            v = hW[((size_t)h * DD + k) * PP + p];
        } else {
            v = cW[(size_t)k * CC + (n - NH)];
        }
        g_Wt[i] = tohalf(v);
    }
    if (i < NTOT) g_bias[i] = (i < NH) ? hb[i] : cb[i - NH];
}

// ---------------- kernel 3: fp16x2 HMMA GEMM (NT), 3-stage, 2 CTAs/SM ---------
__global__ void __launch_bounds__(256, 2)
gemm2x_kernel(const uint16_t* __restrict__ Ah,
              const uint16_t* __restrict__ Al,
              const uint16_t* __restrict__ B,
              int K, int Ncols, const float* __restrict__ bias,
              float* __restrict__ Chead, int ld_head,
              float* __restrict__ Ccls, int colsplit) {
    extern __shared__ __align__(128) char smem[];
    const uint32_t smbase = smem_u32_of(smem);

    const int tid = threadIdx.x;
    const int lane = tid & 31;
    const int wid = tid >> 5;
    const int wm = wid >> 1;
    const int wn = wid & 1;
    const int g = lane >> 2;
    const int t = lane & 3;
    const int row0 = blockIdx.y * BM;
    const int col0 = blockIdx.x * BN;
    const int nchunk = K / BK;

    float acc[2][8][4];
#pragma unroll
    for (int mi = 0; mi < 2; ++mi)
#pragma unroll
        for (int ni = 0; ni < 8; ++ni)
#pragma unroll
            for (int j = 0; j < 4; ++j) acc[mi][ni][j] = 0.0f;

    auto load_chunk = [&](int c, int s) {
        const uint32_t st = smbase + (uint32_t)s * STAGEB;
        const int k0 = c * BK;
#pragma unroll
        for (int j = 0; j < 6; ++j) {
            int idx = tid + 256 * j;
            int part = idx >> 9;          // 0:Ah 1:Al 2:B
            int within = idx & 511;
            int r = within >> 2;
            int q = within & 3;
            uint32_t dst = st + (uint32_t)part * PARTB + r * PITCHB + q * 16;
            const uint16_t* src;
            int sz = 16;
            if (part == 0) {
                src = Ah + (size_t)(row0 + r) * K + k0 + q * 8;
            } else if (part == 1) {
                src = Al + (size_t)(row0 + r) * K + k0 + q * 8;
            } else {
                int n = col0 + r;
                if (n < Ncols) {
                    src = B + (size_t)n * K + k0 + q * 8;
                } else {
                    src = B;
                    sz = 0;
                }
            }
            asm volatile("cp.async.cg.shared.global [%0], [%1], 16, %2;"
                         :: "r"(dst), "l"(src), "r"(sz) : "memory");
        }
        asm volatile("cp.async.commit_group;" ::: "memory");
    };

    load_chunk(0, 0);
    load_chunk(1, 1);

    const uint32_t aRowOff = (uint32_t)(lane & 15) * PITCHB;
    const uint32_t aByte   = (uint32_t)((lane >> 4) << 4);
    const uint32_t bRowOff = (uint32_t)(((lane >> 4) & 1) * 8 + (lane & 7)) * PITCHB;
    const uint32_t bByte   = (uint32_t)(((lane >> 3) & 1) << 4);

    int s = 0;
    for (int c = 0; c < nchunk; ++c) {
        if (c + 2 < nchunk) {
            load_chunk(c + 2, (s + 2 >= NSTAGE) ? (s + 2 - NSTAGE) : (s + 2));
            asm volatile("cp.async.wait_group 2;" ::: "memory");
        } else if (c + 1 < nchunk) {
            asm volatile("cp.async.wait_group 1;" ::: "memory");
        } else {
            asm volatile("cp.async.wait_group 0;" ::: "memory");
        }
        __syncthreads();

        const uint32_t st  = smbase + (uint32_t)s * STAGEB;
        const uint32_t sAh = st;
        const uint32_t sAl = st + PARTB;
        const uint32_t sB  = st + 2 * PARTB;

#pragma unroll
        for (int kk = 0; kk < 2; ++kk) {
            const uint32_t kb = (uint32_t)kk * 32;
            uint32_t ah[2][4], al[2][4];
#pragma unroll
            for (int mi = 0; mi < 2; ++mi) {
                uint32_t abase = (uint32_t)(wm * 32 + mi * 16) * PITCHB + aRowOff + kb + aByte;
                ldsm4(sAh + abase, ah[mi]);
                ldsm4(sAl + abase, al[mi]);
            }
#pragma unroll
            for (int p = 0; p < 4; ++p) {
                uint32_t bbase = (uint32_t)(wn * 64 + p * 16) * PITCHB + bRowOff + kb + bByte;
                uint32_t bh[4];
                ldsm4(sB + bbase, bh);
                // hi term (4 apart per accumulator), then lo term
#pragma unroll
                for (int mi = 0; mi < 2; ++mi) {
                    mma_f16(acc[mi][2 * p],     ah[mi], bh[0], bh[1]);
                    mma_f16(acc[mi][2 * p + 1], ah[mi], bh[2], bh[3]);
                }
#pragma unroll
                for (int mi = 0; mi < 2; ++mi) {
                    mma_f16(acc[mi][2 * p],     al[mi], bh[0], bh[1]);
                    mma_f16(acc[mi][2 * p + 1], al[mi], bh[2], bh[3]);
                }
            }
        }
        __syncthreads();
        ++s;
        if (s == NSTAGE) s = 0;
    }

    // ---- epilogue ----
    const bool has_bias = (bias != nullptr);
#pragma unroll
    for (int mi = 0; mi < 2; ++mi) {
        int r = row0 + wm * 32 + mi * 16 + g;
#pragma unroll
        for (int ni = 0; ni < 8; ++ni) {
            int cb = col0 + wn * 64 + ni * 8 + 2 * t;
            if (cb >= Ncols) continue;
            float b0 = has_bias ? bias[cb] : 0.0f;
            float b1 = (has_bias && (cb + 1) < Ncols) ? bias[cb + 1] : 0.0f;
            float v00 = acc[mi][ni][0] + b0;
            float v01 = acc[mi][ni][1] + b1;
            float v10 = acc[mi][ni][2] + b0;
            float v11 = acc[mi][ni][3] + b1;
            if (cb + 1 < colsplit) {
                float2* d0 = reinterpret_cast<float2*>(Chead + (size_t)r * ld_head + cb);
                float2* d1 = reinterpret_cast<float2*>(Chead + (size_t)(r + 8) * ld_head + cb);
                *d0 = make_float2(v00, v01);
                *d1 = make_float2(v10, v11);
            } else {
                for (int jj = 0; jj < 2; ++jj) {
                    int col = cb + jj;
                    if (col >= Ncols) break;
                    float va = (jj == 0) ? v00 : v01;
                    float vb = (jj == 0) ? v10 : v11;
                    if (col < colsplit) {
                        Chead[(size_t)r * ld_head + col] = va;
                        Chead[(size_t)(r + 8) * ld_head + col] = vb;
                    } else {
                        Ccls[(size_t)r * CC + (col - colsplit)] = va;
                        Ccls[(size_t)(r + 8) * CC + (col - colsplit)] = vb;
                    }
                }
            }
        }
    }
}

// ---------------- kernel 4: L2 normalize + fp16 output -----------------------
// Xl == nullptr -> single fp16 output; else split hi/lo.
__global__ void normalize_kernel(const float* __restrict__ X,
                                 uint16_t* __restrict__ Xh,
                                 uint16_t* __restrict__ Xl,
                                 int rows, float extra) {
    int wwid = (blockIdx.x * blockDim.x + threadIdx.x) >> 5;
    int lane = threadIdx.x & 31;
    int total = rows * HH;
    if (wwid >= total) return;
    int n = wwid / HH;
    int h = wwid - n * HH;
    size_t base = (size_t)n * NH + h * PP;
    const float4* p4 = reinterpret_cast<const float4*>(X + base);
    float4 v0 = p4[lane];
    float4 v1 = p4[lane + 32];
    float ss = v0.x * v0.x + v0.y * v0.y + v0.z * v0.z + v0.w * v0.w
             + v1.x * v1.x + v1.y * v1.y + v1.z * v1.z + v1.w * v1.w;
#pragma unroll
    for (int off = 16; off > 0; off >>= 1)
        ss += __shfl_xor_sync(0xffffffffu, ss, off);
    float sc = extra / fmaxf(sqrtf(ss), EPSN);
    float a0 = v0.x * sc, a1 = v0.y * sc, a2 = v0.z * sc, a3 = v0.w * sc;
    float a4 = v1.x * sc, a5 = v1.y * sc, a6 = v1.z * sc, a7 = v1.w * sc;
    if (Xl == nullptr) {
        ushort4 h0, h1;
        h0.x = tohalf(a0); h0.y = tohalf(a1); h0.z = tohalf(a2); h0.w = tohalf(a3);
        h1.x = tohalf(a4); h1.y = tohalf(a5); h1.z = tohalf(a6); h1.w = tohalf(a7);
        ushort4* ph = reinterpret_cast<ushort4*>(Xh + base);
        ph[lane] = h0; ph[lane + 32] = h1;
    } else {
        ushort4 h0, l0, h1, l1;
        split1(a0, h0.x, l0.x); split1(a1, h0.y, l0.y);
        split1(a2, h0.z, l0.z); split1(a3, h0.w, l0.w);
        split1(a4, h1.x, l1.x); split1(a5, h1.y, l1.y);
        split1(a6, h1.z, l1.z); split1(a7, h1.w, l1.w);
        ushort4* ph = reinterpret_cast<ushort4*>(Xh + base);
        ushort4* pl = reinterpret_cast<ushort4*>(Xl + base);
        ph[lane] = h0; ph[lane + 32] = h1;
        pl[lane] = l0; pl[lane + 32] = l1;
    }
}

// ---------------- launch -------------------------------------------------------
extern "C" void kernel_launch(void* const* d_in, const int* in_sizes, int n_in,
                              void* d_out, int out_size) {
    const float* query   = (const float*)d_in[0];
    const float* support = (const float*)d_in[1];
    const float* head_W  = (const float*)d_in[2];
    const float* head_b  = (const float*)d_in[3];
    const float* cls_W   = (const float*)d_in[4];
    const float* cls_b   = (const float*)d_in[5];

    float* out_match = (float*)d_out;
    float* out_preds = (float*)d_out + (size_t)NQ * NS;

    uint16_t *Aggh, *Aggl, *Suph, *Supl, *Wt, *Qh, *Ql, *Sn;
    float *bias, *Qf, *Sf;
    cudaGetSymbolAddress((void**)&Aggh, g_Aggh);
    cudaGetSymbolAddress((void**)&Aggl, g_Aggl);
    cudaGetSymbolAddress((void**)&Suph, g_Suph);
    cudaGetSymbolAddress((void**)&Supl, g_Supl);
    cudaGetSymbolAddress((void**)&Wt,   g_Wt);
    cudaGetSymbolAddress((void**)&bias, g_bias);
    cudaGetSymbolAddress((void**)&Qf,   g_Qf);
    cudaGetSymbolAddress((void**)&Sf,   g_Sf);
    cudaGetSymbolAddress((void**)&Qh,   g_Qh);
    cudaGetSymbolAddress((void**)&Ql,   g_Ql);
    cudaGetSymbolAddress((void**)&Sn,   g_Sn);

    cudaFuncSetAttribute(gemm2x_kernel,
                         cudaFuncAttributeMaxDynamicSharedMemorySize, SMEMB);

    {
        int n4 = (NQ * DD) / 4;
        mean_kernel<<<(n4 + 255) / 256, 256>>>(query);
        int s4 = (NS * DD) / 4;
        split_support_kernel<<<(s4 + 255) / 256, 256>>>(support);
    }
    {
        int total = NTOT * DD;
        pack_kernel<<<(total + 255) / 256, 256>>>(head_W, head_b, cls_W, cls_b);
    }
    // Q projection: A = mean(query) split, B = Wt single
    {
        dim3 grid(NH / BN, NQ / BM);
        gemm2x_kernel<<<grid, 256, SMEMB>>>(Aggh, Aggl, Wt, DD, NH, bias,
                                            Qf, NH, nullptr, NH);
    }
    // S projection + classifier
    {
        dim3 grid((NTOT + BN - 1) / BN, NS / BM);
        gemm2x_kernel<<<grid, 256, SMEMB>>>(Suph, Supl, Wt, DD, NTOT, bias,
                                            Sf, NH, out_preds, NH);
    }
    // normalize: Q -> split (folds 1/H), S -> single
    {
        int warpsQ = NQ * HH;
        normalize_kernel<<<(warpsQ * 32 + 255) / 256, 256>>>(Qf, Qh, Ql, NQ,
                                                             1.0f / (float)HH);
        int warpsS = NS * HH;
        normalize_kernel<<<(warpsS * 32 + 255) / 256, 256>>>(Sf, Sn, nullptr, NS, 1.0f);
    }
    // match GEMM: A = Qn split, B = Sn single
    {
        dim3 grid(NS / BN, NQ / BM);
        gemm2x_kernel<<<grid, 256, SMEMB>>>(Qh, Ql, Sn, NH, NS, nullptr,
                                            out_match, NS, nullptr, NS);
    }
}

// round 7
// speedup vs baseline: 3.9605x; 1.1182x over previous
#include <cuda_runtime.h>
#include <cuda_fp16.h>
#include <cstdint>
#include <math.h>

// ---------------- problem constants ----------------------------------------
#define NQ     4096
#define DD     1024
#define NS     2048
#define HH     3
#define PP     256
#define CC     100
#define NH     768
#define NTOT   868
#define EPSN   1e-8f

// ---------------- GEMM tiling ----------------------------------------------
#define BM     128
#define BN     128
#define BK     64
#define PITCHB 144               // 128 B data + 16 B pad (conflict-free)
#define PARTB  (BM * PITCHB)     // 18432 B
#define STAGEB (3 * PARTB)       // Ah | Al | B  (55296 B)
#define NSTAGE 2
#define SMEMB  (NSTAGE * STAGEB) // 110592 B -> 2 CTAs/SM (221184 <= 228K)

// ---------------- scratch --------------------------------------------------
__device__ uint16_t g_Aggh[NQ * DD], g_Aggl[NQ * DD];   // fp16 split of mean(query)
__device__ uint16_t g_Suph[NS * DD], g_Supl[NS * DD];   // fp16 split of support
__device__ uint16_t g_Wt[NTOT * DD];                    // single fp16 W^T
__device__ float    g_bias[NTOT];
__device__ float    g_Qf[NQ * NH];
__device__ float    g_Sf[NS * NH];
__device__ uint16_t g_Qh[NQ * NH], g_Ql[NQ * NH];       // fp16 split of normalized Q
__device__ uint16_t g_Sn[NS * NH];                      // single fp16 normalized S

// ---------------- helpers ----------------------------------------------------
__device__ __forceinline__ uint32_t smem_u32_of(const void* p) {
    uint32_t a;
    asm("{ .reg .u64 t; cvta.to.shared.u64 t, %1; cvt.u32.u64 %0, t; }"
        : "=r"(a) : "l"(p));
    return a;
}

__device__ __forceinline__ void ldsm4(uint32_t addr, uint32_t* r) {
    asm volatile("ldmatrix.sync.aligned.m8n8.x4.shared.b16 {%0,%1,%2,%3}, [%4];"
                 : "=r"(r[0]), "=r"(r[1]), "=r"(r[2]), "=r"(r[3]) : "r"(addr));
}

__device__ __forceinline__ void split1(float x, uint16_t& h, uint16_t& l) {
    __half hh = __float2half_rn(x);
    float r = x - __half2float(hh);
    __half ll = __float2half_rn(r);
    h = __half_as_ushort(hh);
    l = __half_as_ushort(ll);
}

__device__ __forceinline__ uint16_t tohalf(float x) {
    return __half_as_ushort(__float2half_rn(x));
}

__device__ __forceinline__ void mma_f16(float* c, const uint32_t* a,
                                        uint32_t b0, uint32_t b1) {
    asm volatile(
        "mma.sync.aligned.m16n8k16.row.col.f32.f16.f16.f32 "
        "{%0,%1,%2,%3}, {%4,%5,%6,%7}, {%8,%9}, {%0,%1,%2,%3};"
        : "+f"(c[0]), "+f"(c[1]), "+f"(c[2]), "+f"(c[3])
        : "r"(a[0]), "r"(a[1]), "r"(a[2]), "r"(a[3]), "r"(b0), "r"(b1));
}

// ---------------- kernel 1: mean over frames + fp16 split --------------------
__global__ void mean_kernel(const float* __restrict__ q) {
    int i = blockIdx.x * blockDim.x + threadIdx.x;
    const int n4 = (NQ * DD) / 4;
    if (i >= n4) return;
    const float4* p = reinterpret_cast<const float4*>(q);
    float4 a = p[i], b = p[i + n4], c = p[i + 2 * n4], d = p[i + 3 * n4];
    float v0 = 0.25f * (a.x + b.x + c.x + d.x);
    float v1 = 0.25f * (a.y + b.y + c.y + d.y);
    float v2 = 0.25f * (a.z + b.z + c.z + d.z);
    float v3 = 0.25f * (a.w + b.w + c.w + d.w);
    ushort4 hs, ls;
    split1(v0, hs.x, ls.x); split1(v1, hs.y, ls.y);
    split1(v2, hs.z, ls.z); split1(v3, hs.w, ls.w);
    reinterpret_cast<ushort4*>(g_Aggh)[i] = hs;
    reinterpret_cast<ushort4*>(g_Aggl)[i] = ls;
}

// ---------------- kernel 1b: split support ----------------------------------
__global__ void split_support_kernel(const float* __restrict__ s) {
    int i = blockIdx.x * blockDim.x + threadIdx.x;
    const int n4 = (NS * DD) / 4;
    if (i >= n4) return;
    float4 v = reinterpret_cast<const float4*>(s)[i];
    ushort4 hs, ls;
    split1(v.x, hs.x, ls.x); split1(v.y, hs.y, ls.y);
    split1(v.z, hs.z, ls.z); split1(v.w, hs.w, ls.w);
    reinterpret_cast<ushort4*>(g_Suph)[i] = hs;
    reinterpret_cast<ushort4*>(g_Supl)[i] = ls;
}

// ---------------- kernel 2: pack W^T + bias (single fp16) ---------------------
__global__ void pack_kernel(const float* __restrict__ hW,
                            const float* __restrict__ hb,
                            const float* __restrict__ cW,
                            const float* __restrict__ cb) {
    int i = blockIdx.x * blockDim.x + threadIdx.x;
    if (i < NTOT * DD) {
        int n = i >> 10;
        int k = i & 1023;
        float v;
        if (n < NH) {
            int h = n >> 8;
            int p = n & 255;
            v = hW[((size_t)h * DD + k) * PP + p];
        } else {
            v = cW[(size_t)k * CC + (n - NH)];
        }
        g_Wt[i] = tohalf(v);
    }
    if (i < NTOT) g_bias[i] = (i < NH) ? hb[i] : cb[i - NH];
}

// ---------------- kernel 3: fp16x2 HMMA GEMM (NT), BK=64, 2 CTAs/SM -----------
__global__ void __launch_bounds__(256, 2)
gemm2x_kernel(const uint16_t* __restrict__ Ah,
              const uint16_t* __restrict__ Al,
              const uint16_t* __restrict__ B,
              int K, int Ncols, const float* __restrict__ bias,
              float* __restrict__ Chead, int ld_head,
              float* __restrict__ Ccls, int colsplit) {
    extern __shared__ __align__(128) char smem[];
    const uint32_t smbase = smem_u32_of(smem);

    const int tid = threadIdx.x;
    const int lane = tid & 31;
    const int wid = tid >> 5;
    const int wm = wid >> 1;
    const int wn = wid & 1;
    const int g = lane >> 2;
    const int t = lane & 3;
    const int row0 = blockIdx.y * BM;
    const int col0 = blockIdx.x * BN;
    const int nchunk = K / BK;

    float acc[2][8][4];
#pragma unroll
    for (int mi = 0; mi < 2; ++mi)
#pragma unroll
        for (int ni = 0; ni < 8; ++ni)
#pragma unroll
            for (int j = 0; j < 4; ++j) acc[mi][ni][j] = 0.0f;

    // loader: 3 parts x 128 rows x 8 x 16B = 3072 chunks; 12 per thread
    auto load_chunk = [&](int c, int s) {
        const uint32_t st = smbase + (uint32_t)s * STAGEB;
        const int k0 = c * BK;
#pragma unroll
        for (int j = 0; j < 12; ++j) {
            int idx = tid + 256 * j;
            int part = idx >> 10;          // 0:Ah 1:Al 2:B
            int within = idx & 1023;
            int r = within >> 3;
            int q = within & 7;
            uint32_t dst = st + (uint32_t)part * PARTB + r * PITCHB + q * 16;
            const uint16_t* src;
            int sz = 16;
            if (part == 0) {
                src = Ah + (size_t)(row0 + r) * K + k0 + q * 8;
            } else if (part == 1) {
                src = Al + (size_t)(row0 + r) * K + k0 + q * 8;
            } else {
                int n = col0 + r;
                if (n < Ncols) {
                    src = B + (size_t)n * K + k0 + q * 8;
                } else {
                    src = B;
                    sz = 0;
                }
            }
            asm volatile("cp.async.cg.shared.global [%0], [%1], 16, %2;"
                         :: "r"(dst), "l"(src), "r"(sz) : "memory");
        }
        asm volatile("cp.async.commit_group;" ::: "memory");
    };

    load_chunk(0, 0);

    const uint32_t aRowOff = (uint32_t)(lane & 15) * PITCHB;
    const uint32_t aByte   = (uint32_t)((lane >> 4) << 4);
    const uint32_t bRowOff = (uint32_t)(((lane >> 4) & 1) * 8 + (lane & 7)) * PITCHB;
    const uint32_t bByte   = (uint32_t)(((lane >> 3) & 1) << 4);

    for (int c = 0; c < nchunk; ++c) {
        const int s = c & 1;
        if (c + 1 < nchunk) {
            load_chunk(c + 1, s ^ 1);
            asm volatile("cp.async.wait_group 1;" ::: "memory");
        } else {
            asm volatile("cp.async.wait_group 0;" ::: "memory");
        }
        __syncthreads();

        const uint32_t st  = smbase + (uint32_t)s * STAGEB;
        const uint32_t sAh = st;
        const uint32_t sAl = st + PARTB;
        const uint32_t sB  = st + 2 * PARTB;

#pragma unroll
        for (int kk = 0; kk < 4; ++kk) {
            const uint32_t kb = (uint32_t)kk * 32;
            uint32_t ah[2][4], al[2][4];
#pragma unroll
            for (int mi = 0; mi < 2; ++mi) {
                uint32_t abase = (uint32_t)(wm * 32 + mi * 16) * PITCHB + aRowOff + kb + aByte;
                ldsm4(sAh + abase, ah[mi]);
                ldsm4(sAl + abase, al[mi]);
            }
#pragma unroll
            for (int p = 0; p < 4; ++p) {
                uint32_t bbase = (uint32_t)(wn * 64 + p * 16) * PITCHB + bRowOff + kb + bByte;
                uint32_t bh[4];
                ldsm4(sB + bbase, bh);
#pragma unroll
                for (int mi = 0; mi < 2; ++mi) {
                    mma_f16(acc[mi][2 * p],     ah[mi], bh[0], bh[1]);
                    mma_f16(acc[mi][2 * p + 1], ah[mi], bh[2], bh[3]);
                }
#pragma unroll
                for (int mi = 0; mi < 2; ++mi) {
                    mma_f16(acc[mi][2 * p],     al[mi], bh[0], bh[1]);
                    mma_f16(acc[mi][2 * p + 1], al[mi], bh[2], bh[3]);
                }
            }
        }
        __syncthreads();
    }

    // ---- epilogue ----
    const bool has_bias = (bias != nullptr);
#pragma unroll
    for (int mi = 0; mi < 2; ++mi) {
        int r = row0 + wm * 32 + mi * 16 + g;
#pragma unroll
        for (int ni = 0; ni < 8; ++ni) {
            int cb = col0 + wn * 64 + ni * 8 + 2 * t;
            if (cb >= Ncols) continue;
            float b0 = has_bias ? bias[cb] : 0.0f;
            float b1 = (has_bias && (cb + 1) < Ncols) ? bias[cb + 1] : 0.0f;
            float v00 = acc[mi][ni][0] + b0;
            float v01 = acc[mi][ni][1] + b1;
            float v10 = acc[mi][ni][2] + b0;
            float v11 = acc[mi][ni][3] + b1;
            if (cb + 1 < colsplit) {
                float2* d0 = reinterpret_cast<float2*>(Chead + (size_t)r * ld_head + cb);
                float2* d1 = reinterpret_cast<float2*>(Chead + (size_t)(r + 8) * ld_head + cb);
                *d0 = make_float2(v00, v01);
                *d1 = make_float2(v10, v11);
            } else {
                for (int jj = 0; jj < 2; ++jj) {
                    int col = cb + jj;
                    if (col >= Ncols) break;
                    float va = (jj == 0) ? v00 : v01;
                    float vb = (jj == 0) ? v10 : v11;
                    if (col < colsplit) {
                        Chead[(size_t)r * ld_head + col] = va;
                        Chead[(size_t)(r + 8) * ld_head + col] = vb;
                    } else {
                        Ccls[(size_t)r * CC + (col - colsplit)] = va;
                        Ccls[(size_t)(r + 8) * CC + (col - colsplit)] = vb;
                    }
                }
            }
        }
    }
}

// ---------------- kernel 4: L2 normalize + fp16 output -----------------------
__global__ void normalize_kernel(const float* __restrict__ X,
                                 uint16_t* __restrict__ Xh,
                                 uint16_t* __restrict__ Xl,
                                 int rows, float extra) {
    int wwid = (blockIdx.x * blockDim.x + threadIdx.x) >> 5;
    int lane = threadIdx.x & 31;
    int total = rows * HH;
    if (wwid >= total) return;
    int n = wwid / HH;
    int h = wwid - n * HH;
    size_t base = (size_t)n * NH + h * PP;
    const float4* p4 = reinterpret_cast<const float4*>(X + base);
    float4 v0 = p4[lane];
    float4 v1 = p4[lane + 32];
    float ss = v0.x * v0.x + v0.y * v0.y + v0.z * v0.z + v0.w * v0.w
             + v1.x * v1.x + v1.y * v1.y + v1.z * v1.z + v1.w * v1.w;
#pragma unroll
    for (int off = 16; off > 0; off >>= 1)
        ss += __shfl_xor_sync(0xffffffffu, ss, off);
    float sc = extra / fmaxf(sqrtf(ss), EPSN);
    float a0 = v0.x * sc, a1 = v0.y * sc, a2 = v0.z * sc, a3 = v0.w * sc;
    float a4 = v1.x * sc, a5 = v1.y * sc, a6 = v1.z * sc, a7 = v1.w * sc;
    if (Xl == nullptr) {
        ushort4 h0, h1;
        h0.x = tohalf(a0); h0.y = tohalf(a1); h0.z = tohalf(a2); h0.w = tohalf(a3);
        h1.x = tohalf(a4); h1.y = tohalf(a5); h1.z = tohalf(a6); h1.w = tohalf(a7);
        ushort4* ph = reinterpret_cast<ushort4*>(Xh + base);
        ph[lane] = h0; ph[lane + 32] = h1;
    } else {
        ushort4 h0, l0, h1, l1;
        split1(a0, h0.x, l0.x); split1(a1, h0.y, l0.y);
        split1(a2, h0.z, l0.z); split1(a3, h0.w, l0.w);
        split1(a4, h1.x, l1.x); split1(a5, h1.y, l1.y);
        split1(a6, h1.z, l1.z); split1(a7, h1.w, l1.w);
        ushort4* ph = reinterpret_cast<ushort4*>(Xh + base);
        ushort4* pl = reinterpret_cast<ushort4*>(Xl + base);
        ph[lane] = h0; ph[lane + 32] = h1;
        pl[lane] = l0; pl[lane + 32] = l1;
    }
}

// ---------------- launch -------------------------------------------------------
extern "C" void kernel_launch(void* const* d_in, const int* in_sizes, int n_in,
                              void* d_out, int out_size) {
    const float* query   = (const float*)d_in[0];
    const float* support = (const float*)d_in[1];
    const float* head_W  = (const float*)d_in[2];
    const float* head_b  = (const float*)d_in[3];
    const float* cls_W   = (const float*)d_in[4];
    const float* cls_b   = (const float*)d_in[5];

    float* out_match = (float*)d_out;
    float* out_preds = (float*)d_out + (size_t)NQ * NS;

    uint16_t *Aggh, *Aggl, *Suph, *Supl, *Wt, *Qh, *Ql, *Sn;
    float *bias, *Qf, *Sf;
    cudaGetSymbolAddress((void**)&Aggh, g_Aggh);
    cudaGetSymbolAddress((void**)&Aggl, g_Aggl);
    cudaGetSymbolAddress((void**)&Suph, g_Suph);
    cudaGetSymbolAddress((void**)&Supl, g_Supl);
    cudaGetSymbolAddress((void**)&Wt,   g_Wt);
    cudaGetSymbolAddress((void**)&bias, g_bias);
    cudaGetSymbolAddress((void**)&Qf,   g_Qf);
    cudaGetSymbolAddress((void**)&Sf,   g_Sf);
    cudaGetSymbolAddress((void**)&Qh,   g_Qh);
    cudaGetSymbolAddress((void**)&Ql,   g_Ql);
    cudaGetSymbolAddress((void**)&Sn,   g_Sn);

    cudaFuncSetAttribute(gemm2x_kernel,
                         cudaFuncAttributeMaxDynamicSharedMemorySize, SMEMB);

    {
        int n4 = (NQ * DD) / 4;
        mean_kernel<<<(n4 + 255) / 256, 256>>>(query);
        int s4 = (NS * DD) / 4;
        split_support_kernel<<<(s4 + 255) / 256, 256>>>(support);
    }
    {
        int total = NTOT * DD;
        pack_kernel<<<(total + 255) / 256, 256>>>(head_W, head_b, cls_W, cls_b);
    }
    // Q projection
    {
        dim3 grid(NH / BN, NQ / BM);
        gemm2x_kernel<<<grid, 256, SMEMB>>>(Aggh, Aggl, Wt, DD, NH, bias,
                                            Qf, NH, nullptr, NH);
    }
    // S projection + classifier
    {
        dim3 grid((NTOT + BN - 1) / BN, NS / BM);
        gemm2x_kernel<<<grid, 256, SMEMB>>>(Suph, Supl, Wt, DD, NTOT, bias,
                                            Sf, NH, out_preds, NH);
    }
    // normalize: Q -> split (folds 1/H), S -> single fp16
    {
        int warpsQ = NQ * HH;
        normalize_kernel<<<(warpsQ * 32 + 255) / 256, 256>>>(Qf, Qh, Ql, NQ,
                                                             1.0f / (float)HH);
        int warpsS = NS * HH;
        normalize_kernel<<<(warpsS * 32 + 255) / 256, 256>>>(Sf, Sn, nullptr, NS, 1.0f);
    }
    // match GEMM
    {
        dim3 grid(NS / BN, NQ / BM);
        gemm2x_kernel<<<grid, 256, SMEMB>>>(Qh, Ql, Sn, NH, NS, nullptr,
                                            out_match, NS, nullptr, NS);
    }
}

// round 8
// speedup vs baseline: 4.7856x; 1.2083x over previous
#include <cuda_runtime.h>
#include <cuda_fp16.h>
#include <cstdint>
#include <math.h>

// ---------------- problem constants ----------------------------------------
#define NQ     4096
#define DD     1024
#define NS     2048
#define HH     3
#define PP     256
#define CC     100
#define NH     768
#define NTOT   868
#define MTOTAL (NQ + NS)         // 6144 merged projection rows
#define EPSN   1e-8f

// ---------------- GEMM tiling ----------------------------------------------
#define BM     128
#define BN     128
#define BK     64
#define PITCHB 144               // 128 B data + 16 B pad (conflict-free)
#define PARTB  (BM * PITCHB)     // 18432 B
#define STAGEB (3 * PARTB)       // Ah | Al | B  (55296 B)
#define SMEMB  (2 * STAGEB)      // 110592 B -> 2 CTAs/SM

// ---------------- scratch --------------------------------------------------
__device__ uint16_t g_Xh[MTOTAL * DD];   // fp16 hi: rows 0..4095 mean(query), 4096.. support
__device__ uint16_t g_Xl[MTOTAL * DD];   // fp16 lo
__device__ uint16_t g_Wt[NTOT * DD];     // single fp16 W^T
__device__ float    g_bias[NTOT];
__device__ float    g_Qf[NQ * NH];
__device__ float    g_Sf[NS * NH];
__device__ uint16_t g_Qn[NQ * NH];       // single fp16 normalized Q (x 1/H)
__device__ uint16_t g_Sn[NS * NH];       // single fp16 normalized S

// ---------------- helpers ----------------------------------------------------
__device__ __forceinline__ uint32_t smem_u32_of(const void* p) {
    uint32_t a;
    asm("{ .reg .u64 t; cvta.to.shared.u64 t, %1; cvt.u32.u64 %0, t; }"
        : "=r"(a) : "l"(p));
    return a;
}

__device__ __forceinline__ void ldsm4(uint32_t addr, uint32_t* r) {
    asm volatile("ldmatrix.sync.aligned.m8n8.x4.shared.b16 {%0,%1,%2,%3}, [%4];"
                 : "=r"(r[0]), "=r"(r[1]), "=r"(r[2]), "=r"(r[3]) : "r"(addr));
}

__device__ __forceinline__ void split1(float x, uint16_t& h, uint16_t& l) {
    __half hh = __float2half_rn(x);
    float r = x - __half2float(hh);
    __half ll = __float2half_rn(r);
    h = __half_as_ushort(hh);
    l = __half_as_ushort(ll);
}

__device__ __forceinline__ uint16_t tohalf(float x) {
    return __half_as_ushort(__float2half_rn(x));
}

__device__ __forceinline__ void mma_f16(float* c, const uint32_t* a,
                                        uint32_t b0, uint32_t b1) {
    asm volatile(
        "mma.sync.aligned.m16n8k16.row.col.f32.f16.f16.f32 "
        "{%0,%1,%2,%3}, {%4,%5,%6,%7}, {%8,%9}, {%0,%1,%2,%3};"
        : "+f"(c[0]), "+f"(c[1]), "+f"(c[2]), "+f"(c[3])
        : "r"(a[0]), "r"(a[1]), "r"(a[2]), "r"(a[3]), "r"(b0), "r"(b1));
}

// ---------------- kernel 1: mean over frames + fp16 split --------------------
__global__ void mean_kernel(const float* __restrict__ q) {
    int i = blockIdx.x * blockDim.x + threadIdx.x;
    const int n4 = (NQ * DD) / 4;
    if (i >= n4) return;
    const float4* p = reinterpret_cast<const float4*>(q);
    float4 a = p[i], b = p[i + n4], c = p[i + 2 * n4], d = p[i + 3 * n4];
    float v0 = 0.25f * (a.x + b.x + c.x + d.x);
    float v1 = 0.25f * (a.y + b.y + c.y + d.y);
    float v2 = 0.25f * (a.z + b.z + c.z + d.z);
    float v3 = 0.25f * (a.w + b.w + c.w + d.w);
    ushort4 hs, ls;
    split1(v0, hs.x, ls.x); split1(v1, hs.y, ls.y);
    split1(v2, hs.z, ls.z); split1(v3, hs.w, ls.w);
    reinterpret_cast<ushort4*>(g_Xh)[i] = hs;
    reinterpret_cast<ushort4*>(g_Xl)[i] = ls;
}

// ---------------- kernel 1b: split support into rows NQ.. -------------------
__global__ void split_support_kernel(const float* __restrict__ s) {
    int i = blockIdx.x * blockDim.x + threadIdx.x;
    const int n4 = (NS * DD) / 4;
    if (i >= n4) return;
    const int off4 = (NQ * DD) / 4;
    float4 v = reinterpret_cast<const float4*>(s)[i];
    ushort4 hs, ls;
    split1(v.x, hs.x, ls.x); split1(v.y, hs.y, ls.y);
    split1(v.z, hs.z, ls.z); split1(v.w, hs.w, ls.w);
    reinterpret_cast<ushort4*>(g_Xh)[off4 + i] = hs;
    reinterpret_cast<ushort4*>(g_Xl)[off4 + i] = ls;
}

// ---------------- kernel 2: pack W^T + bias (single fp16) ---------------------
__global__ void pack_kernel(const float* __restrict__ hW,
                            const float* __restrict__ hb,
                            const float* __restrict__ cW,
                            const float* __restrict__ cb) {
    int i = blockIdx.x * blockDim.x + threadIdx.x;
    if (i < NTOT * DD) {
        int n = i >> 10;
        int k = i & 1023;
        float v;
        if (n < NH) {
            int h = n >> 8;
            int p = n & 255;
            v = hW[((size_t)h * DD + k) * PP + p];
        } else {
            v = cW[(size_t)k * CC + (n - NH)];
        }
        g_Wt[i] = tohalf(v);
    }
    if (i < NTOT) g_bias[i] = (i < NH) ? hb[i] : cb[i - NH];
}

// ---------------- kernel 3: fp16 HMMA GEMM (NT), optional A-split -------------
// Output routing: row r < m_split -> Cq (ld_q), cols [0, colsplit) only.
//                 row r >= m_split -> rr = r - m_split;
//                     col < colsplit -> Cs (ld_s); col >= colsplit -> Ccls (ld CC)
template <bool SPLIT_A>
__global__ void __launch_bounds__(256, 2)
gemm_kernel(const uint16_t* __restrict__ Ah,
            const uint16_t* __restrict__ Al,
            const uint16_t* __restrict__ B,
            int K, int Ncols, const float* __restrict__ bias,
            float* __restrict__ Cq, int ld_q,
            float* __restrict__ Cs, int ld_s,
            float* __restrict__ Ccls,
            int m_split, int colsplit) {
    extern __shared__ __align__(128) char smem[];
    const uint32_t smbase = smem_u32_of(smem);

    const int tid = threadIdx.x;
    const int lane = tid & 31;
    const int wid = tid >> 5;
    const int wm = wid >> 1;
    const int wn = wid & 1;
    const int g = lane >> 2;
    const int t = lane & 3;
    const int row0 = blockIdx.y * BM;
    const int col0 = blockIdx.x * BN;
    const int nchunk = K / BK;

    float acc[2][8][4];
#pragma unroll
    for (int mi = 0; mi < 2; ++mi)
#pragma unroll
        for (int ni = 0; ni < 8; ++ni)
#pragma unroll
            for (int j = 0; j < 4; ++j) acc[mi][ni][j] = 0.0f;

    constexpr int NLOAD = SPLIT_A ? 12 : 8;

    auto load_chunk = [&](int c, int s) {
        const uint32_t st = smbase + (uint32_t)s * STAGEB;
        const int k0 = c * BK;
#pragma unroll
        for (int j = 0; j < NLOAD; ++j) {
            int idx = tid + 256 * j;
            int plin = idx >> 10;
            int part = SPLIT_A ? plin : (plin == 0 ? 0 : 2);
            int within = idx & 1023;
            int r = within >> 3;
            int q = within & 7;
            uint32_t dst = st + (uint32_t)part * PARTB + r * PITCHB + q * 16;
            const uint16_t* src;
            int sz = 16;
            if (part == 0) {
                src = Ah + (size_t)(row0 + r) * K + k0 + q * 8;
            } else if (part == 1) {
                src = Al + (size_t)(row0 + r) * K + k0 + q * 8;
            } else {
                int n = col0 + r;
                if (n < Ncols) {
                    src = B + (size_t)n * K + k0 + q * 8;
                } else {
                    src = B;
                    sz = 0;
                }
            }
            asm volatile("cp.async.cg.shared.global [%0], [%1], 16, %2;"
                         :: "r"(dst), "l"(src), "r"(sz) : "memory");
        }
        asm volatile("cp.async.commit_group;" ::: "memory");
    };

    load_chunk(0, 0);

    const uint32_t aRowOff = (uint32_t)(lane & 15) * PITCHB;
    const uint32_t aByte   = (uint32_t)((lane >> 4) << 4);
    const uint32_t bRowOff = (uint32_t)(((lane >> 4) & 1) * 8 + (lane & 7)) * PITCHB;
    const uint32_t bByte   = (uint32_t)(((lane >> 3) & 1) << 4);

    for (int c = 0; c < nchunk; ++c) {
        const int s = c & 1;
        if (c + 1 < nchunk) {
            load_chunk(c + 1, s ^ 1);
            asm volatile("cp.async.wait_group 1;" ::: "memory");
        } else {
            asm volatile("cp.async.wait_group 0;" ::: "memory");
        }
        __syncthreads();

        const uint32_t st  = smbase + (uint32_t)s * STAGEB;
        const uint32_t sAh = st;
        const uint32_t sAl = st + PARTB;
        const uint32_t sB  = st + 2 * PARTB;

#pragma unroll
        for (int kk = 0; kk < 4; ++kk) {
            const uint32_t kb = (uint32_t)kk * 32;
            uint32_t ah[2][4], al[2][4];
#pragma unroll
            for (int mi = 0; mi < 2; ++mi) {
                uint32_t abase = (uint32_t)(wm * 32 + mi * 16) * PITCHB + aRowOff + kb + aByte;
                ldsm4(sAh + abase, ah[mi]);
                if (SPLIT_A) ldsm4(sAl + abase, al[mi]);
            }
#pragma unroll
            for (int p = 0; p < 4; ++p) {
                uint32_t bbase = (uint32_t)(wn * 64 + p * 16) * PITCHB + bRowOff + kb + bByte;
                uint32_t bh[4];
                ldsm4(sB + bbase, bh);
#pragma unroll
                for (int mi = 0; mi < 2; ++mi) {
                    mma_f16(acc[mi][2 * p],     ah[mi], bh[0], bh[1]);
                    mma_f16(acc[mi][2 * p + 1], ah[mi], bh[2], bh[3]);
                }
                if (SPLIT_A) {
#pragma unroll
                    for (int mi = 0; mi < 2; ++mi) {
                        mma_f16(acc[mi][2 * p],     al[mi], bh[0], bh[1]);
                        mma_f16(acc[mi][2 * p + 1], al[mi], bh[2], bh[3]);
                    }
                }
            }
        }
        __syncthreads();
    }

    // ---- epilogue ----
    const bool has_bias = (bias != nullptr);
#pragma unroll
    for (int mi = 0; mi < 2; ++mi) {
        int rbase = row0 + wm * 32 + mi * 16 + g;
#pragma unroll
        for (int ni = 0; ni < 8; ++ni) {
            int cb = col0 + wn * 64 + ni * 8 + 2 * t;
            if (cb >= Ncols) continue;
            float b0 = has_bias ? bias[cb] : 0.0f;
            float b1 = (has_bias && (cb + 1) < Ncols) ? bias[cb + 1] : 0.0f;
            float vals[2][2] = { { acc[mi][ni][0] + b0, acc[mi][ni][1] + b1 },
                                 { acc[mi][ni][2] + b0, acc[mi][ni][3] + b1 } };
#pragma unroll
            for (int rr2 = 0; rr2 < 2; ++rr2) {
                int r = rbase + rr2 * 8;
                if (r < m_split) {
                    // Q-side rows: only head columns
                    if (cb + 1 < colsplit) {
                        *reinterpret_cast<float2*>(Cq + (size_t)r * ld_q + cb) =
                            make_float2(vals[rr2][0], vals[rr2][1]);
                    } else {
                        if (cb < colsplit) Cq[(size_t)r * ld_q + cb] = vals[rr2][0];
                        if (cb + 1 < colsplit && cb + 1 < Ncols)
                            Cq[(size_t)r * ld_q + cb + 1] = vals[rr2][1];
                    }
                } else {
                    int rs = r - m_split;
#pragma unroll
                    for (int jj = 0; jj < 2; ++jj) {
                        int col = cb + jj;
                        if (col >= Ncols) break;
                        float v = vals[rr2][jj];
                        if (col < colsplit)
                            Cs[(size_t)rs * ld_s + col] = v;
                        else
                            Ccls[(size_t)rs * CC + (col - colsplit)] = v;
                    }
                }
            }
        }
    }
}

// ---------------- kernel 4: L2 normalize -> single fp16 ----------------------
__global__ void normalize_kernel(const float* __restrict__ X,
                                 uint16_t* __restrict__ Xo,
                                 int rows, float extra) {
    int wwid = (blockIdx.x * blockDim.x + threadIdx.x) >> 5;
    int lane = threadIdx.x & 31;
    int total = rows * HH;
    if (wwid >= total) return;
    int n = wwid / HH;
    int h = wwid - n * HH;
    size_t base = (size_t)n * NH + h * PP;
    const float4* p4 = reinterpret_cast<const float4*>(X + base);
    float4 v0 = p4[lane];
    float4 v1 = p4[lane + 32];
    float ss = v0.x * v0.x + v0.y * v0.y + v0.z * v0.z + v0.w * v0.w
             + v1.x * v1.x + v1.y * v1.y + v1.z * v1.z + v1.w * v1.w;
#pragma unroll
    for (int off = 16; off > 0; off >>= 1)
        ss += __shfl_xor_sync(0xffffffffu, ss, off);
    float sc = extra / fmaxf(sqrtf(ss), EPSN);
    ushort4 h0, h1;
    h0.x = tohalf(v0.x * sc); h0.y = tohalf(v0.y * sc);
    h0.z = tohalf(v0.z * sc); h0.w = tohalf(v0.w * sc);
    h1.x = tohalf(v1.x * sc); h1.y = tohalf(v1.y * sc);
    h1.z = tohalf(v1.z * sc); h1.w = tohalf(v1.w * sc);
    ushort4* ph = reinterpret_cast<ushort4*>(Xo + base);
    ph[lane] = h0; ph[lane + 32] = h1;
}

// ---------------- launch -------------------------------------------------------
extern "C" void kernel_launch(void* const* d_in, const int* in_sizes, int n_in,
                              void* d_out, int out_size) {
    const float* query   = (const float*)d_in[0];
    const float* support = (const float*)d_in[1];
    const float* head_W  = (const float*)d_in[2];
    const float* head_b  = (const float*)d_in[3];
    const float* cls_W   = (const float*)d_in[4];
    const float* cls_b   = (const float*)d_in[5];

    float* out_match = (float*)d_out;
    float* out_preds = (float*)d_out + (size_t)NQ * NS;

    uint16_t *Xh, *Xl, *Wt, *Qn, *Sn;
    float *bias, *Qf, *Sf;
    cudaGetSymbolAddress((void**)&Xh,   g_Xh);
    cudaGetSymbolAddress((void**)&Xl,   g_Xl);
    cudaGetSymbolAddress((void**)&Wt,   g_Wt);
    cudaGetSymbolAddress((void**)&bias, g_bias);
    cudaGetSymbolAddress((void**)&Qf,   g_Qf);
    cudaGetSymbolAddress((void**)&Sf,   g_Sf);
    cudaGetSymbolAddress((void**)&Qn,   g_Qn);
    cudaGetSymbolAddress((void**)&Sn,   g_Sn);

    cudaFuncSetAttribute(gemm_kernel<true>,
                         cudaFuncAttributeMaxDynamicSharedMemorySize, SMEMB);
    cudaFuncSetAttribute(gemm_kernel<false>,
                         cudaFuncAttributeMaxDynamicSharedMemorySize, SMEMB);

    // 1) mean over frames + support split (into merged X rows)
    {
        int n4 = (NQ * DD) / 4;
        mean_kernel<<<(n4 + 255) / 256, 256>>>(query);
        int s4 = (NS * DD) / 4;
        split_support_kernel<<<(s4 + 255) / 256, 256>>>(support);
    }
    // 2) pack W^T + bias
    {
        int total = NTOT * DD;
        pack_kernel<<<(total + 255) / 256, 256>>>(head_W, head_b, cls_W, cls_b);
    }
    // 3) merged projection GEMM: X[6144,1024] @ Wt[868,1024]^T (2-term A)
    {
        dim3 grid((NTOT + BN - 1) / BN, MTOTAL / BM);  // (7, 48) = 336 CTAs
        gemm_kernel<true><<<grid, 256, SMEMB>>>(Xh, Xl, Wt, DD, NTOT, bias,
                                                Qf, NH, Sf, NH, out_preds,
                                                NQ, NH);
    }
    // 4) normalize -> single fp16 (Q folds 1/H)
    {
        int warpsQ = NQ * HH;
        normalize_kernel<<<(warpsQ * 32 + 255) / 256, 256>>>(Qf, Qn, NQ,
                                                             1.0f / (float)HH);
        int warpsS = NS * HH;
        normalize_kernel<<<(warpsS * 32 + 255) / 256, 256>>>(Sf, Sn, NS, 1.0f);
    }
    // 5) match GEMM: Qn[4096,768] @ Sn[2048,768]^T (single-term)
    {
        dim3 grid(NS / BN, NQ / BM);  // (16, 32) = 512 CTAs
        gemm_kernel<false><<<grid, 256, SMEMB>>>(Qn, nullptr, Sn, NH, NS, nullptr,
                                                 out_match, NS, nullptr, 0, nullptr,
                                                 NQ, NS);
    }
}

// round 9
// speedup vs baseline: 5.9008x; 1.2330x over previous
#include <cuda_runtime.h>
#include <cuda_fp16.h>
#include <cstdint>
#include <math.h>

// ---------------- problem constants ----------------------------------------
#define NQ     4096
#define DD     1024
#define NS     2048
#define HH     3
#define PP     256
#define CC     100
#define NH     768
#define NTOT   868
#define MTOTAL (NQ + NS)         // 6144 merged projection rows
#define EPSN   1e-8f

// ---------------- GEMM tiling ----------------------------------------------
#define BM     128
#define BN     128
#define BK     64
#define PITCHB 144               // 128 B data + 16 B pad (conflict-free)
#define PARTB  (BM * PITCHB)     // 18432 B
#define STAGEB (2 * PARTB)       // A | B  (36864 B)
#define NSTAGE 3
#define SMEMB  (NSTAGE * STAGEB) // 110592 B -> 2 CTAs/SM

// ---------------- scratch --------------------------------------------------
__device__ uint16_t g_X[MTOTAL * DD];    // fp16: rows 0..4095 mean(query), 4096.. support
__device__ uint16_t g_Wt[NTOT * DD];     // fp16 W^T
__device__ float    g_bias[NTOT];
__device__ float    g_Qf[NQ * NH];
__device__ float    g_Sf[NS * NH];
__device__ uint16_t g_Qn[NQ * NH];       // fp16 normalized Q (x 1/H)
__device__ uint16_t g_Sn[NS * NH];       // fp16 normalized S

// ---------------- helpers ----------------------------------------------------
__device__ __forceinline__ uint32_t smem_u32_of(const void* p) {
    uint32_t a;
    asm("{ .reg .u64 t; cvta.to.shared.u64 t, %1; cvt.u32.u64 %0, t; }"
        : "=r"(a) : "l"(p));
    return a;
}

__device__ __forceinline__ void ldsm4(uint32_t addr, uint32_t* r) {
    asm volatile("ldmatrix.sync.aligned.m8n8.x4.shared.b16 {%0,%1,%2,%3}, [%4];"
                 : "=r"(r[0]), "=r"(r[1]), "=r"(r[2]), "=r"(r[3]) : "r"(addr));
}

__device__ __forceinline__ uint16_t tohalf(float x) {
    return __half_as_ushort(__float2half_rn(x));
}

__device__ __forceinline__ void mma_f16(float* c, const uint32_t* a,
                                        uint32_t b0, uint32_t b1) {
    asm volatile(
        "mma.sync.aligned.m16n8k16.row.col.f32.f16.f16.f32 "
        "{%0,%1,%2,%3}, {%4,%5,%6,%7}, {%8,%9}, {%0,%1,%2,%3};"
        : "+f"(c[0]), "+f"(c[1]), "+f"(c[2]), "+f"(c[3])
        : "r"(a[0]), "r"(a[1]), "r"(a[2]), "r"(a[3]), "r"(b0), "r"(b1));
}

// ---------------- kernel 1: mean over frames -> fp16 --------------------------
__global__ void mean_kernel(const float* __restrict__ q) {
    int i = blockIdx.x * blockDim.x + threadIdx.x;
    const int n4 = (NQ * DD) / 4;
    if (i >= n4) return;
    const float4* p = reinterpret_cast<const float4*>(q);
    float4 a = p[i], b = p[i + n4], c = p[i + 2 * n4], d = p[i + 3 * n4];
    ushort4 hs;
    hs.x = tohalf(0.25f * (a.x + b.x + c.x + d.x));
    hs.y = tohalf(0.25f * (a.y + b.y + c.y + d.y));
    hs.z = tohalf(0.25f * (a.z + b.z + c.z + d.z));
    hs.w = tohalf(0.25f * (a.w + b.w + c.w + d.w));
    reinterpret_cast<ushort4*>(g_X)[i] = hs;
}

// ---------------- kernel 1b: support -> fp16 rows NQ.. ------------------------
__global__ void split_support_kernel(const float* __restrict__ s) {
    int i = blockIdx.x * blockDim.x + threadIdx.x;
    const int n4 = (NS * DD) / 4;
    if (i >= n4) return;
    const int off4 = (NQ * DD) / 4;
    float4 v = reinterpret_cast<const float4*>(s)[i];
    ushort4 hs;
    hs.x = tohalf(v.x); hs.y = tohalf(v.y);
    hs.z = tohalf(v.z); hs.w = tohalf(v.w);
    reinterpret_cast<ushort4*>(g_X)[off4 + i] = hs;
}

// ---------------- kernel 2: pack W^T + bias (fp16) ----------------------------
__global__ void pack_kernel(const float* __restrict__ hW,
                            const float* __restrict__ hb,
                            const float* __restrict__ cW,
                            const float* __restrict__ cb) {
    int i = blockIdx.x * blockDim.x + threadIdx.x;
    if (i < NTOT * DD) {
        int n = i >> 10;
        int k = i & 1023;
        float v;
        if (n < NH) {
            int h = n >> 8;
            int p = n & 255;
            v = hW[((size_t)h * DD + k) * PP + p];
        } else {
            v = cW[(size_t)k * CC + (n - NH)];
        }
        g_Wt[i] = tohalf(v);
    }
    if (i < NTOT) g_bias[i] = (i < NH) ? hb[i] : cb[i - NH];
}

// ---------------- kernel 3: fp16 HMMA GEMM (NT), 3-stage, 2 CTAs/SM -----------
// Output routing: row r < m_split -> Cq (ld_q), cols [0, colsplit) only.
//                 row r >= m_split -> rs = r - m_split;
//                     col < colsplit -> Cs (ld_s); col >= colsplit -> Ccls (ld CC)
__global__ void __launch_bounds__(256, 2)
gemm_kernel(const uint16_t* __restrict__ A,
            const uint16_t* __restrict__ B,
            int K, int Ncols, const float* __restrict__ bias,
            float* __restrict__ Cq, int ld_q,
            float* __restrict__ Cs, int ld_s,
            float* __restrict__ Ccls,
            int m_split, int colsplit) {
    extern __shared__ __align__(128) char smem[];
    const uint32_t smbase = smem_u32_of(smem);

    const int tid = threadIdx.x;
    const int lane = tid & 31;
    const int wid = tid >> 5;
    const int wm = wid >> 1;
    const int wn = wid & 1;
    const int g = lane >> 2;
    const int t = lane & 3;
    const int row0 = blockIdx.y * BM;
    const int col0 = blockIdx.x * BN;
    const int nchunk = K / BK;

    float acc[2][8][4];
#pragma unroll
    for (int mi = 0; mi < 2; ++mi)
#pragma unroll
        for (int ni = 0; ni < 8; ++ni)
#pragma unroll
            for (int j = 0; j < 4; ++j) acc[mi][ni][j] = 0.0f;

    // loader: 2 parts x 128 rows x 8 x 16B = 2048 chunks; 8 per thread
    auto load_chunk = [&](int c, int s) {
        const uint32_t st = smbase + (uint32_t)s * STAGEB;
        const int k0 = c * BK;
#pragma unroll
        for (int j = 0; j < 8; ++j) {
            int idx = tid + 256 * j;
            int part = idx >> 10;          // 0:A 1:B
            int within = idx & 1023;
            int r = within >> 3;
            int q = within & 7;
            uint32_t dst = st + (uint32_t)part * PARTB + r * PITCHB + q * 16;
            const uint16_t* src;
            int sz = 16;
            if (part == 0) {
                src = A + (size_t)(row0 + r) * K + k0 + q * 8;
            } else {
                int n = col0 + r;
                if (n < Ncols) {
                    src = B + (size_t)n * K + k0 + q * 8;
                } else {
                    src = B;
                    sz = 0;
                }
            }
            asm volatile("cp.async.cg.shared.global [%0], [%1], 16, %2;"
                         :: "r"(dst), "l"(src), "r"(sz) : "memory");
        }
        asm volatile("cp.async.commit_group;" ::: "memory");
    };

    load_chunk(0, 0);
    load_chunk(1, 1);

    const uint32_t aRowOff = (uint32_t)(lane & 15) * PITCHB;
    const uint32_t aByte   = (uint32_t)((lane >> 4) << 4);
    const uint32_t bRowOff = (uint32_t)(((lane >> 4) & 1) * 8 + (lane & 7)) * PITCHB;
    const uint32_t bByte   = (uint32_t)(((lane >> 3) & 1) << 4);

    int s = 0;
    for (int c = 0; c < nchunk; ++c) {
        if (c + 2 < nchunk) {
            load_chunk(c + 2, (s + 2 >= NSTAGE) ? (s + 2 - NSTAGE) : (s + 2));
            asm volatile("cp.async.wait_group 2;" ::: "memory");
        } else if (c + 1 < nchunk) {
            asm volatile("cp.async.wait_group 1;" ::: "memory");
        } else {
            asm volatile("cp.async.wait_group 0;" ::: "memory");
        }
        __syncthreads();

        const uint32_t st = smbase + (uint32_t)s * STAGEB;
        const uint32_t sA = st;
        const uint32_t sB = st + PARTB;

#pragma unroll
        for (int kk = 0; kk < 4; ++kk) {
            const uint32_t kb = (uint32_t)kk * 32;
            uint32_t af[2][4];
#pragma unroll
            for (int mi = 0; mi < 2; ++mi) {
                uint32_t abase = (uint32_t)(wm * 32 + mi * 16) * PITCHB + aRowOff + kb + aByte;
                ldsm4(sA + abase, af[mi]);
            }
#pragma unroll
            for (int p = 0; p < 4; ++p) {
                uint32_t bbase = (uint32_t)(wn * 64 + p * 16) * PITCHB + bRowOff + kb + bByte;
                uint32_t bf[4];
                ldsm4(sB + bbase, bf);
#pragma unroll
                for (int mi = 0; mi < 2; ++mi) {
                    mma_f16(acc[mi][2 * p],     af[mi], bf[0], bf[1]);
                    mma_f16(acc[mi][2 * p + 1], af[mi], bf[2], bf[3]);
                }
            }
        }
        __syncthreads();
        ++s;
        if (s == NSTAGE) s = 0;
    }

    // ---- epilogue ----
    const bool has_bias = (bias != nullptr);
#pragma unroll
    for (int mi = 0; mi < 2; ++mi) {
        int rbase = row0 + wm * 32 + mi * 16 + g;
#pragma unroll
        for (int ni = 0; ni < 8; ++ni) {
            int cb = col0 + wn * 64 + ni * 8 + 2 * t;
            if (cb >= Ncols) continue;
            float b0 = has_bias ? bias[cb] : 0.0f;
            float b1 = (has_bias && (cb + 1) < Ncols) ? bias[cb + 1] : 0.0f;
            float vals[2][2] = { { acc[mi][ni][0] + b0, acc[mi][ni][1] + b1 },
                                 { acc[mi][ni][2] + b0, acc[mi][ni][3] + b1 } };
#pragma unroll
            for (int rr2 = 0; rr2 < 2; ++rr2) {
                int r = rbase + rr2 * 8;
                if (r < m_split) {
                    if (cb + 1 < colsplit) {
                        *reinterpret_cast<float2*>(Cq + (size_t)r * ld_q + cb) =
                            make_float2(vals[rr2][0], vals[rr2][1]);
                    } else {
                        if (cb < colsplit) Cq[(size_t)r * ld_q + cb] = vals[rr2][0];
                        if (cb + 1 < colsplit && cb + 1 < Ncols)
                            Cq[(size_t)r * ld_q + cb + 1] = vals[rr2][1];
                    }
                } else {
                    int rs = r - m_split;
#pragma unroll
                    for (int jj = 0; jj < 2; ++jj) {
                        int col = cb + jj;
                        if (col >= Ncols) break;
                        float v = vals[rr2][jj];
                        if (col < colsplit)
                            Cs[(size_t)rs * ld_s + col] = v;
                        else
                            Ccls[(size_t)rs * CC + (col - colsplit)] = v;
                    }
                }
            }
        }
    }
}

// ---------------- kernel 4: L2 normalize -> fp16 ------------------------------
__global__ void normalize_kernel(const float* __restrict__ X,
                                 uint16_t* __restrict__ Xo,
                                 int rows, float extra) {
    int wwid = (blockIdx.x * blockDim.x + threadIdx.x) >> 5;
    int lane = threadIdx.x & 31;
    int total = rows * HH;
    if (wwid >= total) return;
    int n = wwid / HH;
    int h = wwid - n * HH;
    size_t base = (size_t)n * NH + h * PP;
    const float4* p4 = reinterpret_cast<const float4*>(X + base);
    float4 v0 = p4[lane];
    float4 v1 = p4[lane + 32];
    float ss = v0.x * v0.x + v0.y * v0.y + v0.z * v0.z + v0.w * v0.w
             + v1.x * v1.x + v1.y * v1.y + v1.z * v1.z + v1.w * v1.w;
#pragma unroll
    for (int off = 16; off > 0; off >>= 1)
        ss += __shfl_xor_sync(0xffffffffu, ss, off);
    float sc = extra / fmaxf(sqrtf(ss), EPSN);
    ushort4 h0, h1;
    h0.x = tohalf(v0.x * sc); h0.y = tohalf(v0.y * sc);
    h0.z = tohalf(v0.z * sc); h0.w = tohalf(v0.w * sc);
    h1.x = tohalf(v1.x * sc); h1.y = tohalf(v1.y * sc);
    h1.z = tohalf(v1.z * sc); h1.w = tohalf(v1.w * sc);
    ushort4* ph = reinterpret_cast<ushort4*>(Xo + base);
    ph[lane] = h0; ph[lane + 32] = h1;
}

// ---------------- launch -------------------------------------------------------
extern "C" void kernel_launch(void* const* d_in, const int* in_sizes, int n_in,
                              void* d_out, int out_size) {
    const float* query   = (const float*)d_in[0];
    const float* support = (const float*)d_in[1];
    const float* head_W  = (const float*)d_in[2];
    const float* head_b  = (const float*)d_in[3];
    const float* cls_W   = (const float*)d_in[4];
    const float* cls_b   = (const float*)d_in[5];

    float* out_match = (float*)d_out;
    float* out_preds = (float*)d_out + (size_t)NQ * NS;

    uint16_t *X, *Wt, *Qn, *Sn;
    float *bias, *Qf, *Sf;
    cudaGetSymbolAddress((void**)&X,    g_X);
    cudaGetSymbolAddress((void**)&Wt,   g_Wt);
    cudaGetSymbolAddress((void**)&bias, g_bias);
    cudaGetSymbolAddress((void**)&Qf,   g_Qf);
    cudaGetSymbolAddress((void**)&Sf,   g_Sf);
    cudaGetSymbolAddress((void**)&Qn,   g_Qn);
    cudaGetSymbolAddress((void**)&Sn,   g_Sn);

    cudaFuncSetAttribute(gemm_kernel,
                         cudaFuncAttributeMaxDynamicSharedMemorySize, SMEMB);

    // 1) mean over frames + support -> fp16 merged X
    {
        int n4 = (NQ * DD) / 4;
        mean_kernel<<<(n4 + 255) / 256, 256>>>(query);
        int s4 = (NS * DD) / 4;
        split_support_kernel<<<(s4 + 255) / 256, 256>>>(support);
    }
    // 2) pack W^T + bias
    {
        int total = NTOT * DD;
        pack_kernel<<<(total + 255) / 256, 256>>>(head_W, head_b, cls_W, cls_b);
    }
    // 3) merged projection GEMM: X[6144,1024] @ Wt[868,1024]^T
    {
        dim3 grid((NTOT + BN - 1) / BN, MTOTAL / BM);  // (7, 48) = 336 CTAs
        gemm_kernel<<<grid, 256, SMEMB>>>(X, Wt, DD, NTOT, bias,
                                          Qf, NH, Sf, NH, out_preds,
                                          NQ, NH);
    }
    // 4) normalize -> fp16 (Q folds 1/H)
    {
        int warpsQ = NQ * HH;
        normalize_kernel<<<(warpsQ * 32 + 255) / 256, 256>>>(Qf, Qn, NQ,
                                                             1.0f / (float)HH);
        int warpsS = NS * HH;
        normalize_kernel<<<(warpsS * 32 + 255) / 256, 256>>>(Sf, Sn, NS, 1.0f);
    }
    // 5) match GEMM: Qn[4096,768] @ Sn[2048,768]^T
    {
        dim3 grid(NS / BN, NQ / BM);  // (16, 32) = 512 CTAs
        gemm_kernel<<<grid, 256, SMEMB>>>(Qn, Sn, NH, NS, nullptr,
                                          out_match, NS, nullptr, 0, nullptr,
                                          NQ, NS);
    }
}

// round 10
// speedup vs baseline: 6.1042x; 1.0345x over previous
#include <cuda_runtime.h>
#include <cuda_fp16.h>
#include <cstdint>
#include <math.h>

// ---------------- problem constants ----------------------------------------
#define NQ     4096
#define DD     1024
#define NS     2048
#define HH     3
#define PP     256
#define CC     100
#define NH     768
#define NTOT   868
#define MTOTAL (NQ + NS)         // 6144 merged projection rows
#define EPSN   1e-8f

// ---------------- GEMM tiling ----------------------------------------------
#define BM     128
#define BN     128
#define BK     64
#define PITCHB 144               // 128 B data + 16 B pad (conflict-free)
#define PARTB  (BM * PITCHB)     // 18432 B
#define STAGEB (2 * PARTB)       // A | B  (36864 B)
#define NSTAGE 3
#define SMEMB  (NSTAGE * STAGEB) // 110592 B -> 2 CTAs/SM

// ---------------- scratch --------------------------------------------------
__device__ uint16_t g_X[MTOTAL * DD];    // fp16: rows 0..4095 mean(query), 4096.. support
__device__ uint16_t g_Wt[NTOT * DD];     // fp16 W^T (head rows 0..767, cls rows 768..867)
__device__ float    g_bias[NTOT];
__device__ float    g_Qf[NQ * NH];
__device__ float    g_Sf[NS * NH];
__device__ uint16_t g_Qn[NQ * NH];       // fp16 normalized Q (x 1/H)
__device__ uint16_t g_Sn[NS * NH];       // fp16 normalized S

// ---------------- helpers ----------------------------------------------------
__device__ __forceinline__ uint32_t smem_u32_of(const void* p) {
    uint32_t a;
    asm("{ .reg .u64 t; cvta.to.shared.u64 t, %1; cvt.u32.u64 %0, t; }"
        : "=r"(a) : "l"(p));
    return a;
}

__device__ __forceinline__ void ldsm4(uint32_t addr, uint32_t* r) {
    asm volatile("ldmatrix.sync.aligned.m8n8.x4.shared.b16 {%0,%1,%2,%3}, [%4];"
                 : "=r"(r[0]), "=r"(r[1]), "=r"(r[2]), "=r"(r[3]) : "r"(addr));
}

__device__ __forceinline__ uint16_t tohalf(float x) {
    return __half_as_ushort(__float2half_rn(x));
}

__device__ __forceinline__ void mma_f16(float* c, const uint32_t* a,
                                        uint32_t b0, uint32_t b1) {
    asm volatile(
        "mma.sync.aligned.m16n8k16.row.col.f32.f16.f16.f32 "
        "{%0,%1,%2,%3}, {%4,%5,%6,%7}, {%8,%9}, {%0,%1,%2,%3};"
        : "+f"(c[0]), "+f"(c[1]), "+f"(c[2]), "+f"(c[3])
        : "r"(a[0]), "r"(a[1]), "r"(a[2]), "r"(a[3]), "r"(b0), "r"(b1));
}

// ---------------- kernel 1: mean over frames -> fp16 --------------------------
__global__ void mean_kernel(const float* __restrict__ q) {
    int i = blockIdx.x * blockDim.x + threadIdx.x;
    const int n4 = (NQ * DD) / 4;
    if (i >= n4) return;
    const float4* p = reinterpret_cast<const float4*>(q);
    float4 a = p[i], b = p[i + n4], c = p[i + 2 * n4], d = p[i + 3 * n4];
    ushort4 hs;
    hs.x = tohalf(0.25f * (a.x + b.x + c.x + d.x));
    hs.y = tohalf(0.25f * (a.y + b.y + c.y + d.y));
    hs.z = tohalf(0.25f * (a.z + b.z + c.z + d.z));
    hs.w = tohalf(0.25f * (a.w + b.w + c.w + d.w));
    reinterpret_cast<ushort4*>(g_X)[i] = hs;
}

// ---------------- kernel 1b: support -> fp16 rows NQ.. ------------------------
__global__ void split_support_kernel(const float* __restrict__ s) {
    int i = blockIdx.x * blockDim.x + threadIdx.x;
    const int n4 = (NS * DD) / 4;
    if (i >= n4) return;
    const int off4 = (NQ * DD) / 4;
    float4 v = reinterpret_cast<const float4*>(s)[i];
    ushort4 hs;
    hs.x = tohalf(v.x); hs.y = tohalf(v.y);
    hs.z = tohalf(v.z); hs.w = tohalf(v.w);
    reinterpret_cast<ushort4*>(g_X)[off4 + i] = hs;
}

// ---------------- kernel 2: pack W^T + bias (fp16) ----------------------------
__global__ void pack_kernel(const float* __restrict__ hW,
                            const float* __restrict__ hb,
                            const float* __restrict__ cW,
                            const float* __restrict__ cb) {
    int i = blockIdx.x * blockDim.x + threadIdx.x;
    if (i < NTOT * DD) {
        int n = i >> 10;
        int k = i & 1023;
        float v;
        if (n < NH) {
            int h = n >> 8;
            int p = n & 255;
            v = hW[((size_t)h * DD + k) * PP + p];
        } else {
            v = cW[(size_t)k * CC + (n - NH)];
        }
        g_Wt[i] = tohalf(v);
    }
    if (i < NTOT) g_bias[i] = (i < NH) ? hb[i] : cb[i - NH];
}

// ---------------- kernel 3: fp16 HMMA GEMM (NT), 3-stage, 1 sync/chunk --------
// Main job: routing row r < m_split -> Cq; else -> Cs / Ccls by colsplit.
// Aux job (A2 != nullptr, blockIdx.y == gridDim.y-1, blockIdx.x < aux_mtiles):
//   small GEMM A2[aux rows] @ B2^T -> C2 (ld CC), all cols, bias2.
__global__ void __launch_bounds__(256, 2)
gemm_kernel(const uint16_t* __restrict__ A,
            const uint16_t* __restrict__ B,
            int K, int Ncols, const float* __restrict__ bias,
            float* __restrict__ Cq, int ld_q,
            float* __restrict__ Cs, int ld_s,
            float* __restrict__ Ccls,
            int m_split, int colsplit,
            const uint16_t* __restrict__ A2,
            const uint16_t* __restrict__ B2,
            int K2, int N2, const float* __restrict__ bias2,
            float* __restrict__ C2, int aux_mtiles) {
    extern __shared__ __align__(128) char smem[];
    const uint32_t smbase = smem_u32_of(smem);

    int row0, col0;
    const bool aux = (A2 != nullptr) && ((int)blockIdx.y == (int)gridDim.y - 1);
    if (aux) {
        if ((int)blockIdx.x >= aux_mtiles) return;
        A = A2; B = B2; K = K2; Ncols = N2; bias = bias2;
        Ccls = C2; m_split = 0; colsplit = 0;
        row0 = blockIdx.x * BM;
        col0 = 0;
    } else {
        row0 = blockIdx.y * BM;
        col0 = blockIdx.x * BN;
    }

    const int tid = threadIdx.x;
    const int lane = tid & 31;
    const int wid = tid >> 5;
    const int wm = wid >> 1;
    const int wn = wid & 1;
    const int g = lane >> 2;
    const int t = lane & 3;
    const int nchunk = K / BK;

    float acc[2][8][4];
#pragma unroll
    for (int mi = 0; mi < 2; ++mi)
#pragma unroll
        for (int ni = 0; ni < 8; ++ni)
#pragma unroll
            for (int j = 0; j < 4; ++j) acc[mi][ni][j] = 0.0f;

    auto load_chunk = [&](int c, int s) {
        const uint32_t st = smbase + (uint32_t)s * STAGEB;
        const int k0 = c * BK;
#pragma unroll
        for (int j = 0; j < 8; ++j) {
            int idx = tid + 256 * j;
            int part = idx >> 10;          // 0:A 1:B
            int within = idx & 1023;
            int r = within >> 3;
            int q = within & 7;
            uint32_t dst = st + (uint32_t)part * PARTB + r * PITCHB + q * 16;
            const uint16_t* src;
            int sz = 16;
            if (part == 0) {
                src = A + (size_t)(row0 + r) * K + k0 + q * 8;
            } else {
                int n = col0 + r;
                if (n < Ncols) {
                    src = B + (size_t)n * K + k0 + q * 8;
                } else {
                    src = B;
                    sz = 0;
                }
            }
            asm volatile("cp.async.cg.shared.global [%0], [%1], 16, %2;"
                         :: "r"(dst), "l"(src), "r"(sz) : "memory");
        }
        asm volatile("cp.async.commit_group;" ::: "memory");
    };

    load_chunk(0, 0);
    if (nchunk > 1) load_chunk(1, 1);

    const uint32_t aRowOff = (uint32_t)(lane & 15) * PITCHB;
    const uint32_t aByte   = (uint32_t)((lane >> 4) << 4);
    const uint32_t bRowOff = (uint32_t)(((lane >> 4) & 1) * 8 + (lane & 7)) * PITCHB;
    const uint32_t bByte   = (uint32_t)(((lane >> 3) & 1) << 4);

    int s = 0;
    for (int c = 0; c < nchunk; ++c) {
        if (c + 1 < nchunk) {
            asm volatile("cp.async.wait_group 1;" ::: "memory");
        } else {
            asm volatile("cp.async.wait_group 0;" ::: "memory");
        }
        __syncthreads();
        // stage (s+2)%NSTAGE held chunk c-1's data (finished last iter, fenced
        // by the sync above) -> safe to overwrite now
        if (c + 2 < nchunk) {
            int s2 = s + 2 >= NSTAGE ? s + 2 - NSTAGE : s + 2;
            load_chunk(c + 2, s2);
        }

        const uint32_t st = smbase + (uint32_t)s * STAGEB;
        const uint32_t sA = st;
        const uint32_t sB = st + PARTB;

        // register-pipelined fragment loads
        uint32_t af[2][2][4];   // [kk parity][mi][frag]
        uint32_t bf[2][4];      // [p parity][frag]
#pragma unroll
        for (int mi = 0; mi < 2; ++mi)
            ldsm4(sA + (uint32_t)(wm * 32 + mi * 16) * PITCHB + aRowOff + aByte,
                  af[0][mi]);
        ldsm4(sB + (uint32_t)(wn * 64) * PITCHB + bRowOff + bByte, bf[0]);

#pragma unroll
        for (int kk = 0; kk < 4; ++kk) {
            const int cur = kk & 1;
            const int nxt = cur ^ 1;
            if (kk < 3) {
                const uint32_t kbn = (uint32_t)(kk + 1) * 32;
#pragma unroll
                for (int mi = 0; mi < 2; ++mi)
                    ldsm4(sA + (uint32_t)(wm * 32 + mi * 16) * PITCHB + aRowOff + kbn + aByte,
                          af[nxt][mi]);
            }
            const uint32_t kb = (uint32_t)kk * 32;
#pragma unroll
            for (int p = 0; p < 4; ++p) {
                const int pc = p & 1;
                const int pn = pc ^ 1;
                if (p < 3) {
                    ldsm4(sB + (uint32_t)(wn * 64 + (p + 1) * 16) * PITCHB + bRowOff + kb + bByte,
                          bf[pn]);
                } else if (kk < 3) {
                    ldsm4(sB + (uint32_t)(wn * 64) * PITCHB + bRowOff + kb + 32 + bByte,
                          bf[pn]);
                }
#pragma unroll
                for (int mi = 0; mi < 2; ++mi) {
                    mma_f16(acc[mi][2 * p],     af[cur][mi], bf[pc][0], bf[pc][1]);
                    mma_f16(acc[mi][2 * p + 1], af[cur][mi], bf[pc][2], bf[pc][3]);
                }
            }
        }
        ++s;
        if (s == NSTAGE) s = 0;
    }

    // ---- epilogue ----
    const bool has_bias = (bias != nullptr);
#pragma unroll
    for (int mi = 0; mi < 2; ++mi) {
        int rbase = row0 + wm * 32 + mi * 16 + g;
#pragma unroll
        for (int ni = 0; ni < 8; ++ni) {
            int cb = col0 + wn * 64 + ni * 8 + 2 * t;
            if (cb >= Ncols) continue;
            float b0 = has_bias ? bias[cb] : 0.0f;
            float b1 = (has_bias && (cb + 1) < Ncols) ? bias[cb + 1] : 0.0f;
            float vals[2][2] = { { acc[mi][ni][0] + b0, acc[mi][ni][1] + b1 },
                                 { acc[mi][ni][2] + b0, acc[mi][ni][3] + b1 } };
#pragma unroll
            for (int rr2 = 0; rr2 < 2; ++rr2) {
                int r = rbase + rr2 * 8;
                if (r < m_split) {
                    if (cb + 1 < colsplit) {
                        *reinterpret_cast<float2*>(Cq + (size_t)r * ld_q + cb) =
                            make_float2(vals[rr2][0], vals[rr2][1]);
                    } else {
                        if (cb < colsplit) Cq[(size_t)r * ld_q + cb] = vals[rr2][0];
                        if (cb + 1 < colsplit && cb + 1 < Ncols)
                            Cq[(size_t)r * ld_q + cb + 1] = vals[rr2][1];
                    }
                } else {
                    int rs = r - m_split;
#pragma unroll
                    for (int jj = 0; jj < 2; ++jj) {
                        int col = cb + jj;
                        if (col >= Ncols) break;
                        float v = vals[rr2][jj];
                        if (col < colsplit)
                            Cs[(size_t)rs * ld_s + col] = v;
                        else
                            Ccls[(size_t)rs * CC + (col - colsplit)] = v;
                    }
                }
            }
        }
    }
}

// ---------------- kernel 4: L2 normalize -> fp16 ------------------------------
__global__ void normalize_kernel(const float* __restrict__ X,
                                 uint16_t* __restrict__ Xo,
                                 int rows, float extra) {
    int wwid = (blockIdx.x * blockDim.x + threadIdx.x) >> 5;
    int lane = threadIdx.x & 31;
    int total = rows * HH;
    if (wwid >= total) return;
    int n = wwid / HH;
    int h = wwid - n * HH;
    size_t base = (size_t)n * NH + h * PP;
    const float4* p4 = reinterpret_cast<const float4*>(X + base);
    float4 v0 = p4[lane];
    float4 v1 = p4[lane + 32];
    float ss = v0.x * v0.x + v0.y * v0.y + v0.z * v0.z + v0.w * v0.w
             + v1.x * v1.x + v1.y * v1.y + v1.z * v1.z + v1.w * v1.w;
#pragma unroll
    for (int off = 16; off > 0; off >>= 1)
        ss += __shfl_xor_sync(0xffffffffu, ss, off);
    float sc = extra / fmaxf(sqrtf(ss), EPSN);
    ushort4 h0, h1;
    h0.x = tohalf(v0.x * sc); h0.y = tohalf(v0.y * sc);
    h0.z = tohalf(v0.z * sc); h0.w = tohalf(v0.w * sc);
    h1.x = tohalf(v1.x * sc); h1.y = tohalf(v1.y * sc);
    h1.z = tohalf(v1.z * sc); h1.w = tohalf(v1.w * sc);
    ushort4* ph = reinterpret_cast<ushort4*>(Xo + base);
    ph[lane] = h0; ph[lane + 32] = h1;
}

// ---------------- launch -------------------------------------------------------
extern "C" void kernel_launch(void* const* d_in, const int* in_sizes, int n_in,
                              void* d_out, int out_size) {
    const float* query   = (const float*)d_in[0];
    const float* support = (const float*)d_in[1];
    const float* head_W  = (const float*)d_in[2];
    const float* head_b  = (const float*)d_in[3];
    const float* cls_W   = (const float*)d_in[4];
    const float* cls_b   = (const float*)d_in[5];

    float* out_match = (float*)d_out;
    float* out_preds = (float*)d_out + (size_t)NQ * NS;

    uint16_t *X, *Wt, *Qn, *Sn;
    float *bias, *Qf, *Sf;
    cudaGetSymbolAddress((void**)&X,    g_X);
    cudaGetSymbolAddress((void**)&Wt,   g_Wt);
    cudaGetSymbolAddress((void**)&bias, g_bias);
    cudaGetSymbolAddress((void**)&Qf,   g_Qf);
    cudaGetSymbolAddress((void**)&Sf,   g_Sf);
    cudaGetSymbolAddress((void**)&Qn,   g_Qn);
    cudaGetSymbolAddress((void**)&Sn,   g_Sn);

    cudaFuncSetAttribute(gemm_kernel,
                         cudaFuncAttributeMaxDynamicSharedMemorySize, SMEMB);

    // 1) mean over frames + support -> fp16 merged X
    {
        int n4 = (NQ * DD) / 4;
        mean_kernel<<<(n4 + 255) / 256, 256>>>(query);
        int s4 = (NS * DD) / 4;
        split_support_kernel<<<(s4 + 255) / 256, 256>>>(support);
    }
    // 2) pack W^T + bias
    {
        int total = NTOT * DD;
        pack_kernel<<<(total + 255) / 256, 256>>>(head_W, head_b, cls_W, cls_b);
    }
    // 3) projection GEMM (head cols only): X[6144,1024] @ Wt[768,1024]^T
    //    grid (6, 48) = 288 CTAs -> single wave at 2 CTAs/SM
    {
        dim3 grid(NH / BN, MTOTAL / BM);
        gemm_kernel<<<grid, 256, SMEMB>>>(X, Wt, DD, NH, bias,
                                          Qf, NH, Sf, NH, nullptr,
                                          NQ, NH,
                                          nullptr, nullptr, 0, 0, nullptr,
                                          nullptr, 0);
    }
    // 4) normalize -> fp16 (Q folds 1/H)
    {
        int warpsQ = NQ * HH;
        normalize_kernel<<<(warpsQ * 32 + 255) / 256, 256>>>(Qf, Qn, NQ,
                                                             1.0f / (float)HH);
        int warpsS = NS * HH;
        normalize_kernel<<<(warpsS * 32 + 255) / 256, 256>>>(Sf, Sn, NS, 1.0f);
    }
    // 5) match GEMM Qn[4096,768] @ Sn[2048,768]^T  + fused aux cls GEMM:
    //    support_fp16[2048,1024] @ Wt_cls[100,1024]^T -> out_preds
    {
        dim3 grid(NS / BN, NQ / BM + 1);   // (16, 33); last y-row = aux
        gemm_kernel<<<grid, 256, SMEMB>>>(Qn, Sn, NH, NS, nullptr,
                                          out_match, NS, nullptr, 0, nullptr,
                                          NQ, NS,
                                          X + (size_t)NQ * DD, Wt + (size_t)NH * DD,
                                          DD, CC, bias + NH,
                                          out_preds, NS / BM);
    }
}

// round 11
// speedup vs baseline: 6.3972x; 1.0480x over previous
#include <cuda_runtime.h>
#include <cuda_fp16.h>
#include <cstdint>
#include <math.h>

// ---------------- problem constants ----------------------------------------
#define NQ     4096
#define DD     1024
#define NS     2048
#define HH     3
#define PP     256
#define CC     100
#define NH     768
#define NTOT   868
#define MTOTAL (NQ + NS)         // 6144 merged projection rows
#define EPSN   1e-8f

// ---------------- GEMM tiling ----------------------------------------------
#define BM     128
#define BN     128
#define BK     64
#define PITCHB 144               // 128 B data + 16 B pad (conflict-free)
#define PARTB  (BM * PITCHB)     // 18432 B
#define STAGEB (2 * PARTB)       // A | B  (36864 B)
#define NSTAGE 3
#define SMEMB  (NSTAGE * STAGEB) // 110592 B -> 2 CTAs/SM

// ---------------- scratch --------------------------------------------------
__device__ uint16_t g_X[MTOTAL * DD];    // fp16: rows 0..4095 mean(query), 4096.. support
__device__ uint16_t g_Wt[NTOT * DD];     // fp16 W^T (head rows 0..767, cls rows 768..867)
__device__ float    g_bias[NTOT];
__device__ uint16_t g_Qn[NQ * NH];       // fp16 Q proj (unnorm -> normalized in place)
__device__ uint16_t g_Sn[NS * NH];       // fp16 S proj (unnorm -> normalized in place)
__device__ float    g_sumsq[MTOTAL * HH];// per-(row,head) sum of squares

// ---------------- helpers ----------------------------------------------------
__device__ __forceinline__ uint32_t smem_u32_of(const void* p) {
    uint32_t a;
    asm("{ .reg .u64 t; cvta.to.shared.u64 t, %1; cvt.u32.u64 %0, t; }"
        : "=r"(a) : "l"(p));
    return a;
}

__device__ __forceinline__ void ldsm4(uint32_t addr, uint32_t* r) {
    asm volatile("ldmatrix.sync.aligned.m8n8.x4.shared.b16 {%0,%1,%2,%3}, [%4];"
                 : "=r"(r[0]), "=r"(r[1]), "=r"(r[2]), "=r"(r[3]) : "r"(addr));
}

__device__ __forceinline__ uint16_t tohalf(float x) {
    return __half_as_ushort(__float2half_rn(x));
}

__device__ __forceinline__ uint32_t packhalf2(float lo, float hi) {
    uint32_t r;
    asm("cvt.rn.f16x2.f32 %0, %1, %2;" : "=r"(r) : "f"(hi), "f"(lo));
    return r;
}

__device__ __forceinline__ void mma_f16(float* c, const uint32_t* a,
                                        uint32_t b0, uint32_t b1) {
    asm volatile(
        "mma.sync.aligned.m16n8k16.row.col.f32.f16.f16.f32 "
        "{%0,%1,%2,%3}, {%4,%5,%6,%7}, {%8,%9}, {%0,%1,%2,%3};"
        : "+f"(c[0]), "+f"(c[1]), "+f"(c[2]), "+f"(c[3])
        : "r"(a[0]), "r"(a[1]), "r"(a[2]), "r"(a[3]), "r"(b0), "r"(b1));
}

// ---------------- kernel 1: mean(query) + support -> fp16 merged X -----------
__global__ void prep_kernel(const float* __restrict__ q,
                            const float* __restrict__ s) {
    int i = blockIdx.x * blockDim.x + threadIdx.x;
    const int n4q = (NQ * DD) / 4;
    const int n4tot = n4q + (NS * DD) / 4;
    if (i >= n4tot) return;
    ushort4 hs;
    if (i < n4q) {
        const float4* p = reinterpret_cast<const float4*>(q);
        float4 a = p[i], b = p[i + n4q], c = p[i + 2 * n4q], d = p[i + 3 * n4q];
        hs.x = tohalf(0.25f * (a.x + b.x + c.x + d.x));
        hs.y = tohalf(0.25f * (a.y + b.y + c.y + d.y));
        hs.z = tohalf(0.25f * (a.z + b.z + c.z + d.z));
        hs.w = tohalf(0.25f * (a.w + b.w + c.w + d.w));
    } else {
        float4 v = reinterpret_cast<const float4*>(s)[i - n4q];
        hs.x = tohalf(v.x); hs.y = tohalf(v.y);
        hs.z = tohalf(v.z); hs.w = tohalf(v.w);
    }
    reinterpret_cast<ushort4*>(g_X)[i] = hs;
}

// ---------------- kernel 2: pack W^T + bias (fp16), zero sumsq ----------------
__global__ void pack_kernel(const float* __restrict__ hW,
                            const float* __restrict__ hb,
                            const float* __restrict__ cW,
                            const float* __restrict__ cb) {
    int i = blockIdx.x * blockDim.x + threadIdx.x;
    if (i < NTOT * DD) {
        int n = i >> 10;
        int k = i & 1023;
        float v;
        if (n < NH) {
            int h = n >> 8;
            int p = n & 255;
            v = hW[((size_t)h * DD + k) * PP + p];
        } else {
            v = cW[(size_t)k * CC + (n - NH)];
        }
        g_Wt[i] = tohalf(v);
    }
    if (i < NTOT) g_bias[i] = (i < NH) ? hb[i] : cb[i - NH];
    if (i < MTOTAL * HH) g_sumsq[i] = 0.0f;
}

// ---------------- kernel 3: fp16 HMMA GEMM (NT), 3-stage, 1 sync/chunk --------
// fp16-out mode (Cq16 != nullptr): writes fp16 proj + atomic sumsq per (row,head).
// fp32 mode: routing row < m_split -> Cq; else -> Cs / Ccls by colsplit.
// Aux job (A2 != nullptr, blockIdx.y == gridDim.y-1): small cls GEMM -> C2 fp32.
__global__ void __launch_bounds__(256, 2)
gemm_kernel(const uint16_t* __restrict__ A,
            const uint16_t* __restrict__ B,
            int K, int Ncols, const float* __restrict__ bias,
            float* __restrict__ Cq, int ld_q,
            float* __restrict__ Ccls,
            int m_split, int colsplit,
            uint16_t* __restrict__ Cq16, uint16_t* __restrict__ Cs16,
            float* __restrict__ sumsq,
            const uint16_t* __restrict__ A2,
            const uint16_t* __restrict__ B2,
            int K2, int N2, const float* __restrict__ bias2,
            float* __restrict__ C2, int aux_mtiles) {
    extern __shared__ __align__(128) char smem[];
    const uint32_t smbase = smem_u32_of(smem);

    int row0, col0;
    const bool aux = (A2 != nullptr) && ((int)blockIdx.y == (int)gridDim.y - 1);
    if (aux) {
        if ((int)blockIdx.x >= aux_mtiles) return;
        A = A2; B = B2; K = K2; Ncols = N2; bias = bias2;
        Ccls = C2; m_split = 0; colsplit = 0; Cq16 = nullptr;
        row0 = blockIdx.x * BM;
        col0 = 0;
    } else {
        row0 = blockIdx.y * BM;
        col0 = blockIdx.x * BN;
    }

    const int tid = threadIdx.x;
    const int lane = tid & 31;
    const int wid = tid >> 5;
    const int wm = wid >> 1;
    const int wn = wid & 1;
    const int g = lane >> 2;
    const int t = lane & 3;
    const int nchunk = K / BK;

    float acc[2][8][4];
#pragma unroll
    for (int mi = 0; mi < 2; ++mi)
#pragma unroll
        for (int ni = 0; ni < 8; ++ni)
#pragma unroll
            for (int j = 0; j < 4; ++j) acc[mi][ni][j] = 0.0f;

    auto load_chunk = [&](int c, int s) {
        const uint32_t st = smbase + (uint32_t)s * STAGEB;
        const int k0 = c * BK;
#pragma unroll
        for (int j = 0; j < 8; ++j) {
            int idx = tid + 256 * j;
            int part = idx >> 10;          // 0:A 1:B
            int within = idx & 1023;
            int r = within >> 3;
            int q = within & 7;
            uint32_t dst = st + (uint32_t)part * PARTB + r * PITCHB + q * 16;
            const uint16_t* src;
            int sz = 16;
            if (part == 0) {
                src = A + (size_t)(row0 + r) * K + k0 + q * 8;
            } else {
                int n = col0 + r;
                if (n < Ncols) {
                    src = B + (size_t)n * K + k0 + q * 8;
                } else {
                    src = B;
                    sz = 0;
                }
            }
            asm volatile("cp.async.cg.shared.global [%0], [%1], 16, %2;"
                         :: "r"(dst), "l"(src), "r"(sz) : "memory");
        }
        asm volatile("cp.async.commit_group;" ::: "memory");
    };

    load_chunk(0, 0);
    if (nchunk > 1) load_chunk(1, 1);

    const uint32_t aRowOff = (uint32_t)(lane & 15) * PITCHB;
    const uint32_t aByte   = (uint32_t)((lane >> 4) << 4);
    const uint32_t bRowOff = (uint32_t)(((lane >> 4) & 1) * 8 + (lane & 7)) * PITCHB;
    const uint32_t bByte   = (uint32_t)(((lane >> 3) & 1) << 4);

    int s = 0;
    for (int c = 0; c < nchunk; ++c) {
        if (c + 1 < nchunk) {
            asm volatile("cp.async.wait_group 1;" ::: "memory");
        } else {
            asm volatile("cp.async.wait_group 0;" ::: "memory");
        }
        __syncthreads();
        if (c + 2 < nchunk) {
            int s2 = s + 2 >= NSTAGE ? s + 2 - NSTAGE : s + 2;
            load_chunk(c + 2, s2);
        }

        const uint32_t st = smbase + (uint32_t)s * STAGEB;
        const uint32_t sA = st;
        const uint32_t sB = st + PARTB;

        uint32_t af[2][2][4];
        uint32_t bf[2][4];
#pragma unroll
        for (int mi = 0; mi < 2; ++mi)
            ldsm4(sA + (uint32_t)(wm * 32 + mi * 16) * PITCHB + aRowOff + aByte,
                  af[0][mi]);
        ldsm4(sB + (uint32_t)(wn * 64) * PITCHB + bRowOff + bByte, bf[0]);

#pragma unroll
        for (int kk = 0; kk < 4; ++kk) {
            const int cur = kk & 1;
            const int nxt = cur ^ 1;
            if (kk < 3) {
                const uint32_t kbn = (uint32_t)(kk + 1) * 32;
#pragma unroll
                for (int mi = 0; mi < 2; ++mi)
                    ldsm4(sA + (uint32_t)(wm * 32 + mi * 16) * PITCHB + aRowOff + kbn + aByte,
                          af[nxt][mi]);
            }
            const uint32_t kb = (uint32_t)kk * 32;
#pragma unroll
            for (int p = 0; p < 4; ++p) {
                const int pc = p & 1;
                const int pn = pc ^ 1;
                if (p < 3) {
                    ldsm4(sB + (uint32_t)(wn * 64 + (p + 1) * 16) * PITCHB + bRowOff + kb + bByte,
                          bf[pn]);
                } else if (kk < 3) {
                    ldsm4(sB + (uint32_t)(wn * 64) * PITCHB + bRowOff + kb + 32 + bByte,
                          bf[pn]);
                }
#pragma unroll
                for (int mi = 0; mi < 2; ++mi) {
                    mma_f16(acc[mi][2 * p],     af[cur][mi], bf[pc][0], bf[pc][1]);
                    mma_f16(acc[mi][2 * p + 1], af[cur][mi], bf[pc][2], bf[pc][3]);
                }
            }
        }
        ++s;
        if (s == NSTAGE) s = 0;
    }

    // ---- epilogue ----
    if (Cq16 != nullptr) {
        // fp16 projection output + per-(row,head) sumsq atomics.
        // BN=128 tile lies entirely inside one head (PP=256 = 2*BN).
        const int head = col0 >> 8;
#pragma unroll
        for (int mi = 0; mi < 2; ++mi) {
            int rbase = row0 + wm * 32 + mi * 16 + g;
            float sq0 = 0.0f, sq1 = 0.0f;
#pragma unroll
            for (int ni = 0; ni < 8; ++ni) {
                int cb = col0 + wn * 64 + ni * 8 + 2 * t;
                float b0 = bias[cb];
                float b1 = bias[cb + 1];
                float v00 = acc[mi][ni][0] + b0;
                float v01 = acc[mi][ni][1] + b1;
                float v10 = acc[mi][ni][2] + b0;
                float v11 = acc[mi][ni][3] + b1;
                sq0 += v00 * v00 + v01 * v01;
                sq1 += v10 * v10 + v11 * v11;
                uint32_t p0 = packhalf2(v00, v01);
                uint32_t p1 = packhalf2(v10, v11);
                int r0i = rbase;
                int r1i = rbase + 8;
                uint16_t* d0 = (r0i < m_split) ? (Cq16 + (size_t)r0i * NH + cb)
                                               : (Cs16 + (size_t)(r0i - m_split) * NH + cb);
                uint16_t* d1 = (r1i < m_split) ? (Cq16 + (size_t)r1i * NH + cb)
                                               : (Cs16 + (size_t)(r1i - m_split) * NH + cb);
                *reinterpret_cast<uint32_t*>(d0) = p0;
                *reinterpret_cast<uint32_t*>(d1) = p1;
            }
            atomicAdd(&sumsq[(size_t)rbase * HH + head], sq0);
            atomicAdd(&sumsq[(size_t)(rbase + 8) * HH + head], sq1);
        }
    } else {
        const bool has_bias = (bias != nullptr);
#pragma unroll
        for (int mi = 0; mi < 2; ++mi) {
            int rbase = row0 + wm * 32 + mi * 16 + g;
#pragma unroll
            for (int ni = 0; ni < 8; ++ni) {
                int cb = col0 + wn * 64 + ni * 8 + 2 * t;
                if (cb >= Ncols) continue;
                float b0 = has_bias ? bias[cb] : 0.0f;
                float b1 = (has_bias && (cb + 1) < Ncols) ? bias[cb + 1] : 0.0f;
                float vals[2][2] = { { acc[mi][ni][0] + b0, acc[mi][ni][1] + b1 },
                                     { acc[mi][ni][2] + b0, acc[mi][ni][3] + b1 } };
#pragma unroll
                for (int rr2 = 0; rr2 < 2; ++rr2) {
                    int r = rbase + rr2 * 8;
                    if (r < m_split) {
                        if (cb + 1 < colsplit) {
                            *reinterpret_cast<float2*>(Cq + (size_t)r * ld_q + cb) =
                                make_float2(vals[rr2][0], vals[rr2][1]);
                        } else {
                            if (cb < colsplit) Cq[(size_t)r * ld_q + cb] = vals[rr2][0];
                            if (cb + 1 < colsplit && cb + 1 < Ncols)
                                Cq[(size_t)r * ld_q + cb + 1] = vals[rr2][1];
                        }
                    } else {
                        int rs = r - m_split;
#pragma unroll
                        for (int jj = 0; jj < 2; ++jj) {
                            int col = cb + jj;
                            if (col >= Ncols) break;
                            Ccls[(size_t)rs * CC + (col - colsplit)] = vals[rr2][jj];
                        }
                    }
                }
            }
        }
    }
}

// ---------------- kernel 4: fused in-place L2 normalize (fp16) ----------------
__global__ void normalize_kernel(uint16_t* __restrict__ Q,
                                 uint16_t* __restrict__ S,
                                 const float* __restrict__ sumsq) {
    int wwid = (blockIdx.x * blockDim.x + threadIdx.x) >> 5;
    int lane = threadIdx.x & 31;
    if (wwid >= MTOTAL * HH) return;
    int row = wwid / HH;
    int h = wwid - row * HH;
    float ss = sumsq[wwid];
    float extra = (row < NQ) ? (1.0f / (float)HH) : 1.0f;
    float sc = extra / fmaxf(sqrtf(ss), EPSN);
    uint16_t* p = ((row < NQ) ? (Q + (size_t)row * NH)
                              : (S + (size_t)(row - NQ) * NH)) + h * PP;
    uint4* p4 = reinterpret_cast<uint4*>(p);   // 8 fp16 per lane
    uint4 v = p4[lane];
    uint32_t* vw = reinterpret_cast<uint32_t*>(&v);
#pragma unroll
    for (int j = 0; j < 4; ++j) {
        __half2 h2 = *reinterpret_cast<__half2*>(&vw[j]);
        float2 f2 = __half22float2(h2);
        vw[j] = packhalf2(f2.x * sc, f2.y * sc);
    }
    p4[lane] = v;
}

// ---------------- launch -------------------------------------------------------
extern "C" void kernel_launch(void* const* d_in, const int* in_sizes, int n_in,
                              void* d_out, int out_size) {
    const float* query   = (const float*)d_in[0];
    const float* support = (const float*)d_in[1];
    const float* head_W  = (const float*)d_in[2];
    const float* head_b  = (const float*)d_in[3];
    const float* cls_W   = (const float*)d_in[4];
    const float* cls_b   = (const float*)d_in[5];

    float* out_match = (float*)d_out;
    float* out_preds = (float*)d_out + (size_t)NQ * NS;

    uint16_t *X, *Wt, *Qn, *Sn;
    float *bias, *sumsq;
    cudaGetSymbolAddress((void**)&X,     g_X);
    cudaGetSymbolAddress((void**)&Wt,    g_Wt);
    cudaGetSymbolAddress((void**)&bias,  g_bias);
    cudaGetSymbolAddress((void**)&Qn,    g_Qn);
    cudaGetSymbolAddress((void**)&Sn,    g_Sn);
    cudaGetSymbolAddress((void**)&sumsq, g_sumsq);

    cudaFuncSetAttribute(gemm_kernel,
                         cudaFuncAttributeMaxDynamicSharedMemorySize, SMEMB);

    // 1) mean(query) + support -> fp16 merged X (one kernel)
    {
        int n4tot = (NQ * DD + NS * DD) / 4;
        prep_kernel<<<(n4tot + 255) / 256, 256>>>(query, support);
    }
    // 2) pack W^T + bias, zero sumsq
    {
        int total = NTOT * DD;
        pack_kernel<<<(total + 255) / 256, 256>>>(head_W, head_b, cls_W, cls_b);
    }
    // 3) projection GEMM (head cols): X[6144,1024] @ Wt[768,1024]^T -> fp16 + sumsq
    {
        dim3 grid(NH / BN, MTOTAL / BM);   // (6, 48) = 288 CTAs, single wave
        gemm_kernel<<<grid, 256, SMEMB>>>(X, Wt, DD, NH, bias,
                                          nullptr, 0, nullptr, NQ, NH,
                                          Qn, Sn, sumsq,
                                          nullptr, nullptr, 0, 0, nullptr,
                                          nullptr, 0);
    }
    // 4) fused in-place normalize (Q folds 1/H)
    {
        int warps = MTOTAL * HH;
        normalize_kernel<<<(warps * 32 + 255) / 256, 256>>>(Qn, Sn, sumsq);
    }
    // 5) match GEMM Qn[4096,768] @ Sn[2048,768]^T + fused aux cls GEMM
    {
        dim3 grid(NS / BN, NQ / BM + 1);   // (16, 33); last y-row = aux
        gemm_kernel<<<grid, 256, SMEMB>>>(Qn, Sn, NH, NS, nullptr,
                                          out_match, NS, nullptr, NQ, NS,
                                          nullptr, nullptr, nullptr,
                                          X + (size_t)NQ * DD, Wt + (size_t)NH * DD,
                                          DD, CC, bias + NH,
                                          out_preds, NS / BM);
    }
}

// round 12
// speedup vs baseline: 6.8467x; 1.0703x over previous
#include <cuda_runtime.h>
#include <cuda_fp16.h>
#include <cstdint>
#include <math.h>

// ---------------- problem constants ----------------------------------------
#define NQ     4096
#define DD     1024
#define NS     2048
#define HH     3
#define PP     256
#define CC     100
#define NH     768
#define NTOT   868
#define MTOTAL (NQ + NS)         // 6144 merged projection rows
#define EPSN   1e-8f

// ---------------- GEMM tiling ----------------------------------------------
#define BM     128
#define BN     128
#define BK     64
#define PITCHB 144               // 128 B data + 16 B pad (conflict-free)
#define PARTB  (BM * PITCHB)     // 18432 B
#define STAGEB (2 * PARTB)       // A | B  (36864 B)
#define NSTAGE 3
#define SMEMB  (NSTAGE * STAGEB) // 110592 B -> 2 CTAs/SM

// ---------------- scratch --------------------------------------------------
__device__ uint16_t g_X[MTOTAL * DD];    // fp16: rows 0..4095 mean(query), 4096.. support
__device__ uint16_t g_Wt[NTOT * DD];     // fp16 W^T (head rows 0..767, cls rows 768..867)
__device__ float    g_bias[NTOT];
__device__ uint16_t g_Qn[NQ * NH];       // fp16 Q proj (unnorm -> normalized in place)
__device__ uint16_t g_Sn[NS * NH];       // fp16 S proj (unnorm -> normalized in place)
__device__ float    g_sumsq[MTOTAL * HH];// per-(row,head) sum of squares

// ---------------- helpers ----------------------------------------------------
__device__ __forceinline__ uint32_t smem_u32_of(const void* p) {
    uint32_t a;
    asm("{ .reg .u64 t; cvta.to.shared.u64 t, %1; cvt.u32.u64 %0, t; }"
        : "=r"(a) : "l"(p));
    return a;
}

__device__ __forceinline__ void ldsm4(uint32_t addr, uint32_t* r) {
    asm volatile("ldmatrix.sync.aligned.m8n8.x4.shared.b16 {%0,%1,%2,%3}, [%4];"
                 : "=r"(r[0]), "=r"(r[1]), "=r"(r[2]), "=r"(r[3]) : "r"(addr));
}

__device__ __forceinline__ uint16_t tohalf(float x) {
    return __half_as_ushort(__float2half_rn(x));
}

__device__ __forceinline__ uint32_t packhalf2(float lo, float hi) {
    uint32_t r;
    asm("cvt.rn.f16x2.f32 %0, %1, %2;" : "=r"(r) : "f"(hi), "f"(lo));
    return r;
}

__device__ __forceinline__ void mma_f16(float* c, const uint32_t* a,
                                        uint32_t b0, uint32_t b1) {
    asm volatile(
        "mma.sync.aligned.m16n8k16.row.col.f32.f16.f16.f32 "
        "{%0,%1,%2,%3}, {%4,%5,%6,%7}, {%8,%9}, {%0,%1,%2,%3};"
        : "+f"(c[0]), "+f"(c[1]), "+f"(c[2]), "+f"(c[3])
        : "r"(a[0]), "r"(a[1]), "r"(a[2]), "r"(a[3]), "r"(b0), "r"(b1));
}

// ---------------- kernel 1: mean(query) + support -> fp16 merged X -----------
__global__ void prep_kernel(const float* __restrict__ q,
                            const float* __restrict__ s) {
    int i = blockIdx.x * blockDim.x + threadIdx.x;
    const int n4q = (NQ * DD) / 4;
    const int n4tot = n4q + (NS * DD) / 4;
    if (i >= n4tot) return;
    ushort4 hs;
    if (i < n4q) {
        const float4* p = reinterpret_cast<const float4*>(q);
        float4 a = p[i], b = p[i + n4q], c = p[i + 2 * n4q], d = p[i + 3 * n4q];
        hs.x = tohalf(0.25f * (a.x + b.x + c.x + d.x));
        hs.y = tohalf(0.25f * (a.y + b.y + c.y + d.y));
        hs.z = tohalf(0.25f * (a.z + b.z + c.z + d.z));
        hs.w = tohalf(0.25f * (a.w + b.w + c.w + d.w));
    } else {
        float4 v = reinterpret_cast<const float4*>(s)[i - n4q];
        hs.x = tohalf(v.x); hs.y = tohalf(v.y);
        hs.z = tohalf(v.z); hs.w = tohalf(v.w);
    }
    reinterpret_cast<ushort4*>(g_X)[i] = hs;
}

// ---------------- kernel 2: pack W^T + bias (fp16), zero sumsq ----------------
__global__ void pack_kernel(const float* __restrict__ hW,
                            const float* __restrict__ hb,
                            const float* __restrict__ cW,
                            const float* __restrict__ cb) {
    int i = blockIdx.x * blockDim.x + threadIdx.x;
    if (i < NTOT * DD) {
        int n = i >> 10;
        int k = i & 1023;
        float v;
        if (n < NH) {
            int h = n >> 8;
            int p = n & 255;
            v = hW[((size_t)h * DD + k) * PP + p];
        } else {
            v = cW[(size_t)k * CC + (n - NH)];
        }
        g_Wt[i] = tohalf(v);
    }
    if (i < NTOT) g_bias[i] = (i < NH) ? hb[i] : cb[i - NH];
    if (i < MTOTAL * HH) g_sumsq[i] = 0.0f;
}

// ---------------- kernel 3: fp16 HMMA GEMM (NT), persistent M-tiles -----------
// Each main CTA processes `mtiles` consecutive M-tiles (same N strip).
// fp16-out mode (Cq16 != nullptr): fp16 proj + atomic sumsq per (row,head).
// fp32 mode: row < m_split -> Cq; else -> Ccls by colsplit.
// Aux job (A2 != nullptr, blockIdx.y == gridDim.y-1): cls GEMM -> C2 fp32.
__global__ void __launch_bounds__(256, 2)
gemm_kernel(const uint16_t* __restrict__ A,
            const uint16_t* __restrict__ B,
            int K, int Ncols, const float* __restrict__ bias,
            float* __restrict__ Cq, int ld_q,
            float* __restrict__ Ccls,
            int m_split, int colsplit,
            uint16_t* __restrict__ Cq16, uint16_t* __restrict__ Cs16,
            float* __restrict__ sumsq,
            int mtiles,
            const uint16_t* __restrict__ A2,
            const uint16_t* __restrict__ B2,
            int K2, int N2, const float* __restrict__ bias2,
            float* __restrict__ C2, int aux_mtiles) {
    extern __shared__ __align__(128) char smem[];
    const uint32_t smbase = smem_u32_of(smem);

    int col0;
    const bool aux = (A2 != nullptr) && ((int)blockIdx.y == (int)gridDim.y - 1);
    if (aux) {
        if ((int)blockIdx.x >= aux_mtiles) return;
        A = A2; B = B2; K = K2; Ncols = N2; bias = bias2;
        Ccls = C2; m_split = 0; colsplit = 0; Cq16 = nullptr;
        mtiles = 1;
        col0 = 0;
    } else {
        col0 = blockIdx.x * BN;
    }

    const int tid = threadIdx.x;
    const int lane = tid & 31;
    const int wid = tid >> 5;
    const int wm = wid >> 1;
    const int wn = wid & 1;
    const int g = lane >> 2;
    const int t = lane & 3;
    const int nchunk = K / BK;

    const uint32_t aRowOff = (uint32_t)(lane & 15) * PITCHB;
    const uint32_t aByte   = (uint32_t)((lane >> 4) << 4);
    const uint32_t bRowOff = (uint32_t)(((lane >> 4) & 1) * 8 + (lane & 7)) * PITCHB;
    const uint32_t bByte   = (uint32_t)(((lane >> 3) & 1) << 4);

    for (int mt = 0; mt < mtiles; ++mt) {
        const int row0 = aux ? (int)blockIdx.x * BM
                             : ((int)blockIdx.y * mtiles + mt) * BM;

        float acc[2][8][4];
#pragma unroll
        for (int mi = 0; mi < 2; ++mi)
#pragma unroll
            for (int ni = 0; ni < 8; ++ni)
#pragma unroll
                for (int j = 0; j < 4; ++j) acc[mi][ni][j] = 0.0f;

        auto load_chunk = [&](int c, int s) {
            const uint32_t st = smbase + (uint32_t)s * STAGEB;
            const int k0 = c * BK;
#pragma unroll
            for (int j = 0; j < 8; ++j) {
                int idx = tid + 256 * j;
                int part = idx >> 10;          // 0:A 1:B
                int within = idx & 1023;
                int r = within >> 3;
                int q = within & 7;
                uint32_t dst = st + (uint32_t)part * PARTB + r * PITCHB + q * 16;
                const uint16_t* src;
                int sz = 16;
                if (part == 0) {
                    src = A + (size_t)(row0 + r) * K + k0 + q * 8;
                } else {
                    int n = col0 + r;
                    if (n < Ncols) {
                        src = B + (size_t)n * K + k0 + q * 8;
                    } else {
                        src = B;
                        sz = 0;
                    }
                }
                asm volatile("cp.async.cg.shared.global [%0], [%1], 16, %2;"
                             :: "r"(dst), "l"(src), "r"(sz) : "memory");
            }
            asm volatile("cp.async.commit_group;" ::: "memory");
        };

        if (mt > 0) __syncthreads();   // prior tile's last compute must finish
        load_chunk(0, 0);
        if (nchunk > 1) load_chunk(1, 1);

        int s = 0;
        for (int c = 0; c < nchunk; ++c) {
            if (c + 1 < nchunk) {
                asm volatile("cp.async.wait_group 1;" ::: "memory");
            } else {
                asm volatile("cp.async.wait_group 0;" ::: "memory");
            }
            __syncthreads();
            if (c + 2 < nchunk) {
                int s2 = s + 2 >= NSTAGE ? s + 2 - NSTAGE : s + 2;
                load_chunk(c + 2, s2);
            }

            const uint32_t st = smbase + (uint32_t)s * STAGEB;
            const uint32_t sA = st;
            const uint32_t sB = st + PARTB;

            uint32_t af[2][2][4];
            uint32_t bf[2][4];
#pragma unroll
            for (int mi = 0; mi < 2; ++mi)
                ldsm4(sA + (uint32_t)(wm * 32 + mi * 16) * PITCHB + aRowOff + aByte,
                      af[0][mi]);
            ldsm4(sB + (uint32_t)(wn * 64) * PITCHB + bRowOff + bByte, bf[0]);

#pragma unroll
            for (int kk = 0; kk < 4; ++kk) {
                const int cur = kk & 1;
                const int nxt = cur ^ 1;
                if (kk < 3) {
                    const uint32_t kbn = (uint32_t)(kk + 1) * 32;
#pragma unroll
                    for (int mi = 0; mi < 2; ++mi)
                        ldsm4(sA + (uint32_t)(wm * 32 + mi * 16) * PITCHB + aRowOff + kbn + aByte,
                              af[nxt][mi]);
                }
                const uint32_t kb = (uint32_t)kk * 32;
#pragma unroll
                for (int p = 0; p < 4; ++p) {
                    const int pc = p & 1;
                    const int pn = pc ^ 1;
                    if (p < 3) {
                        ldsm4(sB + (uint32_t)(wn * 64 + (p + 1) * 16) * PITCHB + bRowOff + kb + bByte,
                              bf[pn]);
                    } else if (kk < 3) {
                        ldsm4(sB + (uint32_t)(wn * 64) * PITCHB + bRowOff + kb + 32 + bByte,
                              bf[pn]);
                    }
#pragma unroll
                    for (int mi = 0; mi < 2; ++mi) {
                        mma_f16(acc[mi][2 * p],     af[cur][mi], bf[pc][0], bf[pc][1]);
                        mma_f16(acc[mi][2 * p + 1], af[cur][mi], bf[pc][2], bf[pc][3]);
                    }
                }
            }
            ++s;
            if (s == NSTAGE) s = 0;
        }

        // ---- epilogue ----
        if (Cq16 != nullptr) {
            const int head = col0 >> 8;
#pragma unroll
            for (int mi = 0; mi < 2; ++mi) {
                int rbase = row0 + wm * 32 + mi * 16 + g;
                float sq0 = 0.0f, sq1 = 0.0f;
#pragma unroll
                for (int ni = 0; ni < 8; ++ni) {
                    int cb = col0 + wn * 64 + ni * 8 + 2 * t;
                    float b0 = bias[cb];
                    float b1 = bias[cb + 1];
                    float v00 = acc[mi][ni][0] + b0;
                    float v01 = acc[mi][ni][1] + b1;
                    float v10 = acc[mi][ni][2] + b0;
                    float v11 = acc[mi][ni][3] + b1;
                    sq0 += v00 * v00 + v01 * v01;
                    sq1 += v10 * v10 + v11 * v11;
                    uint32_t p0 = packhalf2(v00, v01);
                    uint32_t p1 = packhalf2(v10, v11);
                    int r0i = rbase;
                    int r1i = rbase + 8;
                    uint16_t* d0 = (r0i < m_split) ? (Cq16 + (size_t)r0i * NH + cb)
                                                   : (Cs16 + (size_t)(r0i - m_split) * NH + cb);
                    uint16_t* d1 = (r1i < m_split) ? (Cq16 + (size_t)r1i * NH + cb)
                                                   : (Cs16 + (size_t)(r1i - m_split) * NH + cb);
                    *reinterpret_cast<uint32_t*>(d0) = p0;
                    *reinterpret_cast<uint32_t*>(d1) = p1;
                }
                atomicAdd(&sumsq[(size_t)rbase * HH + head], sq0);
                atomicAdd(&sumsq[(size_t)(rbase + 8) * HH + head], sq1);
            }
        } else {
            const bool has_bias = (bias != nullptr);
#pragma unroll
            for (int mi = 0; mi < 2; ++mi) {
                int rbase = row0 + wm * 32 + mi * 16 + g;
#pragma unroll
                for (int ni = 0; ni < 8; ++ni) {
                    int cb = col0 + wn * 64 + ni * 8 + 2 * t;
                    if (cb >= Ncols) continue;
                    float b0 = has_bias ? bias[cb] : 0.0f;
                    float b1 = (has_bias && (cb + 1) < Ncols) ? bias[cb + 1] : 0.0f;
                    float vals[2][2] = { { acc[mi][ni][0] + b0, acc[mi][ni][1] + b1 },
                                         { acc[mi][ni][2] + b0, acc[mi][ni][3] + b1 } };
#pragma unroll
                    for (int rr2 = 0; rr2 < 2; ++rr2) {
                        int r = rbase + rr2 * 8;
                        if (r < m_split) {
                            if (cb + 1 < colsplit) {
                                *reinterpret_cast<float2*>(Cq + (size_t)r * ld_q + cb) =
                                    make_float2(vals[rr2][0], vals[rr2][1]);
                            } else {
                                if (cb < colsplit) Cq[(size_t)r * ld_q + cb] = vals[rr2][0];
                                if (cb + 1 < colsplit && cb + 1 < Ncols)
                                    Cq[(size_t)r * ld_q + cb + 1] = vals[rr2][1];
                            }
                        } else {
                            int rs = r - m_split;
#pragma unroll
                            for (int jj = 0; jj < 2; ++jj) {
                                int col = cb + jj;
                                if (col >= Ncols) break;
                                Ccls[(size_t)rs * CC + (col - colsplit)] = vals[rr2][jj];
                            }
                        }
                    }
                }
            }
        }
    }
}

// ---------------- kernel 4: fused in-place L2 normalize (fp16) ----------------
__global__ void normalize_kernel(uint16_t* __restrict__ Q,
                                 uint16_t* __restrict__ S,
                                 const float* __restrict__ sumsq) {
    int wwid = (blockIdx.x * blockDim.x + threadIdx.x) >> 5;
    int lane = threadIdx.x & 31;
    if (wwid >= MTOTAL * HH) return;
    int row = wwid / HH;
    int h = wwid - row * HH;
    float ss = sumsq[wwid];
    float extra = (row < NQ) ? (1.0f / (float)HH) : 1.0f;
    float sc = extra / fmaxf(sqrtf(ss), EPSN);
    uint16_t* p = ((row < NQ) ? (Q + (size_t)row * NH)
                              : (S + (size_t)(row - NQ) * NH)) + h * PP;
    uint4* p4 = reinterpret_cast<uint4*>(p);
    uint4 v = p4[lane];
    uint32_t* vw = reinterpret_cast<uint32_t*>(&v);
#pragma unroll
    for (int j = 0; j < 4; ++j) {
        __half2 h2 = *reinterpret_cast<__half2*>(&vw[j]);
        float2 f2 = __half22float2(h2);
        vw[j] = packhalf2(f2.x * sc, f2.y * sc);
    }
    p4[lane] = v;
}

// ---------------- launch -------------------------------------------------------
extern "C" void kernel_launch(void* const* d_in, const int* in_sizes, int n_in,
                              void* d_out, int out_size) {
    const float* query   = (const float*)d_in[0];
    const float* support = (const float*)d_in[1];
    const float* head_W  = (const float*)d_in[2];
    const float* head_b  = (const float*)d_in[3];
    const float* cls_W   = (const float*)d_in[4];
    const float* cls_b   = (const float*)d_in[5];

    float* out_match = (float*)d_out;
    float* out_preds = (float*)d_out + (size_t)NQ * NS;

    uint16_t *X, *Wt, *Qn, *Sn;
    float *bias, *sumsq;
    cudaGetSymbolAddress((void**)&X,     g_X);
    cudaGetSymbolAddress((void**)&Wt,    g_Wt);
    cudaGetSymbolAddress((void**)&bias,  g_bias);
    cudaGetSymbolAddress((void**)&Qn,    g_Qn);
    cudaGetSymbolAddress((void**)&Sn,    g_Sn);
    cudaGetSymbolAddress((void**)&sumsq, g_sumsq);

    cudaFuncSetAttribute(gemm_kernel,
                         cudaFuncAttributeMaxDynamicSharedMemorySize, SMEMB);

    // 1) mean(query) + support -> fp16 merged X
    {
        int n4tot = (NQ * DD + NS * DD) / 4;
        prep_kernel<<<(n4tot + 255) / 256, 256>>>(query, support);
    }
    // 2) pack W^T + bias, zero sumsq
    {
        int total = NTOT * DD;
        pack_kernel<<<(total + 255) / 256, 256>>>(head_W, head_b, cls_W, cls_b);
    }
    // 3) projection GEMM: X[6144,1024] @ Wt[768,1024]^T -> fp16 + sumsq
    {
        dim3 grid(NH / BN, MTOTAL / BM);   // (6, 48) = 288 CTAs, single wave
        gemm_kernel<<<grid, 256, SMEMB>>>(X, Wt, DD, NH, bias,
                                          nullptr, 0, nullptr, NQ, NH,
                                          Qn, Sn, sumsq, 1,
                                          nullptr, nullptr, 0, 0, nullptr,
                                          nullptr, 0);
    }
    // 4) fused in-place normalize (Q folds 1/H)
    {
        int warps = MTOTAL * HH;
        normalize_kernel<<<(warps * 32 + 255) / 256, 256>>>(Qn, Sn, sumsq);
    }
    // 5) match GEMM (2 M-tiles per CTA, single wave) + fused aux cls GEMM
    {
        dim3 grid(NS / BN, NQ / (2 * BM) + 1);   // (16, 17); last y-row = aux
        gemm_kernel<<<grid, 256, SMEMB>>>(Qn, Sn, NH, NS, nullptr,
                                          out_match, NS, nullptr, NQ, NS,
                                          nullptr, nullptr, nullptr, 2,
                                          X + (size_t)NQ * DD, Wt + (size_t)NH * DD,
                                          DD, CC, bias + NH,
                                          out_preds, NS / BM);
    }
}

// round 13
// speedup vs baseline: 6.8876x; 1.0060x over previous
#include <cuda_runtime.h>
#include <cuda_fp16.h>
#include <cstdint>
#include <math.h>

// ---------------- problem constants ----------------------------------------
#define NQ     4096
#define DD     1024
#define NS     2048
#define HH     3
#define PP     256
#define CC     100
#define NH     768
#define NTOT   868
#define MTOTAL (NQ + NS)         // 6144 merged projection rows
#define EPSN   1e-8f

// ---------------- GEMM tiling ----------------------------------------------
#define BM     128
#define BN     128
#define BK     64
#define PITCHB 144               // 128 B data + 16 B pad (conflict-free)
#define PARTB  (BM * PITCHB)     // 18432 B
#define STAGEB (2 * PARTB)       // A | B  (36864 B)
#define NSTAGE 3
#define SMEMB  (NSTAGE * STAGEB) // 110592 B -> 2 CTAs/SM

// ---------------- scratch --------------------------------------------------
__device__ uint16_t g_X[MTOTAL * DD];    // fp16: rows 0..4095 mean(query), 4096.. support
__device__ uint16_t g_Wt[NTOT * DD];     // fp16 W^T (head rows 0..767, cls rows 768..867)
__device__ float    g_bias[NTOT];
__device__ uint16_t g_Qn[NQ * NH];       // fp16 Q proj (unnorm -> normalized in place)
__device__ uint16_t g_Sn[NS * NH];       // fp16 S proj (unnorm -> normalized in place)
__device__ float    g_sumsq[MTOTAL * HH];// per-(row,head) sum of squares

// ---------------- helpers ----------------------------------------------------
__device__ __forceinline__ uint32_t smem_u32_of(const void* p) {
    uint32_t a;
    asm("{ .reg .u64 t; cvta.to.shared.u64 t, %1; cvt.u32.u64 %0, t; }"
        : "=r"(a) : "l"(p));
    return a;
}

__device__ __forceinline__ void ldsm4(uint32_t addr, uint32_t* r) {
    asm volatile("ldmatrix.sync.aligned.m8n8.x4.shared.b16 {%0,%1,%2,%3}, [%4];"
                 : "=r"(r[0]), "=r"(r[1]), "=r"(r[2]), "=r"(r[3]) : "r"(addr));
}

__device__ __forceinline__ uint16_t tohalf(float x) {
    return __half_as_ushort(__float2half_rn(x));
}

__device__ __forceinline__ uint32_t packhalf2(float lo, float hi) {
    uint32_t r;
    asm("cvt.rn.f16x2.f32 %0, %1, %2;" : "=r"(r) : "f"(hi), "f"(lo));
    return r;
}

__device__ __forceinline__ void mma_f16(float* c, const uint32_t* a,
                                        uint32_t b0, uint32_t b1) {
    asm volatile(
        "mma.sync.aligned.m16n8k16.row.col.f32.f16.f16.f32 "
        "{%0,%1,%2,%3}, {%4,%5,%6,%7}, {%8,%9}, {%0,%1,%2,%3};"
        : "+f"(c[0]), "+f"(c[1]), "+f"(c[2]), "+f"(c[3])
        : "r"(a[0]), "r"(a[1]), "r"(a[2]), "r"(a[3]), "r"(b0), "r"(b1));
}

// ---------------- kernel 1: fused setup --------------------------------------
// i over max workload; does: mean(query)+support -> fp16 X, pack W^T fp16,
// pack bias, zero sumsq.
__global__ void setup_kernel(const float* __restrict__ q,
                             const float* __restrict__ s,
                             const float* __restrict__ hW,
                             const float* __restrict__ hb,
                             const float* __restrict__ cW,
                             const float* __restrict__ cb) {
    int i = blockIdx.x * blockDim.x + threadIdx.x;
    const int n4q = (NQ * DD) / 4;
    const int n4tot = n4q + (NS * DD) / 4;
    if (i < n4tot) {
        ushort4 hs;
        if (i < n4q) {
            const float4* p = reinterpret_cast<const float4*>(q);
            float4 a = p[i], b = p[i + n4q], c = p[i + 2 * n4q], d = p[i + 3 * n4q];
            hs.x = tohalf(0.25f * (a.x + b.x + c.x + d.x));
            hs.y = tohalf(0.25f * (a.y + b.y + c.y + d.y));
            hs.z = tohalf(0.25f * (a.z + b.z + c.z + d.z));
            hs.w = tohalf(0.25f * (a.w + b.w + c.w + d.w));
        } else {
            float4 v = reinterpret_cast<const float4*>(s)[i - n4q];
            hs.x = tohalf(v.x); hs.y = tohalf(v.y);
            hs.z = tohalf(v.z); hs.w = tohalf(v.w);
        }
        reinterpret_cast<ushort4*>(g_X)[i] = hs;
    }
    if (i < NTOT * DD) {
        int n = i >> 10;
        int k = i & 1023;
        float v;
        if (n < NH) {
            int h = n >> 8;
            int p = n & 255;
            v = hW[((size_t)h * DD + k) * PP + p];
        } else {
            v = cW[(size_t)k * CC + (n - NH)];
        }
        g_Wt[i] = tohalf(v);
    }
    if (i < NTOT) g_bias[i] = (i < NH) ? hb[i] : cb[i - NH];
    if (i < MTOTAL * HH) g_sumsq[i] = 0.0f;
}

// ---------------- kernel 2: fp16 HMMA GEMM (NT), flat-pipelined M-tiles -------
// Each main CTA processes `mtiles` consecutive M-tiles (same N strip) in one
// continuously-pipelined chunk stream (no drain at tile boundaries).
// fp16-out mode (Cq16 != nullptr): fp16 proj + atomic sumsq per (row,head).
// fp32 mode: row < m_split -> Cq; else -> Ccls by colsplit.
// Aux job (A2 != nullptr, blockIdx.y == gridDim.y-1): cls GEMM -> C2 fp32.
__global__ void __launch_bounds__(256, 2)
gemm_kernel(const uint16_t* __restrict__ A,
            const uint16_t* __restrict__ B,
            int K, int Ncols, const float* __restrict__ bias,
            float* __restrict__ Cq, int ld_q,
            float* __restrict__ Ccls,
            int m_split, int colsplit,
            uint16_t* __restrict__ Cq16, uint16_t* __restrict__ Cs16,
            float* __restrict__ sumsq,
            int mtiles,
            const uint16_t* __restrict__ A2,
            const uint16_t* __restrict__ B2,
            int K2, int N2, const float* __restrict__ bias2,
            float* __restrict__ C2, int aux_mtiles) {
    extern __shared__ __align__(128) char smem[];
    const uint32_t smbase = smem_u32_of(smem);

    int col0, rowbase;
    const bool aux = (A2 != nullptr) && ((int)blockIdx.y == (int)gridDim.y - 1);
    if (aux) {
        if ((int)blockIdx.x >= aux_mtiles) return;
        A = A2; B = B2; K = K2; Ncols = N2; bias = bias2;
        Ccls = C2; m_split = 0; colsplit = 0; Cq16 = nullptr;
        mtiles = 1;
        col0 = 0;
        rowbase = (int)blockIdx.x * BM;
    } else {
        col0 = blockIdx.x * BN;
        rowbase = (int)blockIdx.y * mtiles * BM;
    }

    const int tid = threadIdx.x;
    const int lane = tid & 31;
    const int wid = tid >> 5;
    const int wm = wid >> 1;
    const int wn = wid & 1;
    const int g = lane >> 2;
    const int t = lane & 3;
    const int nchunk = K / BK;
    const int total = mtiles * nchunk;

    const uint32_t aRowOff = (uint32_t)(lane & 15) * PITCHB;
    const uint32_t aByte   = (uint32_t)((lane >> 4) << 4);
    const uint32_t bRowOff = (uint32_t)(((lane >> 4) & 1) * 8 + (lane & 7)) * PITCHB;
    const uint32_t bByte   = (uint32_t)(((lane >> 3) & 1) << 4);

    float acc[2][8][4];
#pragma unroll
    for (int mi = 0; mi < 2; ++mi)
#pragma unroll
        for (int ni = 0; ni < 8; ++ni)
#pragma unroll
            for (int j = 0; j < 4; ++j) acc[mi][ni][j] = 0.0f;

    auto load_chunk = [&](int gc, int s) {
        const uint32_t st = smbase + (uint32_t)s * STAGEB;
        const int tile = gc / nchunk;
        const int k0 = (gc - tile * nchunk) * BK;
        const int row0 = rowbase + tile * BM;
#pragma unroll
        for (int j = 0; j < 8; ++j) {
            int idx = tid + 256 * j;
            int part = idx >> 10;          // 0:A 1:B
            int within = idx & 1023;
            int r = within >> 3;
            int q = within & 7;
            uint32_t dst = st + (uint32_t)part * PARTB + r * PITCHB + q * 16;
            const uint16_t* src;
            int sz = 16;
            if (part == 0) {
                src = A + (size_t)(row0 + r) * K + k0 + q * 8;
            } else {
                int n = col0 + r;
                if (n < Ncols) {
                    src = B + (size_t)n * K + k0 + q * 8;
                } else {
                    src = B;
                    sz = 0;
                }
            }
            asm volatile("cp.async.cg.shared.global [%0], [%1], 16, %2;"
                         :: "r"(dst), "l"(src), "r"(sz) : "memory");
        }
        asm volatile("cp.async.commit_group;" ::: "memory");
    };

    load_chunk(0, 0);
    if (total > 1) load_chunk(1, 1);

    int s = 0;
    for (int gc = 0; gc < total; ++gc) {
        if (gc + 1 < total) {
            asm volatile("cp.async.wait_group 1;" ::: "memory");
        } else {
            asm volatile("cp.async.wait_group 0;" ::: "memory");
        }
        __syncthreads();
        if (gc + 2 < total) {
            int s2 = s + 2 >= NSTAGE ? s + 2 - NSTAGE : s + 2;
            load_chunk(gc + 2, s2);
        }

        const uint32_t st = smbase + (uint32_t)s * STAGEB;
        const uint32_t sA = st;
        const uint32_t sB = st + PARTB;

        uint32_t af[2][2][4];
        uint32_t bf[2][4];
#pragma unroll
        for (int mi = 0; mi < 2; ++mi)
            ldsm4(sA + (uint32_t)(wm * 32 + mi * 16) * PITCHB + aRowOff + aByte,
                  af[0][mi]);
        ldsm4(sB + (uint32_t)(wn * 64) * PITCHB + bRowOff + bByte, bf[0]);

#pragma unroll
        for (int kk = 0; kk < 4; ++kk) {
            const int cur = kk & 1;
            const int nxt = cur ^ 1;
            if (kk < 3) {
                const uint32_t kbn = (uint32_t)(kk + 1) * 32;
#pragma unroll
                for (int mi = 0; mi < 2; ++mi)
                    ldsm4(sA + (uint32_t)(wm * 32 + mi * 16) * PITCHB + aRowOff + kbn + aByte,
                          af[nxt][mi]);
            }
            const uint32_t kb = (uint32_t)kk * 32;
#pragma unroll
            for (int p = 0; p < 4; ++p) {
                const int pc = p & 1;
                const int pn = pc ^ 1;
                if (p < 3) {
                    ldsm4(sB + (uint32_t)(wn * 64 + (p + 1) * 16) * PITCHB + bRowOff + kb + bByte,
                          bf[pn]);
                } else if (kk < 3) {
                    ldsm4(sB + (uint32_t)(wn * 64) * PITCHB + bRowOff + kb + 32 + bByte,
                          bf[pn]);
                }
#pragma unroll
                for (int mi = 0; mi < 2; ++mi) {
                    mma_f16(acc[mi][2 * p],     af[cur][mi], bf[pc][0], bf[pc][1]);
                    mma_f16(acc[mi][2 * p + 1], af[cur][mi], bf[pc][2], bf[pc][3]);
                }
            }
        }

        // ---- tile boundary: epilogue + acc reset (loads for next tile in flight)
        if (((gc + 1) % nchunk) == 0) {
            const int tile = gc / nchunk;
            const int row0 = rowbase + tile * BM;
            if (Cq16 != nullptr) {
                const int head = col0 >> 8;
#pragma unroll
                for (int mi = 0; mi < 2; ++mi) {
                    int rb = row0 + wm * 32 + mi * 16 + g;
                    float sq0 = 0.0f, sq1 = 0.0f;
#pragma unroll
                    for (int ni = 0; ni < 8; ++ni) {
                        int cb = col0 + wn * 64 + ni * 8 + 2 * t;
                        float b0 = bias[cb];
                        float b1 = bias[cb + 1];
                        float v00 = acc[mi][ni][0] + b0;
                        float v01 = acc[mi][ni][1] + b1;
                        float v10 = acc[mi][ni][2] + b0;
                        float v11 = acc[mi][ni][3] + b1;
                        sq0 += v00 * v00 + v01 * v01;
                        sq1 += v10 * v10 + v11 * v11;
                        uint32_t p0 = packhalf2(v00, v01);
                        uint32_t p1 = packhalf2(v10, v11);
                        int r0i = rb;
                        int r1i = rb + 8;
                        uint16_t* d0 = (r0i < m_split) ? (Cq16 + (size_t)r0i * NH + cb)
                                                       : (Cs16 + (size_t)(r0i - m_split) * NH + cb);
                        uint16_t* d1 = (r1i < m_split) ? (Cq16 + (size_t)r1i * NH + cb)
                                                       : (Cs16 + (size_t)(r1i - m_split) * NH + cb);
                        *reinterpret_cast<uint32_t*>(d0) = p0;
                        *reinterpret_cast<uint32_t*>(d1) = p1;
                    }
                    atomicAdd(&sumsq[(size_t)rb * HH + head], sq0);
                    atomicAdd(&sumsq[(size_t)(rb + 8) * HH + head], sq1);
                }
            } else {
                const bool has_bias = (bias != nullptr);
#pragma unroll
                for (int mi = 0; mi < 2; ++mi) {
                    int rb = row0 + wm * 32 + mi * 16 + g;
#pragma unroll
                    for (int ni = 0; ni < 8; ++ni) {
                        int cb = col0 + wn * 64 + ni * 8 + 2 * t;
                        if (cb >= Ncols) continue;
                        float b0 = has_bias ? bias[cb] : 0.0f;
                        float b1 = (has_bias && (cb + 1) < Ncols) ? bias[cb + 1] : 0.0f;
                        float vals[2][2] = { { acc[mi][ni][0] + b0, acc[mi][ni][1] + b1 },
                                             { acc[mi][ni][2] + b0, acc[mi][ni][3] + b1 } };
#pragma unroll
                        for (int rr2 = 0; rr2 < 2; ++rr2) {
                            int r = rb + rr2 * 8;
                            if (r < m_split) {
                                if (cb + 1 < colsplit) {
                                    *reinterpret_cast<float2*>(Cq + (size_t)r * ld_q + cb) =
                                        make_float2(vals[rr2][0], vals[rr2][1]);
                                } else {
                                    if (cb < colsplit) Cq[(size_t)r * ld_q + cb] = vals[rr2][0];
                                    if (cb + 1 < colsplit && cb + 1 < Ncols)
                                        Cq[(size_t)r * ld_q + cb + 1] = vals[rr2][1];
                                }
                            } else {
                                int rs = r - m_split;
#pragma unroll
                                for (int jj = 0; jj < 2; ++jj) {
                                    int col = cb + jj;
                                    if (col >= Ncols) break;
                                    Ccls[(size_t)rs * CC + (col - colsplit)] = vals[rr2][jj];
                                }
                            }
                        }
                    }
                }
            }
            if (gc + 1 < total) {
#pragma unroll
                for (int mi = 0; mi < 2; ++mi)
#pragma unroll
                    for (int ni = 0; ni < 8; ++ni)
#pragma unroll
                        for (int j = 0; j < 4; ++j) acc[mi][ni][j] = 0.0f;
            }
        }

        ++s;
        if (s == NSTAGE) s = 0;
    }
}

// ---------------- kernel 3: fused in-place L2 normalize (fp16) ----------------
__global__ void normalize_kernel(uint16_t* __restrict__ Q,
                                 uint16_t* __restrict__ S,
                                 const float* __restrict__ sumsq) {
    int wwid = (blockIdx.x * blockDim.x + threadIdx.x) >> 5;
    int lane = threadIdx.x & 31;
    if (wwid >= MTOTAL * HH) return;
    int row = wwid / HH;
    int h = wwid - row * HH;
    float ss = sumsq[wwid];
    float extra = (row < NQ) ? (1.0f / (float)HH) : 1.0f;
    float sc = extra / fmaxf(sqrtf(ss), EPSN);
    uint16_t* p = ((row < NQ) ? (Q + (size_t)row * NH)
                              : (S + (size_t)(row - NQ) * NH)) + h * PP;
    uint4* p4 = reinterpret_cast<uint4*>(p);
    uint4 v = p4[lane];
    uint32_t* vw = reinterpret_cast<uint32_t*>(&v);
#pragma unroll
    for (int j = 0; j < 4; ++j) {
        __half2 h2 = *reinterpret_cast<__half2*>(&vw[j]);
        float2 f2 = __half22float2(h2);
        vw[j] = packhalf2(f2.x * sc, f2.y * sc);
    }
    p4[lane] = v;
}

// ---------------- launch -------------------------------------------------------
extern "C" void kernel_launch(void* const* d_in, const int* in_sizes, int n_in,
                              void* d_out, int out_size) {
    const float* query   = (const float*)d_in[0];
    const float* support = (const float*)d_in[1];
    const float* head_W  = (const float*)d_in[2];
    const float* head_b  = (const float*)d_in[3];
    const float* cls_W   = (const float*)d_in[4];
    const float* cls_b   = (const float*)d_in[5];

    float* out_match = (float*)d_out;
    float* out_preds = (float*)d_out + (size_t)NQ * NS;

    uint16_t *X, *Wt, *Qn, *Sn;
    float *bias, *sumsq;
    cudaGetSymbolAddress((void**)&X,     g_X);
    cudaGetSymbolAddress((void**)&Wt,    g_Wt);
    cudaGetSymbolAddress((void**)&bias,  g_bias);
    cudaGetSymbolAddress((void**)&Qn,    g_Qn);
    cudaGetSymbolAddress((void**)&Sn,    g_Sn);
    cudaGetSymbolAddress((void**)&sumsq, g_sumsq);

    cudaFuncSetAttribute(gemm_kernel,
                         cudaFuncAttributeMaxDynamicSharedMemorySize, SMEMB);

    // 1) fused setup: mean+convert X, pack W^T/bias, zero sumsq
    {
        int n4tot = (NQ * DD + NS * DD) / 4;
        setup_kernel<<<(n4tot + 255) / 256, 256>>>(query, support,
                                                   head_W, head_b, cls_W, cls_b);
    }
    // 2) projection GEMM: X[6144,1024] @ Wt[768,1024]^T -> fp16 + sumsq
    {
        dim3 grid(NH / BN, MTOTAL / BM);   // (6, 48) = 288 CTAs, single wave
        gemm_kernel<<<grid, 256, SMEMB>>>(X, Wt, DD, NH, bias,
                                          nullptr, 0, nullptr, NQ, NH,
                                          Qn, Sn, sumsq, 1,
                                          nullptr, nullptr, 0, 0, nullptr,
                                          nullptr, 0);
    }
    // 3) fused in-place normalize (Q folds 1/H)
    {
        int warps = MTOTAL * HH;
        normalize_kernel<<<(warps * 32 + 255) / 256, 256>>>(Qn, Sn, sumsq);
    }
    // 4) match GEMM (2 M-tiles per CTA, flat-pipelined) + fused aux cls GEMM
    {
        dim3 grid(NS / BN, NQ / (2 * BM) + 1);   // (16, 17); last y-row = aux
        gemm_kernel<<<grid, 256, SMEMB>>>(Qn, Sn, NH, NS, nullptr,
                                          out_match, NS, nullptr, NQ, NS,
                                          nullptr, nullptr, nullptr, 2,
                                          X + (size_t)NQ * DD, Wt + (size_t)NH * DD,
                                          DD, CC, bias + NH,
                                          out_preds, NS / BM);
    }
}

// round 14
// speedup vs baseline: 7.5570x; 1.0972x over previous
#include <cuda_runtime.h>
#include <cuda_fp16.h>
#include <cstdint>
#include <math.h>

// ---------------- problem constants ----------------------------------------
#define NQ     4096
#define DD     1024
#define NS     2048
#define HH     3
#define PP     256
#define CC     100
#define NH     768
#define NTOT   868
#define MTOTAL (NQ + NS)
#define EPSN   1e-8f

// ---------------- shared tiling constants ------------------------------------
#define BK     64
#define PITCHB 144               // 128 B data + 16 B pad (conflict-free)

// match kernel tiling (256 threads, 2 CTAs/SM)
#define BM     128
#define BN     128
#define PARTB  (BM * PITCHB)     // 18432
#define STAGEB (2 * PARTB)       // 36864
#define NSTAGE 3
#define SMEMB  (NSTAGE * STAGEB) // 110592

// proj kernel tiling (512 threads, 1 CTA/SM, full head per CTA)
#define PBM    128
#define PBN    256
#define PPARTA (PBM * PITCHB)            // 18432
#define PPARTB (PBN * PITCHB)            // 36864
#define PSTAGE (PPARTA + PPARTB)         // 55296
#define PSMEM  (NSTAGE * PSTAGE)         // 165888

// ---------------- scratch --------------------------------------------------
__device__ uint16_t g_X[MTOTAL * DD];    // fp16: rows 0..4095 mean(query), 4096.. support
__device__ uint16_t g_Wt[NTOT * DD];     // fp16 W^T (head rows 0..767, cls rows 768..867)
__device__ float    g_bias[NTOT];
__device__ uint16_t g_Qn[NQ * NH];       // fp16 normalized Q (x 1/H)
__device__ uint16_t g_Sn[NS * NH];       // fp16 normalized S

// ---------------- helpers ----------------------------------------------------
__device__ __forceinline__ uint32_t smem_u32_of(const void* p) {
    uint32_t a;
    asm("{ .reg .u64 t; cvta.to.shared.u64 t, %1; cvt.u32.u64 %0, t; }"
        : "=r"(a) : "l"(p));
    return a;
}

__device__ __forceinline__ void ldsm4(uint32_t addr, uint32_t* r) {
    asm volatile("ldmatrix.sync.aligned.m8n8.x4.shared.b16 {%0,%1,%2,%3}, [%4];"
                 : "=r"(r[0]), "=r"(r[1]), "=r"(r[2]), "=r"(r[3]) : "r"(addr));
}

__device__ __forceinline__ uint16_t tohalf(float x) {
    return __half_as_ushort(__float2half_rn(x));
}

__device__ __forceinline__ uint32_t packhalf2(float lo, float hi) {
    uint32_t r;
    asm("cvt.rn.f16x2.f32 %0, %1, %2;" : "=r"(r) : "f"(hi), "f"(lo));
    return r;
}

__device__ __forceinline__ void mma_f16(float* c, const uint32_t* a,
                                        uint32_t b0, uint32_t b1) {
    asm volatile(
        "mma.sync.aligned.m16n8k16.row.col.f32.f16.f16.f32 "
        "{%0,%1,%2,%3}, {%4,%5,%6,%7}, {%8,%9}, {%0,%1,%2,%3};"
        : "+f"(c[0]), "+f"(c[1]), "+f"(c[2]), "+f"(c[3])
        : "r"(a[0]), "r"(a[1]), "r"(a[2]), "r"(a[3]), "r"(b0), "r"(b1));
}

// ---------------- kernel 1: fused setup --------------------------------------
__global__ void setup_kernel(const float* __restrict__ q,
                             const float* __restrict__ s,
                             const float* __restrict__ hW,
                             const float* __restrict__ hb,
                             const float* __restrict__ cW,
                             const float* __restrict__ cb) {
    int i = blockIdx.x * blockDim.x + threadIdx.x;
    const int n4q = (NQ * DD) / 4;
    const int n4tot = n4q + (NS * DD) / 4;
    if (i < n4tot) {
        ushort4 hs;
        if (i < n4q) {
            const float4* p = reinterpret_cast<const float4*>(q);
            float4 a = p[i], b = p[i + n4q], c = p[i + 2 * n4q], d = p[i + 3 * n4q];
            hs.x = tohalf(0.25f * (a.x + b.x + c.x + d.x));
            hs.y = tohalf(0.25f * (a.y + b.y + c.y + d.y));
            hs.z = tohalf(0.25f * (a.z + b.z + c.z + d.z));
            hs.w = tohalf(0.25f * (a.w + b.w + c.w + d.w));
        } else {
            float4 v = reinterpret_cast<const float4*>(s)[i - n4q];
            hs.x = tohalf(v.x); hs.y = tohalf(v.y);
            hs.z = tohalf(v.z); hs.w = tohalf(v.w);
        }
        reinterpret_cast<ushort4*>(g_X)[i] = hs;
    }
    if (i < NTOT * DD) {
        int n = i >> 10;
        int k = i & 1023;
        float v;
        if (n < NH) {
            int h = n >> 8;
            int p = n & 255;
            v = hW[((size_t)h * DD + k) * PP + p];
        } else {
            v = cW[(size_t)k * CC + (n - NH)];
        }
        g_Wt[i] = tohalf(v);
    }
    if (i < NTOT) g_bias[i] = (i < NH) ? hb[i] : cb[i - NH];
}

// ---------------- kernel 2: projection GEMM + fused L2 normalize --------------
// 512 threads, tile 128 x 256 (one full head per CTA). Warp grid 4M x 4N,
// warp tile 32x64. Epilogue: bias, per-row sq-sum reduce (quad shfl + smem
// across the 4 N-warps), scale = extra / max(sqrt, eps), fp16 store.
__global__ void __launch_bounds__(512, 1)
proj_kernel(const uint16_t* __restrict__ A,
            const uint16_t* __restrict__ B,
            const float* __restrict__ bias,
            uint16_t* __restrict__ Qn, uint16_t* __restrict__ Sn) {
    extern __shared__ __align__(128) char smem[];
    const uint32_t smbase = smem_u32_of(smem);

    const int tid = threadIdx.x;
    const int lane = tid & 31;
    const int wid = tid >> 5;
    const int wm = wid >> 2;        // 0..3
    const int wn = wid & 3;         // 0..3
    const int g = lane >> 2;
    const int t = lane & 3;
    const int row0 = blockIdx.y * PBM;
    const int col0 = blockIdx.x * PBN;    // head * 256
    const int nchunk = DD / BK;           // 16

    float acc[2][8][4];
#pragma unroll
    for (int mi = 0; mi < 2; ++mi)
#pragma unroll
        for (int ni = 0; ni < 8; ++ni)
#pragma unroll
            for (int j = 0; j < 4; ++j) acc[mi][ni][j] = 0.0f;

    auto load_chunk = [&](int c, int s) {
        const uint32_t st = smbase + (uint32_t)s * PSTAGE;
        const int k0 = c * BK;
#pragma unroll
        for (int j = 0; j < 6; ++j) {
            int idx = tid + 512 * j;
            if (idx < 1024) {                 // A: 128 rows x 8 slots
                int r = idx >> 3;
                int q = idx & 7;
                uint32_t dst = st + r * PITCHB + q * 16;
                const uint16_t* src = A + (size_t)(row0 + r) * DD + k0 + q * 8;
                asm volatile("cp.async.cg.shared.global [%0], [%1], 16;"
                             :: "r"(dst), "l"(src) : "memory");
            } else {                          // B: 256 rows x 8 slots
                int within = idx - 1024;
                int r = within >> 3;
                int q = within & 7;
                uint32_t dst = st + PPARTA + r * PITCHB + q * 16;
                const uint16_t* src = B + (size_t)(col0 + r) * DD + k0 + q * 8;
                asm volatile("cp.async.cg.shared.global [%0], [%1], 16;"
                             :: "r"(dst), "l"(src) : "memory");
            }
        }
        asm volatile("cp.async.commit_group;" ::: "memory");
    };

    load_chunk(0, 0);
    load_chunk(1, 1);

    const uint32_t aRowOff = (uint32_t)(lane & 15) * PITCHB;
    const uint32_t aByte   = (uint32_t)((lane >> 4) << 4);
    const uint32_t bRowOff = (uint32_t)(((lane >> 4) & 1) * 8 + (lane & 7)) * PITCHB;
    const uint32_t bByte   = (uint32_t)(((lane >> 3) & 1) << 4);

    int s = 0;
    for (int c = 0; c < nchunk; ++c) {
        if (c + 1 < nchunk) {
            asm volatile("cp.async.wait_group 1;" ::: "memory");
        } else {
            asm volatile("cp.async.wait_group 0;" ::: "memory");
        }
        __syncthreads();
        if (c + 2 < nchunk) {
            int s2 = s + 2 >= NSTAGE ? s + 2 - NSTAGE : s + 2;
            load_chunk(c + 2, s2);
        }

        const uint32_t st = smbase + (uint32_t)s * PSTAGE;
        const uint32_t sA = st;
        const uint32_t sB = st + PPARTA;

        uint32_t af[2][2][4];
        uint32_t bf[2][4];
#pragma unroll
        for (int mi = 0; mi < 2; ++mi)
            ldsm4(sA + (uint32_t)(wm * 32 + mi * 16) * PITCHB + aRowOff + aByte,
                  af[0][mi]);
        ldsm4(sB + (uint32_t)(wn * 64) * PITCHB + bRowOff + bByte, bf[0]);

#pragma unroll
        for (int kk = 0; kk < 4; ++kk) {
            const int cur = kk & 1;
            const int nxt = cur ^ 1;
            if (kk < 3) {
                const uint32_t kbn = (uint32_t)(kk + 1) * 32;
#pragma unroll
                for (int mi = 0; mi < 2; ++mi)
                    ldsm4(sA + (uint32_t)(wm * 32 + mi * 16) * PITCHB + aRowOff + kbn + aByte,
                          af[nxt][mi]);
            }
            const uint32_t kb = (uint32_t)kk * 32;
#pragma unroll
            for (int p = 0; p < 4; ++p) {
                const int pc = p & 1;
                const int pn = pc ^ 1;
                if (p < 3) {
                    ldsm4(sB + (uint32_t)(wn * 64 + (p + 1) * 16) * PITCHB + bRowOff + kb + bByte,
                          bf[pn]);
                } else if (kk < 3) {
                    ldsm4(sB + (uint32_t)(wn * 64) * PITCHB + bRowOff + kb + 32 + bByte,
                          bf[pn]);
                }
#pragma unroll
                for (int mi = 0; mi < 2; ++mi) {
                    mma_f16(acc[mi][2 * p],     af[cur][mi], bf[pc][0], bf[pc][1]);
                    mma_f16(acc[mi][2 * p + 1], af[cur][mi], bf[pc][2], bf[pc][3]);
                }
            }
        }
        ++s;
        if (s == NSTAGE) s = 0;
    }

    // ---- fused epilogue: bias + per-row L2 norm over the full head ----
    __syncthreads();                      // all compute done; smem reusable
    float* red = reinterpret_cast<float*>(smem);   // [128 rows][4 wn]

#pragma unroll
    for (int mi = 0; mi < 2; ++mi) {
        int rl = wm * 32 + mi * 16 + g;
        float sq0 = 0.0f, sq1 = 0.0f;
#pragma unroll
        for (int ni = 0; ni < 8; ++ni) {
            int cl = wn * 64 + ni * 8 + 2 * t;
            float b0 = bias[col0 + cl];
            float b1 = bias[col0 + cl + 1];
            acc[mi][ni][0] += b0;
            acc[mi][ni][1] += b1;
            acc[mi][ni][2] += b0;
            acc[mi][ni][3] += b1;
            sq0 += acc[mi][ni][0] * acc[mi][ni][0] + acc[mi][ni][1] * acc[mi][ni][1];
            sq1 += acc[mi][ni][2] * acc[mi][ni][2] + acc[mi][ni][3] * acc[mi][ni][3];
        }
        sq0 += __shfl_xor_sync(0xffffffffu, sq0, 1);
        sq0 += __shfl_xor_sync(0xffffffffu, sq0, 2);
        sq1 += __shfl_xor_sync(0xffffffffu, sq1, 1);
        sq1 += __shfl_xor_sync(0xffffffffu, sq1, 2);
        if (t == 0) {
            red[rl * 4 + wn] = sq0;
            red[(rl + 8) * 4 + wn] = sq1;
        }
    }
    __syncthreads();

    const float extra = (row0 < NQ) ? (1.0f / (float)HH) : 1.0f;
#pragma unroll
    for (int mi = 0; mi < 2; ++mi) {
        int rl = wm * 32 + mi * 16 + g;
        float s0 = red[rl * 4] + red[rl * 4 + 1] + red[rl * 4 + 2] + red[rl * 4 + 3];
        float s1 = red[(rl + 8) * 4] + red[(rl + 8) * 4 + 1]
                 + red[(rl + 8) * 4 + 2] + red[(rl + 8) * 4 + 3];
        float sc0 = extra / fmaxf(sqrtf(s0), EPSN);
        float sc1 = extra / fmaxf(sqrtf(s1), EPSN);
        int gr0 = row0 + rl;
        int gr1 = gr0 + 8;
        uint16_t* d0 = (gr0 < NQ) ? (Qn + (size_t)gr0 * NH) : (Sn + (size_t)(gr0 - NQ) * NH);
        uint16_t* d1 = (gr1 < NQ) ? (Qn + (size_t)gr1 * NH) : (Sn + (size_t)(gr1 - NQ) * NH);
#pragma unroll
        for (int ni = 0; ni < 8; ++ni) {
            int cl = wn * 64 + ni * 8 + 2 * t;
            uint32_t p0 = packhalf2(acc[mi][ni][0] * sc0, acc[mi][ni][1] * sc0);
            uint32_t p1 = packhalf2(acc[mi][ni][2] * sc1, acc[mi][ni][3] * sc1);
            *reinterpret_cast<uint32_t*>(d0 + col0 + cl) = p0;
            *reinterpret_cast<uint32_t*>(d1 + col0 + cl) = p1;
        }
    }
}

// ---------------- kernel 3: match GEMM (flat 2 M-tiles) + aux cls GEMM --------
__global__ void __launch_bounds__(256, 2)
match_kernel(const uint16_t* __restrict__ A,
             const uint16_t* __restrict__ B,
             float* __restrict__ C,             // match out [NQ, NS]
             int mtiles,
             const uint16_t* __restrict__ A2,
             const uint16_t* __restrict__ B2,
             const float* __restrict__ bias2,
             float* __restrict__ C2, int aux_mtiles) {
    extern __shared__ __align__(128) char smem[];
    const uint32_t smbase = smem_u32_of(smem);

    int col0, rowbase, K, Ncols;
    const bool aux = ((int)blockIdx.y == (int)gridDim.y - 1);
    if (aux) {
        if ((int)blockIdx.x >= aux_mtiles) return;
        A = A2; B = B2; K = DD; Ncols = CC;
        mtiles = 1;
        col0 = 0;
        rowbase = (int)blockIdx.x * BM;
    } else {
        K = NH; Ncols = NS;
        col0 = blockIdx.x * BN;
        rowbase = (int)blockIdx.y * mtiles * BM;
    }

    const int tid = threadIdx.x;
    const int lane = tid & 31;
    const int wid = tid >> 5;
    const int wm = wid >> 1;
    const int wn = wid & 1;
    const int g = lane >> 2;
    const int t = lane & 3;
    const int nchunk = K / BK;
    const int total = mtiles * nchunk;

    const uint32_t aRowOff = (uint32_t)(lane & 15) * PITCHB;
    const uint32_t aByte   = (uint32_t)((lane >> 4) << 4);
    const uint32_t bRowOff = (uint32_t)(((lane >> 4) & 1) * 8 + (lane & 7)) * PITCHB;
    const uint32_t bByte   = (uint32_t)(((lane >> 3) & 1) << 4);

    float acc[2][8][4];
#pragma unroll
    for (int mi = 0; mi < 2; ++mi)
#pragma unroll
        for (int ni = 0; ni < 8; ++ni)
#pragma unroll
            for (int j = 0; j < 4; ++j) acc[mi][ni][j] = 0.0f;

    // counter-based chunk indexing (no div/mod in the hot loop)
    auto load_chunk = [&](int tile, int kc, int s) {
        const uint32_t st = smbase + (uint32_t)s * STAGEB;
        const int k0 = kc * BK;
        const int row0 = rowbase + tile * BM;
#pragma unroll
        for (int j = 0; j < 8; ++j) {
            int idx = tid + 256 * j;
            int part = idx >> 10;
            int within = idx & 1023;
            int r = within >> 3;
            int q = within & 7;
            uint32_t dst = st + (uint32_t)part * PARTB + r * PITCHB + q * 16;
            const uint16_t* src;
            int sz = 16;
            if (part == 0) {
                src = A + (size_t)(row0 + r) * K + k0 + q * 8;
            } else {
                int n = col0 + r;
                if (n < Ncols) {
                    src = B + (size_t)n * K + k0 + q * 8;
                } else {
                    src = B;
                    sz = 0;
                }
            }
            asm volatile("cp.async.cg.shared.global [%0], [%1], 16, %2;"
                         :: "r"(dst), "l"(src), "r"(sz) : "memory");
        }
        asm volatile("cp.async.commit_group;" ::: "memory");
    };

    // load cursor
    int lt = 0, lk = 0;
    auto advance_load = [&]() {
        if (++lk == nchunk) { lk = 0; ++lt; }
    };
    load_chunk(lt, lk, 0); advance_load();
    if (total > 1) { load_chunk(lt, lk, 1); advance_load(); }

    int s = 0;
    int ct = 0, ck = 0;   // compute cursor
    for (int gc = 0; gc < total; ++gc) {
        if (gc + 1 < total) {
            asm volatile("cp.async.wait_group 1;" ::: "memory");
        } else {
            asm volatile("cp.async.wait_group 0;" ::: "memory");
        }
        __syncthreads();
        if (gc + 2 < total) {
            int s2 = s + 2 >= NSTAGE ? s + 2 - NSTAGE : s + 2;
            load_chunk(lt, lk, s2);
            advance_load();
        }

        const uint32_t st = smbase + (uint32_t)s * STAGEB;
        const uint32_t sA = st;
        const uint32_t sB = st + PARTB;

        uint32_t af[2][2][4];
        uint32_t bf[2][4];
#pragma unroll
        for (int mi = 0; mi < 2; ++mi)
            ldsm4(sA + (uint32_t)(wm * 32 + mi * 16) * PITCHB + aRowOff + aByte,
                  af[0][mi]);
        ldsm4(sB + (uint32_t)(wn * 64) * PITCHB + bRowOff + bByte, bf[0]);

#pragma unroll
        for (int kk = 0; kk < 4; ++kk) {
            const int cur = kk & 1;
            const int nxt = cur ^ 1;
            if (kk < 3) {
                const uint32_t kbn = (uint32_t)(kk + 1) * 32;
#pragma unroll
                for (int mi = 0; mi < 2; ++mi)
                    ldsm4(sA + (uint32_t)(wm * 32 + mi * 16) * PITCHB + aRowOff + kbn + aByte,
                          af[nxt][mi]);
            }
            const uint32_t kb = (uint32_t)kk * 32;
#pragma unroll
            for (int p = 0; p < 4; ++p) {
                const int pc = p & 1;
                const int pn = pc ^ 1;
                if (p < 3) {
                    ldsm4(sB + (uint32_t)(wn * 64 + (p + 1) * 16) * PITCHB + bRowOff + kb + bByte,
                          bf[pn]);
                } else if (kk < 3) {
                    ldsm4(sB + (uint32_t)(wn * 64) * PITCHB + bRowOff + kb + 32 + bByte,
                          bf[pn]);
                }
#pragma unroll
                for (int mi = 0; mi < 2; ++mi) {
                    mma_f16(acc[mi][2 * p],     af[cur][mi], bf[pc][0], bf[pc][1]);
                    mma_f16(acc[mi][2 * p + 1], af[cur][mi], bf[pc][2], bf[pc][3]);
                }
            }
        }

        // tile boundary: epilogue with next tile's loads already in flight
        if (++ck == nchunk) {
            const int row0 = rowbase + ct * BM;
            if (!aux) {
#pragma unroll
                for (int mi = 0; mi < 2; ++mi) {
                    int rb = row0 + wm * 32 + mi * 16 + g;
#pragma unroll
                    for (int ni = 0; ni < 8; ++ni) {
                        int cb = col0 + wn * 64 + ni * 8 + 2 * t;
                        *reinterpret_cast<float2*>(C + (size_t)rb * NS + cb) =
                            make_float2(acc[mi][ni][0], acc[mi][ni][1]);
                        *reinterpret_cast<float2*>(C + (size_t)(rb + 8) * NS + cb) =
                            make_float2(acc[mi][ni][2], acc[mi][ni][3]);
                    }
                }
            } else {
#pragma unroll
                for (int mi = 0; mi < 2; ++mi) {
                    int rb = row0 + wm * 32 + mi * 16 + g;
#pragma unroll
                    for (int ni = 0; ni < 8; ++ni) {
                        int cb = wn * 64 + ni * 8 + 2 * t;
                        if (cb >= CC) continue;
                        float b0 = bias2[cb];
                        float v0 = acc[mi][ni][0] + b0;
                        float v2 = acc[mi][ni][2] + b0;
                        C2[(size_t)rb * CC + cb] = v0;
                        C2[(size_t)(rb + 8) * CC + cb] = v2;
                        if (cb + 1 < CC) {
                            float b1 = bias2[cb + 1];
                            C2[(size_t)rb * CC + cb + 1] = acc[mi][ni][1] + b1;
                            C2[(size_t)(rb + 8) * CC + cb + 1] = acc[mi][ni][3] + b1;
                        }
                    }
                }
            }
            ck = 0;
            ++ct;
            if (gc + 1 < total) {
#pragma unroll
                for (int mi = 0; mi < 2; ++mi)
#pragma unroll
                    for (int ni = 0; ni < 8; ++ni)
#pragma unroll
                        for (int j = 0; j < 4; ++j) acc[mi][ni][j] = 0.0f;
            }
        }

        ++s;
        if (s == NSTAGE) s = 0;
    }
}

// ---------------- launch -------------------------------------------------------
extern "C" void kernel_launch(void* const* d_in, const int* in_sizes, int n_in,
                              void* d_out, int out_size) {
    const float* query   = (const float*)d_in[0];
    const float* support = (const float*)d_in[1];
    const float* head_W  = (const float*)d_in[2];
    const float* head_b  = (const float*)d_in[3];
    const float* cls_W   = (const float*)d_in[4];
    const float* cls_b   = (const float*)d_in[5];

    float* out_match = (float*)d_out;
    float* out_preds = (float*)d_out + (size_t)NQ * NS;

    uint16_t *X, *Wt, *Qn, *Sn;
    float *bias;
    cudaGetSymbolAddress((void**)&X,    g_X);
    cudaGetSymbolAddress((void**)&Wt,   g_Wt);
    cudaGetSymbolAddress((void**)&bias, g_bias);
    cudaGetSymbolAddress((void**)&Qn,   g_Qn);
    cudaGetSymbolAddress((void**)&Sn,   g_Sn);

    cudaFuncSetAttribute(proj_kernel,
                         cudaFuncAttributeMaxDynamicSharedMemorySize, PSMEM);
    cudaFuncSetAttribute(match_kernel,
                         cudaFuncAttributeMaxDynamicSharedMemorySize, SMEMB);

    // 1) fused setup: mean+convert X, pack W^T/bias
    {
        int n4tot = (NQ * DD + NS * DD) / 4;
        setup_kernel<<<(n4tot + 255) / 256, 256>>>(query, support,
                                                   head_W, head_b, cls_W, cls_b);
    }
    // 2) projection GEMM + fused per-head L2 normalize -> fp16 Qn/Sn
    {
        dim3 grid(HH, MTOTAL / PBM);       // (3, 48) = 144 CTAs, 1/SM, single wave
        proj_kernel<<<grid, 512, PSMEM>>>(X, Wt, bias, Qn, Sn);
    }
    // 3) match GEMM (2 M-tiles/CTA) + fused aux cls GEMM
    {
        dim3 grid(NS / BN, NQ / (2 * BM) + 1);   // (16, 17); last y-row = aux
        match_kernel<<<grid, 256, SMEMB>>>(Qn, Sn, out_match, 2,
                                           X + (size_t)NQ * DD, Wt + (size_t)NH * DD,
                                           bias + NH, out_preds, NS / BM);
    }
}

// round 16
// speedup vs baseline: 7.6936x; 1.0181x over previous
#include <cuda_runtime.h>
#include <cuda_fp16.h>
#include <cstdint>
#include <math.h>

// ---------------- problem constants ----------------------------------------
#define NQ     4096
#define DD     1024
#define NS     2048
#define HH     3
#define PP     256
#define CC     100
#define NH     768
#define NTOT   868
#define MTOTAL (NQ + NS)
#define EPSN   1e-8f

// ---------------- shared tiling constants ------------------------------------
#define BK     64
#define PITCHB 144               // 128 B data + 16 B pad (conflict-free)

// match kernel tiling (256 threads, 2 CTAs/SM)
#define BM     128
#define BN     128
#define PARTB  (BM * PITCHB)     // 18432
#define STAGEB (2 * PARTB)       // 36864
#define NSTAGE 3
#define SMEMB  (NSTAGE * STAGEB) // 110592

// proj kernel tiling (512 threads, 1 CTA/SM, full head per CTA)
#define PBM    128
#define PBN    256
#define PPARTA (PBM * PITCHB)            // 18432
#define PPARTB (PBN * PITCHB)            // 36864
#define PSTAGE (PPARTA + PPARTB)         // 55296
#define PSMEM  (NSTAGE * PSTAGE)         // 165888

// setup kernel block partition (derived, not hand-copied)
#define N4TOT  ((MTOTAL * DD) / 4)            // 1572864 float4 elements
#define NBX    ((N4TOT + 255) / 256)          // 6144 X-conversion blocks
#define NBWH   (HH * (DD / 32) * (PP / 32))   // 768 head transpose tiles
#define NBWC   ((DD / 32) * 4)                // 128 cls transpose tiles
#define NBTOT  (NBX + NBWH + NBWC)

// ---------------- scratch --------------------------------------------------
__device__ uint16_t g_X[MTOTAL * DD];    // fp16: rows 0..4095 mean(query), 4096.. support
__device__ uint16_t g_Wt[NTOT * DD];     // fp16 W^T (head rows 0..767, cls rows 768..867)
__device__ float    g_bias[NTOT];
__device__ uint16_t g_Qn[NQ * NH];       // fp16 normalized Q (x 1/H)
__device__ uint16_t g_Sn[NS * NH];       // fp16 normalized S

// ---------------- helpers ----------------------------------------------------
__device__ __forceinline__ uint32_t smem_u32_of(const void* p) {
    uint32_t a;
    asm("{ .reg .u64 t; cvta.to.shared.u64 t, %1; cvt.u32.u64 %0, t; }"
        : "=r"(a) : "l"(p));
    return a;
}

__device__ __forceinline__ void ldsm4(uint32_t addr, uint32_t* r) {
    asm volatile("ldmatrix.sync.aligned.m8n8.x4.shared.b16 {%0,%1,%2,%3}, [%4];"
                 : "=r"(r[0]), "=r"(r[1]), "=r"(r[2]), "=r"(r[3]) : "r"(addr));
}

__device__ __forceinline__ uint16_t tohalf(float x) {
    return __half_as_ushort(__float2half_rn(x));
}

__device__ __forceinline__ uint32_t packhalf2(float lo, float hi) {
    uint32_t r;
    asm("cvt.rn.f16x2.f32 %0, %1, %2;" : "=r"(r) : "f"(hi), "f"(lo));
    return r;
}

__device__ __forceinline__ void mma_f16(float* c, const uint32_t* a,
                                        uint32_t b0, uint32_t b1) {
    asm volatile(
        "mma.sync.aligned.m16n8k16.row.col.f32.f16.f16.f32 "
        "{%0,%1,%2,%3}, {%4,%5,%6,%7}, {%8,%9}, {%0,%1,%2,%3};"
        : "+f"(c[0]), "+f"(c[1]), "+f"(c[2]), "+f"(c[3])
        : "r"(a[0]), "r"(a[1]), "r"(a[2]), "r"(a[3]), "r"(b0), "r"(b1));
}

// ---------------- kernel 1: fused setup (coalesced weight transpose) ----------
__global__ void setup_kernel(const float* __restrict__ q,
                             const float* __restrict__ s,
                             const float* __restrict__ hW,
                             const float* __restrict__ hb,
                             const float* __restrict__ cW,
                             const float* __restrict__ cb) {
    __shared__ float tile[32][33];
    const int bid = blockIdx.x;
    const int tid = threadIdx.x;

    if (bid < NBX) {
        // ---- X conversion: mean(query) + support -> fp16 ----
        int i = bid * 256 + tid;
        const int n4q = (NQ * DD) / 4;
        if (i >= N4TOT) return;
        ushort4 hs;
        if (i < n4q) {
            const float4* p = reinterpret_cast<const float4*>(q);
            float4 a = p[i], b = p[i + n4q], c = p[i + 2 * n4q], d = p[i + 3 * n4q];
            hs.x = tohalf(0.25f * (a.x + b.x + c.x + d.x));
            hs.y = tohalf(0.25f * (a.y + b.y + c.y + d.y));
            hs.z = tohalf(0.25f * (a.z + b.z + c.z + d.z));
            hs.w = tohalf(0.25f * (a.w + b.w + c.w + d.w));
        } else {
            float4 v = reinterpret_cast<const float4*>(s)[i - n4q];
            hs.x = tohalf(v.x); hs.y = tohalf(v.y);
            hs.z = tohalf(v.z); hs.w = tohalf(v.w);
        }
        reinterpret_cast<ushort4*>(g_X)[i] = hs;
        return;
    }

    const int wb = bid - NBX;
    const int tx = tid & 31;
    const int ty = tid >> 5;        // 0..7

    if (wb == 0) {
        // bias pack (once, by the first weight block)
        for (int i = tid; i < NTOT; i += 256)
            g_bias[i] = (i < NH) ? hb[i] : cb[i - NH];
    }

    if (wb < NBWH) {
        // ---- head_W transpose tile: [32 k] x [32 p] ----
        const int h = wb >> 8;            // 256 tiles per head (32 k-tiles x 8 p-tiles)
        const int rem = wb & 255;
        const int k0 = (rem >> 3) * 32;
        const int p0 = (rem & 7) * 32;
#pragma unroll
        for (int j = 0; j < 4; ++j) {
            int k = k0 + ty + 8 * j;
            tile[ty + 8 * j][tx] = hW[((size_t)h * DD + k) * PP + p0 + tx];
        }
        __syncthreads();
#pragma unroll
        for (int j = 0; j < 4; ++j) {
            int p = p0 + ty + 8 * j;
            int n = h * PP + p;
            g_Wt[(size_t)n * DD + k0 + tx] = tohalf(tile[tx][ty + 8 * j]);
        }
    } else {
        // ---- cls_W transpose tile: [32 k] x [32 c] (c bounds-checked) ----
        const int wb2 = wb - NBWH;
        const int k0 = (wb2 >> 2) * 32;
        const int c0 = (wb2 & 3) * 32;
        const int c = c0 + tx;
#pragma unroll
        for (int j = 0; j < 4; ++j) {
            int k = k0 + ty + 8 * j;
            tile[ty + 8 * j][tx] = (c < CC) ? cW[(size_t)k * CC + c] : 0.0f;
        }
        __syncthreads();
#pragma unroll
        for (int j = 0; j < 4; ++j) {
            int cc = c0 + ty + 8 * j;
            if (cc < CC) {
                int n = NH + cc;
                g_Wt[(size_t)n * DD + k0 + tx] = tohalf(tile[tx][ty + 8 * j]);
            }
        }
    }
}

// ---------------- kernel 2: projection GEMM + fused L2 normalize --------------
__global__ void __launch_bounds__(512, 1)
proj_kernel(const uint16_t* __restrict__ A,
            const uint16_t* __restrict__ B,
            const float* __restrict__ bias,
            uint16_t* __restrict__ Qn, uint16_t* __restrict__ Sn) {
    extern __shared__ __align__(128) char smem[];
    const uint32_t smbase = smem_u32_of(smem);

    const int tid = threadIdx.x;
    const int lane = tid & 31;
    const int wid = tid >> 5;
    const int wm = wid >> 2;
    const int wn = wid & 3;
    const int g = lane >> 2;
    const int t = lane & 3;
    const int row0 = blockIdx.y * PBM;
    const int col0 = blockIdx.x * PBN;
    const int nchunk = DD / BK;

    float acc[2][8][4];
#pragma unroll
    for (int mi = 0; mi < 2; ++mi)
#pragma unroll
        for (int ni = 0; ni < 8; ++ni)
#pragma unroll
            for (int j = 0; j < 4; ++j) acc[mi][ni][j] = 0.0f;

    auto load_chunk = [&](int c, int s) {
        const uint32_t st = smbase + (uint32_t)s * PSTAGE;
        const int k0 = c * BK;
#pragma unroll
        for (int j = 0; j < 6; ++j) {
            int idx = tid + 512 * j;
            if (idx < 1024) {
                int r = idx >> 3;
                int qv = idx & 7;
                uint32_t dst = st + r * PITCHB + qv * 16;
                const uint16_t* src = A + (size_t)(row0 + r) * DD + k0 + qv * 8;
                asm volatile("cp.async.cg.shared.global [%0], [%1], 16;"
                             :: "r"(dst), "l"(src) : "memory");
            } else {
                int within = idx - 1024;
                int r = within >> 3;
                int qv = within & 7;
                uint32_t dst = st + PPARTA + r * PITCHB + qv * 16;
                const uint16_t* src = B + (size_t)(col0 + r) * DD + k0 + qv * 8;
                asm volatile("cp.async.cg.shared.global [%0], [%1], 16;"
                             :: "r"(dst), "l"(src) : "memory");
            }
        }
        asm volatile("cp.async.commit_group;" ::: "memory");
    };

    load_chunk(0, 0);
    load_chunk(1, 1);

    const uint32_t aRowOff = (uint32_t)(lane & 15) * PITCHB;
    const uint32_t aByte   = (uint32_t)((lane >> 4) << 4);
    const uint32_t bRowOff = (uint32_t)(((lane >> 4) & 1) * 8 + (lane & 7)) * PITCHB;
    const uint32_t bByte   = (uint32_t)(((lane >> 3) & 1) << 4);

    int s = 0;
    for (int c = 0; c < nchunk; ++c) {
        if (c + 1 < nchunk) {
            asm volatile("cp.async.wait_group 1;" ::: "memory");
        } else {
            asm volatile("cp.async.wait_group 0;" ::: "memory");
        }
        __syncthreads();
        if (c + 2 < nchunk) {
            int s2 = s + 2 >= NSTAGE ? s + 2 - NSTAGE : s + 2;
            load_chunk(c + 2, s2);
        }

        const uint32_t st = smbase + (uint32_t)s * PSTAGE;
        const uint32_t sA = st;
        const uint32_t sB = st + PPARTA;

        uint32_t af[2][2][4];
        uint32_t bf[2][4];
#pragma unroll
        for (int mi = 0; mi < 2; ++mi)
            ldsm4(sA + (uint32_t)(wm * 32 + mi * 16) * PITCHB + aRowOff + aByte,
                  af[0][mi]);
        ldsm4(sB + (uint32_t)(wn * 64) * PITCHB + bRowOff + bByte, bf[0]);

#pragma unroll
        for (int kk = 0; kk < 4; ++kk) {
            const int cur = kk & 1;
            const int nxt = cur ^ 1;
            if (kk < 3) {
                const uint32_t kbn = (uint32_t)(kk + 1) * 32;
#pragma unroll
                for (int mi = 0; mi < 2; ++mi)
                    ldsm4(sA + (uint32_t)(wm * 32 + mi * 16) * PITCHB + aRowOff + kbn + aByte,
                          af[nxt][mi]);
            }
            const uint32_t kb = (uint32_t)kk * 32;
#pragma unroll
            for (int p = 0; p < 4; ++p) {
                const int pc = p & 1;
                const int pn = pc ^ 1;
                if (p < 3) {
                    ldsm4(sB + (uint32_t)(wn * 64 + (p + 1) * 16) * PITCHB + bRowOff + kb + bByte,
                          bf[pn]);
                } else if (kk < 3) {
                    ldsm4(sB + (uint32_t)(wn * 64) * PITCHB + bRowOff + kb + 32 + bByte,
                          bf[pn]);
                }
#pragma unroll
                for (int mi = 0; mi < 2; ++mi) {
                    mma_f16(acc[mi][2 * p],     af[cur][mi], bf[pc][0], bf[pc][1]);
                    mma_f16(acc[mi][2 * p + 1], af[cur][mi], bf[pc][2], bf[pc][3]);
                }
            }
        }
        ++s;
        if (s == NSTAGE) s = 0;
    }

    // ---- fused epilogue: bias + per-row L2 norm over the full head ----
    __syncthreads();
    float* red = reinterpret_cast<float*>(smem);

#pragma unroll
    for (int mi = 0; mi < 2; ++mi) {
        int rl = wm * 32 + mi * 16 + g;
        float sq0 = 0.0f, sq1 = 0.0f;
#pragma unroll
        for (int ni = 0; ni < 8; ++ni) {
            int cl = wn * 64 + ni * 8 + 2 * t;
            float b0 = bias[col0 + cl];
            float b1 = bias[col0 + cl + 1];
            acc[mi][ni][0] += b0;
            acc[mi][ni][1] += b1;
            acc[mi][ni][2] += b0;
            acc[mi][ni][3] += b1;
            sq0 += acc[mi][ni][0] * acc[mi][ni][0] + acc[mi][ni][1] * acc[mi][ni][1];
            sq1 += acc[mi][ni][2] * acc[mi][ni][2] + acc[mi][ni][3] * acc[mi][ni][3];
        }
        sq0 += __shfl_xor_sync(0xffffffffu, sq0, 1);
        sq0 += __shfl_xor_sync(0xffffffffu, sq0, 2);
        sq1 += __shfl_xor_sync(0xffffffffu, sq1, 1);
        sq1 += __shfl_xor_sync(0xffffffffu, sq1, 2);
        if (t == 0) {
            red[rl * 4 + wn] = sq0;
            red[(rl + 8) * 4 + wn] = sq1;
        }
    }
    __syncthreads();

    const float extra = (row0 < NQ) ? (1.0f / (float)HH) : 1.0f;
#pragma unroll
    for (int mi = 0; mi < 2; ++mi) {
        int rl = wm * 32 + mi * 16 + g;
        float s0 = red[rl * 4] + red[rl * 4 + 1] + red[rl * 4 + 2] + red[rl * 4 + 3];
        float s1 = red[(rl + 8) * 4] + red[(rl + 8) * 4 + 1]
                 + red[(rl + 8) * 4 + 2] + red[(rl + 8) * 4 + 3];
        float sc0 = extra / fmaxf(sqrtf(s0), EPSN);
        float sc1 = extra / fmaxf(sqrtf(s1), EPSN);
        int gr0 = row0 + rl;
        int gr1 = gr0 + 8;
        uint16_t* d0 = (gr0 < NQ) ? (Qn + (size_t)gr0 * NH) : (Sn + (size_t)(gr0 - NQ) * NH);
        uint16_t* d1 = (gr1 < NQ) ? (Qn + (size_t)gr1 * NH) : (Sn + (size_t)(gr1 - NQ) * NH);
#pragma unroll
        for (int ni = 0; ni < 8; ++ni) {
            int cl = wn * 64 + ni * 8 + 2 * t;
            uint32_t p0 = packhalf2(acc[mi][ni][0] * sc0, acc[mi][ni][1] * sc0);
            uint32_t p1 = packhalf2(acc[mi][ni][2] * sc1, acc[mi][ni][3] * sc1);
            *reinterpret_cast<uint32_t*>(d0 + col0 + cl) = p0;
            *reinterpret_cast<uint32_t*>(d1 + col0 + cl) = p1;
        }
    }
}

// ---------------- kernel 3: match GEMM (flat 2 M-tiles) + aux cls GEMM --------
__global__ void __launch_bounds__(256, 2)
match_kernel(const uint16_t* __restrict__ A,
             const uint16_t* __restrict__ B,
             float* __restrict__ C,
             int mtiles,
             const uint16_t* __restrict__ A2,
             const uint16_t* __restrict__ B2,
             const float* __restrict__ bias2,
             float* __restrict__ C2, int aux_mtiles) {
    extern __shared__ __align__(128) char smem[];
    const uint32_t smbase = smem_u32_of(smem);

    int col0, rowbase, K, Ncols;
    const bool aux = ((int)blockIdx.y == (int)gridDim.y - 1);
    if (aux) {
        if ((int)blockIdx.x >= aux_mtiles) return;
        A = A2; B = B2; K = DD; Ncols = CC;
        mtiles = 1;
        col0 = 0;
        rowbase = (int)blockIdx.x * BM;
    } else {
        K = NH; Ncols = NS;
        col0 = blockIdx.x * BN;
        rowbase = (int)blockIdx.y * mtiles * BM;
    }

    const int tid = threadIdx.x;
    const int lane = tid & 31;
    const int wid = tid >> 5;
    const int wm = wid >> 1;
    const int wn = wid & 1;
    const int g = lane >> 2;
    const int t = lane & 3;
    const int nchunk = K / BK;
    const int total = mtiles * nchunk;

    const uint32_t aRowOff = (uint32_t)(lane & 15) * PITCHB;
    const uint32_t aByte   = (uint32_t)((lane >> 4) << 4);
    const uint32_t bRowOff = (uint32_t)(((lane >> 4) & 1) * 8 + (lane & 7)) * PITCHB;
    const uint32_t bByte   = (uint32_t)(((lane >> 3) & 1) << 4);

    float acc[2][8][4];
#pragma unroll
    for (int mi = 0; mi < 2; ++mi)
#pragma unroll
        for (int ni = 0; ni < 8; ++ni)
#pragma unroll
            for (int j = 0; j < 4; ++j) acc[mi][ni][j] = 0.0f;

    auto load_chunk = [&](int tile, int kc, int s) {
        const uint32_t st = smbase + (uint32_t)s * STAGEB;
        const int k0 = kc * BK;
        const int row0 = rowbase + tile * BM;
#pragma unroll
        for (int j = 0; j < 8; ++j) {
            int idx = tid + 256 * j;
            int part = idx >> 10;
            int within = idx & 1023;
            int r = within >> 3;
            int qv = within & 7;
            uint32_t dst = st + (uint32_t)part * PARTB + r * PITCHB + qv * 16;
            const uint16_t* src;
            int sz = 16;
            if (part == 0) {
                src = A + (size_t)(row0 + r) * K + k0 + qv * 8;
            } else {
                int n = col0 + r;
                if (n < Ncols) {
                    src = B + (size_t)n * K + k0 + qv * 8;
                } else {
                    src = B;
                    sz = 0;
                }
            }
            asm volatile("cp.async.cg.shared.global [%0], [%1], 16, %2;"
                         :: "r"(dst), "l"(src), "r"(sz) : "memory");
        }
        asm volatile("cp.async.commit_group;" ::: "memory");
    };

    int lt = 0, lk = 0;
    auto advance_load = [&]() {
        if (++lk == nchunk) { lk = 0; ++lt; }
    };
    load_chunk(lt, lk, 0); advance_load();
    if (total > 1) { load_chunk(lt, lk, 1); advance_load(); }

    int s = 0;
    int ct = 0, ck = 0;
    for (int gc = 0; gc < total; ++gc) {
        if (gc + 1 < total) {
            asm volatile("cp.async.wait_group 1;" ::: "memory");
        } else {
            asm volatile("cp.async.wait_group 0;" ::: "memory");
        }
        __syncthreads();
        if (gc + 2 < total) {
            int s2 = s + 2 >= NSTAGE ? s + 2 - NSTAGE : s + 2;
            load_chunk(lt, lk, s2);
            advance_load();
        }

        const uint32_t st = smbase + (uint32_t)s * STAGEB;
        const uint32_t sA = st;
        const uint32_t sB = st + PARTB;

        uint32_t af[2][2][4];
        uint32_t bf[2][4];
#pragma unroll
        for (int mi = 0; mi < 2; ++mi)
            ldsm4(sA + (uint32_t)(wm * 32 + mi * 16) * PITCHB + aRowOff + aByte,
                  af[0][mi]);
        ldsm4(sB + (uint32_t)(wn * 64) * PITCHB + bRowOff + bByte, bf[0]);

#pragma unroll
        for (int kk = 0; kk < 4; ++kk) {
            const int cur = kk & 1;
            const int nxt = cur ^ 1;
            if (kk < 3) {
                const uint32_t kbn = (uint32_t)(kk + 1) * 32;
#pragma unroll
                for (int mi = 0; mi < 2; ++mi)
                    ldsm4(sA + (uint32_t)(wm * 32 + mi * 16) * PITCHB + aRowOff + kbn + aByte,
                          af[nxt][mi]);
            }
            const uint32_t kb = (uint32_t)kk * 32;
#pragma unroll
            for (int p = 0; p < 4; ++p) {
                const int pc = p & 1;
                const int pn = pc ^ 1;
                if (p < 3) {
                    ldsm4(sB + (uint32_t)(wn * 64 + (p + 1) * 16) * PITCHB + bRowOff + kb + bByte,
                          bf[pn]);
                } else if (kk < 3) {
                    ldsm4(sB + (uint32_t)(wn * 64) * PITCHB + bRowOff + kb + 32 + bByte,
                          bf[pn]);
                }
#pragma unroll
                for (int mi = 0; mi < 2; ++mi) {
                    mma_f16(acc[mi][2 * p],     af[cur][mi], bf[pc][0], bf[pc][1]);
                    mma_f16(acc[mi][2 * p + 1], af[cur][mi], bf[pc][2], bf[pc][3]);
                }
            }
        }

        if (++ck == nchunk) {
            const int row0 = rowbase + ct * BM;
            if (!aux) {
#pragma unroll
                for (int mi = 0; mi < 2; ++mi) {
                    int rb = row0 + wm * 32 + mi * 16 + g;
#pragma unroll
                    for (int ni = 0; ni < 8; ++ni) {
                        int cb = col0 + wn * 64 + ni * 8 + 2 * t;
                        *reinterpret_cast<float2*>(C + (size_t)rb * NS + cb) =
                            make_float2(acc[mi][ni][0], acc[mi][ni][1]);
                        *reinterpret_cast<float2*>(C + (size_t)(rb + 8) * NS + cb) =
                            make_float2(acc[mi][ni][2], acc[mi][ni][3]);
                    }
                }
            } else {
#pragma unroll
                for (int mi = 0; mi < 2; ++mi) {
                    int rb = row0 + wm * 32 + mi * 16 + g;
#pragma unroll
                    for (int ni = 0; ni < 8; ++ni) {
                        int cb = wn * 64 + ni * 8 + 2 * t;
                        if (cb >= CC) continue;
                        float b0 = bias2[cb];
                        C2[(size_t)rb * CC + cb] = acc[mi][ni][0] + b0;
                        C2[(size_t)(rb + 8) * CC + cb] = acc[mi][ni][2] + b0;
                        if (cb + 1 < CC) {
                            float b1 = bias2[cb + 1];
                            C2[(size_t)rb * CC + cb + 1] = acc[mi][ni][1] + b1;
                            C2[(size_t)(rb + 8) * CC + cb + 1] = acc[mi][ni][3] + b1;
                        }
                    }
                }
            }
            ck = 0;
            ++ct;
            if (gc + 1 < total) {
#pragma unroll
                for (int mi = 0; mi < 2; ++mi)
#pragma unroll
                    for (int ni = 0; ni < 8; ++ni)
#pragma unroll
                        for (int j = 0; j < 4; ++j) acc[mi][ni][j] = 0.0f;
            }
        }

        ++s;
        if (s == NSTAGE) s = 0;
    }
}

// ---------------- launch -------------------------------------------------------
extern "C" void kernel_launch(void* const* d_in, const int* in_sizes, int n_in,
                              void* d_out, int out_size) {
    const float* query   = (const float*)d_in[0];
    const float* support = (const float*)d_in[1];
    const float* head_W  = (const float*)d_in[2];
    const float* head_b  = (const float*)d_in[3];
    const float* cls_W   = (const float*)d_in[4];
    const float* cls_b   = (const float*)d_in[5];

    float* out_match = (float*)d_out;
    float* out_preds = (float*)d_out + (size_t)NQ * NS;

    uint16_t *X, *Wt, *Qn, *Sn;
    float *bias;
    cudaGetSymbolAddress((void**)&X,    g_X);
    cudaGetSymbolAddress((void**)&Wt,   g_Wt);
    cudaGetSymbolAddress((void**)&bias, g_bias);
    cudaGetSymbolAddress((void**)&Qn,   g_Qn);
    cudaGetSymbolAddress((void**)&Sn,   g_Sn);

    cudaFuncSetAttribute(proj_kernel,
                         cudaFuncAttributeMaxDynamicSharedMemorySize, PSMEM);
    cudaFuncSetAttribute(match_kernel,
                         cudaFuncAttributeMaxDynamicSharedMemorySize, SMEMB);

    // 1) fused setup: X convert + tiled weight transpose + bias
    setup_kernel<<<NBTOT, 256>>>(query, support, head_W, head_b, cls_W, cls_b);

    // 2) projection GEMM + fused per-head L2 normalize -> fp16 Qn/Sn
    {
        dim3 grid(HH, MTOTAL / PBM);       // (3, 48) = 144 CTAs
        proj_kernel<<<grid, 512, PSMEM>>>(X, Wt, bias, Qn, Sn);
    }
    // 3) match GEMM (2 M-tiles/CTA) + fused aux cls GEMM
    {
        dim3 grid(NS / BN, NQ / (2 * BM) + 1);   // (16, 17); last y-row = aux
        match_kernel<<<grid, 256, SMEMB>>>(Qn, Sn, out_match, 2,
                                           X + (size_t)NQ * DD, Wt + (size_t)NH * DD,
                                           bias + NH, out_preds, NS / BM);
    }
}

// round 17
// speedup vs baseline: 7.6985x; 1.0006x over previous
#include <cuda_runtime.h>
#include <cuda_fp16.h>
#include <cstdint>
#include <math.h>

// ---------------- problem constants ----------------------------------------
#define NQ     4096
#define DD     1024
#define NS     2048
#define HH     3
#define PP     256
#define CC     100
#define NH     768
#define NTOT   868
#define MTOTAL (NQ + NS)
#define EPSN   1e-8f

// ---------------- shared tiling constants ------------------------------------
#define BK     64
#define PITCHB 144               // 128 B data + 16 B pad (conflict-free)

// match kernel tiling (256 threads, 2 CTAs/SM)
#define BM     128
#define BN     128
#define PARTB  (BM * PITCHB)     // 18432
#define STAGEB (2 * PARTB)       // 36864
#define NSTAGE 3
#define SMEMB  (NSTAGE * STAGEB) // 110592

// proj kernel tiling (512 threads, 1 CTA/SM, full head per CTA)
#define PBM    128
#define PBN    256
#define PPARTA (PBM * PITCHB)            // 18432
#define PPARTB (PBN * PITCHB)            // 36864
#define PSTAGE (PPARTA + PPARTB)         // 55296
#define PSMEM  (NSTAGE * PSTAGE)         // 165888

// setup kernel block partition (derived)
#define N4TOT  ((MTOTAL * DD) / 4)            // 1572864 float4 elements
#define N4HALF (N4TOT / 2)                    // 786432
#define NBX    ((N4HALF + 255) / 256)         // 3072 X blocks (2 elems/thread)
#define NBWH   (HH * (DD / 32) * (PP / 32))   // 768 head transpose tiles
#define NBWC   ((DD / 32) * 4)                // 128 cls transpose tiles
#define NBTOT  (NBX + NBWH + NBWC)

// ---------------- scratch --------------------------------------------------
__device__ uint16_t g_X[MTOTAL * DD];    // fp16: rows 0..4095 mean(query), 4096.. support
__device__ uint16_t g_Wt[NTOT * DD];     // fp16 W^T (head rows 0..767, cls rows 768..867)
__device__ float    g_bias[NTOT];
__device__ uint16_t g_Qn[NQ * NH];       // fp16 normalized Q (x 1/H)
__device__ uint16_t g_Sn[NS * NH];       // fp16 normalized S

// ---------------- helpers ----------------------------------------------------
__device__ __forceinline__ uint32_t smem_u32_of(const void* p) {
    uint32_t a;
    asm("{ .reg .u64 t; cvta.to.shared.u64 t, %1; cvt.u32.u64 %0, t; }"
        : "=r"(a) : "l"(p));
    return a;
}

__device__ __forceinline__ void ldsm4(uint32_t addr, uint32_t* r) {
    asm volatile("ldmatrix.sync.aligned.m8n8.x4.shared.b16 {%0,%1,%2,%3}, [%4];"
                 : "=r"(r[0]), "=r"(r[1]), "=r"(r[2]), "=r"(r[3]) : "r"(addr));
}

__device__ __forceinline__ uint16_t tohalf(float x) {
    return __half_as_ushort(__float2half_rn(x));
}

__device__ __forceinline__ uint32_t packhalf2(float lo, float hi) {
    uint32_t r;
    asm("cvt.rn.f16x2.f32 %0, %1, %2;" : "=r"(r) : "f"(hi), "f"(lo));
    return r;
}

__device__ __forceinline__ void mma_f16(float* c, const uint32_t* a,
                                        uint32_t b0, uint32_t b1) {
    asm volatile(
        "mma.sync.aligned.m16n8k16.row.col.f32.f16.f16.f32 "
        "{%0,%1,%2,%3}, {%4,%5,%6,%7}, {%8,%9}, {%0,%1,%2,%3};"
        : "+f"(c[0]), "+f"(c[1]), "+f"(c[2]), "+f"(c[3])
        : "r"(a[0]), "r"(a[1]), "r"(a[2]), "r"(a[3]), "r"(b0), "r"(b1));
}

// ---------------- kernel 1: fused setup ---------------------------------------
__global__ void setup_kernel(const float* __restrict__ q,
                             const float* __restrict__ s,
                             const float* __restrict__ hW,
                             const float* __restrict__ hb,
                             const float* __restrict__ cW,
                             const float* __restrict__ cb) {
    __shared__ float tile[32][33];
    const int bid = blockIdx.x;
    const int tid = threadIdx.x;

    if (bid < NBX) {
        // ---- X conversion: 2 independent float4 elements per thread ----
        const int n4q = (NQ * DD) / 4;
        const float4* qp = reinterpret_cast<const float4*>(q);
        const float4* sp = reinterpret_cast<const float4*>(s);
        int i0 = bid * 256 + tid;
        float4 v[2][4];
        int idx[2] = { i0, i0 + N4HALF };
        bool isq[2];
#pragma unroll
        for (int u = 0; u < 2; ++u) {
            int i = idx[u];
            isq[u] = (i < n4q);
            if (isq[u]) {
                v[u][0] = qp[i];
                v[u][1] = qp[i + n4q];
                v[u][2] = qp[i + 2 * n4q];
                v[u][3] = qp[i + 3 * n4q];
            } else {
                v[u][0] = sp[i - n4q];
            }
        }
#pragma unroll
        for (int u = 0; u < 2; ++u) {
            ushort4 hs;
            if (isq[u]) {
                hs.x = tohalf(0.25f * (v[u][0].x + v[u][1].x + v[u][2].x + v[u][3].x));
                hs.y = tohalf(0.25f * (v[u][0].y + v[u][1].y + v[u][2].y + v[u][3].y));
                hs.z = tohalf(0.25f * (v[u][0].z + v[u][1].z + v[u][2].z + v[u][3].z));
                hs.w = tohalf(0.25f * (v[u][0].w + v[u][1].w + v[u][2].w + v[u][3].w));
            } else {
                hs.x = tohalf(v[u][0].x); hs.y = tohalf(v[u][0].y);
                hs.z = tohalf(v[u][0].z); hs.w = tohalf(v[u][0].w);
            }
            reinterpret_cast<ushort4*>(g_X)[idx[u]] = hs;
        }
        return;
    }

    const int wb = bid - NBX;
    const int tx = tid & 31;
    const int ty = tid >> 5;        // 0..7

    if (wb == 0) {
        for (int i = tid; i < NTOT; i += 256)
            g_bias[i] = (i < NH) ? hb[i] : cb[i - NH];
    }

    if (wb < NBWH) {
        // ---- head_W transpose tile: [32 k] x [32 p] ----
        const int h = wb >> 8;
        const int rem = wb & 255;
        const int k0 = (rem >> 3) * 32;
        const int p0 = (rem & 7) * 32;
#pragma unroll
        for (int j = 0; j < 4; ++j) {
            int k = k0 + ty + 8 * j;
            tile[ty + 8 * j][tx] = hW[((size_t)h * DD + k) * PP + p0 + tx];
        }
        __syncthreads();
#pragma unroll
        for (int j = 0; j < 4; ++j) {
            int p = p0 + ty + 8 * j;
            int n = h * PP + p;
            g_Wt[(size_t)n * DD + k0 + tx] = tohalf(tile[tx][ty + 8 * j]);
        }
    } else {
        // ---- cls_W transpose tile ----
        const int wb2 = wb - NBWH;
        const int k0 = (wb2 >> 2) * 32;
        const int c0 = (wb2 & 3) * 32;
        const int c = c0 + tx;
#pragma unroll
        for (int j = 0; j < 4; ++j) {
            int k = k0 + ty + 8 * j;
            tile[ty + 8 * j][tx] = (c < CC) ? cW[(size_t)k * CC + c] : 0.0f;
        }
        __syncthreads();
#pragma unroll
        for (int j = 0; j < 4; ++j) {
            int cc = c0 + ty + 8 * j;
            if (cc < CC) {
                int n = NH + cc;
                g_Wt[(size_t)n * DD + k0 + tx] = tohalf(tile[tx][ty + 8 * j]);
            }
        }
    }
}

// ---------------- kernel 2: projection GEMM + fused L2 normalize --------------
__global__ void __launch_bounds__(512, 1)
proj_kernel(const uint16_t* __restrict__ A,
            const uint16_t* __restrict__ B,
            const float* __restrict__ bias,
            uint16_t* __restrict__ Qn, uint16_t* __restrict__ Sn) {
    extern __shared__ __align__(128) char smem[];
    const uint32_t smbase = smem_u32_of(smem);

    const int tid = threadIdx.x;
    const int lane = tid & 31;
    const int wid = tid >> 5;
    const int wm = wid >> 2;
    const int wn = wid & 3;
    const int g = lane >> 2;
    const int t = lane & 3;
    const int row0 = blockIdx.y * PBM;
    const int col0 = blockIdx.x * PBN;
    const int nchunk = DD / BK;

    float acc[2][8][4];
#pragma unroll
    for (int mi = 0; mi < 2; ++mi)
#pragma unroll
        for (int ni = 0; ni < 8; ++ni)
#pragma unroll
            for (int j = 0; j < 4; ++j) acc[mi][ni][j] = 0.0f;

    auto load_chunk = [&](int c, int s) {
        const uint32_t st = smbase + (uint32_t)s * PSTAGE;
        const int k0 = c * BK;
#pragma unroll
        for (int j = 0; j < 6; ++j) {
            int idx = tid + 512 * j;
            if (idx < 1024) {
                int r = idx >> 3;
                int qv = idx & 7;
                uint32_t dst = st + r * PITCHB + qv * 16;
                const uint16_t* src = A + (size_t)(row0 + r) * DD + k0 + qv * 8;
                asm volatile("cp.async.cg.shared.global [%0], [%1], 16;"
                             :: "r"(dst), "l"(src) : "memory");
            } else {
                int within = idx - 1024;
                int r = within >> 3;
                int qv = within & 7;
                uint32_t dst = st + PPARTA + r * PITCHB + qv * 16;
                const uint16_t* src = B + (size_t)(col0 + r) * DD + k0 + qv * 8;
                asm volatile("cp.async.cg.shared.global [%0], [%1], 16;"
                             :: "r"(dst), "l"(src) : "memory");
            }
        }
        asm volatile("cp.async.commit_group;" ::: "memory");
    };

    load_chunk(0, 0);
    load_chunk(1, 1);

    const uint32_t aRowOff = (uint32_t)(lane & 15) * PITCHB;
    const uint32_t aByte   = (uint32_t)((lane >> 4) << 4);
    const uint32_t bRowOff = (uint32_t)(((lane >> 4) & 1) * 8 + (lane & 7)) * PITCHB;
    const uint32_t bByte   = (uint32_t)(((lane >> 3) & 1) << 4);

    int s = 0;
    for (int c = 0; c < nchunk; ++c) {
        if (c + 1 < nchunk) {
            asm volatile("cp.async.wait_group 1;" ::: "memory");
        } else {
            asm volatile("cp.async.wait_group 0;" ::: "memory");
        }
        __syncthreads();
        if (c + 2 < nchunk) {
            int s2 = s + 2 >= NSTAGE ? s + 2 - NSTAGE : s + 2;
            load_chunk(c + 2, s2);
        }

        const uint32_t st = smbase + (uint32_t)s * PSTAGE;
        const uint32_t sA = st;
        const uint32_t sB = st + PPARTA;

        uint32_t af[2][2][4];
        uint32_t bf[2][4];
#pragma unroll
        for (int mi = 0; mi < 2; ++mi)
            ldsm4(sA + (uint32_t)(wm * 32 + mi * 16) * PITCHB + aRowOff + aByte,
                  af[0][mi]);
        ldsm4(sB + (uint32_t)(wn * 64) * PITCHB + bRowOff + bByte, bf[0]);

#pragma unroll
        for (int kk = 0; kk < 4; ++kk) {
            const int cur = kk & 1;
            const int nxt = cur ^ 1;
            if (kk < 3) {
                const uint32_t kbn = (uint32_t)(kk + 1) * 32;
#pragma unroll
                for (int mi = 0; mi < 2; ++mi)
                    ldsm4(sA + (uint32_t)(wm * 32 + mi * 16) * PITCHB + aRowOff + kbn + aByte,
                          af[nxt][mi]);
            }
            const uint32_t kb = (uint32_t)kk * 32;
#pragma unroll
            for (int p = 0; p < 4; ++p) {
                const int pc = p & 1;
                const int pn = pc ^ 1;
                if (p < 3) {
                    ldsm4(sB + (uint32_t)(wn * 64 + (p + 1) * 16) * PITCHB + bRowOff + kb + bByte,
                          bf[pn]);
                } else if (kk < 3) {
                    ldsm4(sB + (uint32_t)(wn * 64) * PITCHB + bRowOff + kb + 32 + bByte,
                          bf[pn]);
                }
#pragma unroll
                for (int mi = 0; mi < 2; ++mi) {
                    mma_f16(acc[mi][2 * p],     af[cur][mi], bf[pc][0], bf[pc][1]);
                    mma_f16(acc[mi][2 * p + 1], af[cur][mi], bf[pc][2], bf[pc][3]);
                }
            }
        }
        ++s;
        if (s == NSTAGE) s = 0;
    }

    // ---- fused epilogue: bias + per-row L2 norm over the full head ----
    __syncthreads();
    float* red = reinterpret_cast<float*>(smem);

#pragma unroll
    for (int mi = 0; mi < 2; ++mi) {
        int rl = wm * 32 + mi * 16 + g;
        float sq0 = 0.0f, sq1 = 0.0f;
#pragma unroll
        for (int ni = 0; ni < 8; ++ni) {
            int cl = wn * 64 + ni * 8 + 2 * t;
            float b0 = bias[col0 + cl];
            float b1 = bias[col0 + cl + 1];
            acc[mi][ni][0] += b0;
            acc[mi][ni][1] += b1;
            acc[mi][ni][2] += b0;
            acc[mi][ni][3] += b1;
            sq0 += acc[mi][ni][0] * acc[mi][ni][0] + acc[mi][ni][1] * acc[mi][ni][1];
            sq1 += acc[mi][ni][2] * acc[mi][ni][2] + acc[mi][ni][3] * acc[mi][ni][3];
        }
        sq0 += __shfl_xor_sync(0xffffffffu, sq0, 1);
        sq0 += __shfl_xor_sync(0xffffffffu, sq0, 2);
        sq1 += __shfl_xor_sync(0xffffffffu, sq1, 1);
        sq1 += __shfl_xor_sync(0xffffffffu, sq1, 2);
        if (t == 0) {
            red[rl * 4 + wn] = sq0;
            red[(rl + 8) * 4 + wn] = sq1;
        }
    }
    __syncthreads();

    const float extra = (row0 < NQ) ? (1.0f / (float)HH) : 1.0f;
#pragma unroll
    for (int mi = 0; mi < 2; ++mi) {
        int rl = wm * 32 + mi * 16 + g;
        float s0 = red[rl * 4] + red[rl * 4 + 1] + red[rl * 4 + 2] + red[rl * 4 + 3];
        float s1 = red[(rl + 8) * 4] + red[(rl + 8) * 4 + 1]
                 + red[(rl + 8) * 4 + 2] + red[(rl + 8) * 4 + 3];
        float sc0 = extra / fmaxf(sqrtf(s0), EPSN);
        float sc1 = extra / fmaxf(sqrtf(s1), EPSN);
        int gr0 = row0 + rl;
        int gr1 = gr0 + 8;
        uint16_t* d0 = (gr0 < NQ) ? (Qn + (size_t)gr0 * NH) : (Sn + (size_t)(gr0 - NQ) * NH);
        uint16_t* d1 = (gr1 < NQ) ? (Qn + (size_t)gr1 * NH) : (Sn + (size_t)(gr1 - NQ) * NH);
#pragma unroll
        for (int ni = 0; ni < 8; ++ni) {
            int cl = wn * 64 + ni * 8 + 2 * t;
            uint32_t p0 = packhalf2(acc[mi][ni][0] * sc0, acc[mi][ni][1] * sc0);
            uint32_t p1 = packhalf2(acc[mi][ni][2] * sc1, acc[mi][ni][3] * sc1);
            *reinterpret_cast<uint32_t*>(d0 + col0 + cl) = p0;
            *reinterpret_cast<uint32_t*>(d1 + col0 + cl) = p1;
        }
    }
}

// ---------------- kernel 3: match GEMM (flat 2 M-tiles) + aux cls GEMM --------
__global__ void __launch_bounds__(256, 2)
match_kernel(const uint16_t* __restrict__ A,
             const uint16_t* __restrict__ B,
             float* __restrict__ C,
             int mtiles,
             const uint16_t* __restrict__ A2,
             const uint16_t* __restrict__ B2,
             const float* __restrict__ bias2,
             float* __restrict__ C2, int aux_mtiles) {
    extern __shared__ __align__(128) char smem[];
    const uint32_t smbase = smem_u32_of(smem);

    int col0, rowbase, K, Ncols;
    const bool aux = ((int)blockIdx.y == (int)gridDim.y - 1);
    if (aux) {
        if ((int)blockIdx.x >= aux_mtiles) return;
        A = A2; B = B2; K = DD; Ncols = CC;
        mtiles = 1;
        col0 = 0;
        rowbase = (int)blockIdx.x * BM;
    } else {
        K = NH; Ncols = NS;
        col0 = blockIdx.x * BN;
        rowbase = (int)blockIdx.y * mtiles * BM;
    }

    const int tid = threadIdx.x;
    const int lane = tid & 31;
    const int wid = tid >> 5;
    const int wm = wid >> 1;
    const int wn = wid & 1;
    const int g = lane >> 2;
    const int t = lane & 3;
    const int nchunk = K / BK;
    const int total = mtiles * nchunk;

    const uint32_t aRowOff = (uint32_t)(lane & 15) * PITCHB;
    const uint32_t aByte   = (uint32_t)((lane >> 4) << 4);
    const uint32_t bRowOff = (uint32_t)(((lane >> 4) & 1) * 8 + (lane & 7)) * PITCHB;
    const uint32_t bByte   = (uint32_t)(((lane >> 3) & 1) << 4);

    float acc[2][8][4];
#pragma unroll
    for (int mi = 0; mi < 2; ++mi)
#pragma unroll
        for (int ni = 0; ni < 8; ++ni)
#pragma unroll
            for (int j = 0; j < 4; ++j) acc[mi][ni][j] = 0.0f;

    auto load_chunk = [&](int tile, int kc, int s) {
        const uint32_t st = smbase + (uint32_t)s * STAGEB;
        const int k0 = kc * BK;
        const int row0 = rowbase + tile * BM;
#pragma unroll
        for (int j = 0; j < 8; ++j) {
            int idx = tid + 256 * j;
            int part = idx >> 10;
            int within = idx & 1023;
            int r = within >> 3;
            int qv = within & 7;
            uint32_t dst = st + (uint32_t)part * PARTB + r * PITCHB + qv * 16;
            const uint16_t* src;
            int sz = 16;
            if (part == 0) {
                src = A + (size_t)(row0 + r) * K + k0 + qv * 8;
            } else {
                int n = col0 + r;
                if (n < Ncols) {
                    src = B + (size_t)n * K + k0 + qv * 8;
                } else {
                    src = B;
                    sz = 0;
                }
            }
            asm volatile("cp.async.cg.shared.global [%0], [%1], 16, %2;"
                         :: "r"(dst), "l"(src), "r"(sz) : "memory");
        }
        asm volatile("cp.async.commit_group;" ::: "memory");
    };

    int lt = 0, lk = 0;
    auto advance_load = [&]() {
        if (++lk == nchunk) { lk = 0; ++lt; }
    };
    load_chunk(lt, lk, 0); advance_load();
    if (total > 1) { load_chunk(lt, lk, 1); advance_load(); }

    int s = 0;
    int ct = 0, ck = 0;
    for (int gc = 0; gc < total; ++gc) {
        if (gc + 1 < total) {
            asm volatile("cp.async.wait_group 1;" ::: "memory");
        } else {
            asm volatile("cp.async.wait_group 0;" ::: "memory");
        }
        __syncthreads();
        if (gc + 2 < total) {
            int s2 = s + 2 >= NSTAGE ? s + 2 - NSTAGE : s + 2;
            load_chunk(lt, lk, s2);
            advance_load();
        }

        const uint32_t st = smbase + (uint32_t)s * STAGEB;
        const uint32_t sA = st;
        const uint32_t sB = st + PARTB;

        uint32_t af[2][2][4];
        uint32_t bf[2][4];
#pragma unroll
        for (int mi = 0; mi < 2; ++mi)
            ldsm4(sA + (uint32_t)(wm * 32 + mi * 16) * PITCHB + aRowOff + aByte,
                  af[0][mi]);
        ldsm4(sB + (uint32_t)(wn * 64) * PITCHB + bRowOff + bByte, bf[0]);

#pragma unroll
        for (int kk = 0; kk < 4; ++kk) {
            const int cur = kk & 1;
            const int nxt = cur ^ 1;
            if (kk < 3) {
                const uint32_t kbn = (uint32_t)(kk + 1) * 32;
#pragma unroll
                for (int mi = 0; mi < 2; ++mi)
                    ldsm4(sA + (uint32_t)(wm * 32 + mi * 16) * PITCHB + aRowOff + kbn + aByte,
                          af[nxt][mi]);
            }
            const uint32_t kb = (uint32_t)kk * 32;
#pragma unroll
            for (int p = 0; p < 4; ++p) {
                const int pc = p & 1;
                const int pn = pc ^ 1;
                if (p < 3) {
                    ldsm4(sB + (uint32_t)(wn * 64 + (p + 1) * 16) * PITCHB + bRowOff + kb + bByte,
                          bf[pn]);
                } else if (kk < 3) {
                    ldsm4(sB + (uint32_t)(wn * 64) * PITCHB + bRowOff + kb + 32 + bByte,
                          bf[pn]);
                }
#pragma unroll
                for (int mi = 0; mi < 2; ++mi) {
                    mma_f16(acc[mi][2 * p],     af[cur][mi], bf[pc][0], bf[pc][1]);
                    mma_f16(acc[mi][2 * p + 1], af[cur][mi], bf[pc][2], bf[pc][3]);
                }
            }
        }

        if (++ck == nchunk) {
            const int row0 = rowbase + ct * BM;
            if (!aux) {
#pragma unroll
                for (int mi = 0; mi < 2; ++mi) {
                    int rb = row0 + wm * 32 + mi * 16 + g;
#pragma unroll
                    for (int ni = 0; ni < 8; ++ni) {
                        int cb = col0 + wn * 64 + ni * 8 + 2 * t;
                        *reinterpret_cast<float2*>(C + (size_t)rb * NS + cb) =
                            make_float2(acc[mi][ni][0], acc[mi][ni][1]);
                        *reinterpret_cast<float2*>(C + (size_t)(rb + 8) * NS + cb) =
                            make_float2(acc[mi][ni][2], acc[mi][ni][3]);
                    }
                }
            } else {
#pragma unroll
                for (int mi = 0; mi < 2; ++mi) {
                    int rb = row0 + wm * 32 + mi * 16 + g;
#pragma unroll
                    for (int ni = 0; ni < 8; ++ni) {
                        int cb = wn * 64 + ni * 8 + 2 * t;
                        if (cb >= CC) continue;
                        float b0 = bias2[cb];
                        C2[(size_t)rb * CC + cb] = acc[mi][ni][0] + b0;
                        C2[(size_t)(rb + 8) * CC + cb] = acc[mi][ni][2] + b0;
                        if (cb + 1 < CC) {
                            float b1 = bias2[cb + 1];
                            C2[(size_t)rb * CC + cb + 1] = acc[mi][ni][1] + b1;
                            C2[(size_t)(rb + 8) * CC + cb + 1] = acc[mi][ni][3] + b1;
                        }
                    }
                }
            }
            ck = 0;
            ++ct;
            if (gc + 1 < total) {
#pragma unroll
                for (int mi = 0; mi < 2; ++mi)
#pragma unroll
                    for (int ni = 0; ni < 8; ++ni)
#pragma unroll
                        for (int j = 0; j < 4; ++j) acc[mi][ni][j] = 0.0f;
            }
        }

        ++s;
        if (s == NSTAGE) s = 0;
    }
}

// ---------------- launch -------------------------------------------------------
extern "C" void kernel_launch(void* const* d_in, const int* in_sizes, int n_in,
                              void* d_out, int out_size) {
    const float* query   = (const float*)d_in[0];
    const float* support = (const float*)d_in[1];
    const float* head_W  = (const float*)d_in[2];
    const float* head_b  = (const float*)d_in[3];
    const float* cls_W   = (const float*)d_in[4];
    const float* cls_b   = (const float*)d_in[5];

    float* out_match = (float*)d_out;
    float* out_preds = (float*)d_out + (size_t)NQ * NS;

    uint16_t *X, *Wt, *Qn, *Sn;
    float *bias;
    cudaGetSymbolAddress((void**)&X,    g_X);
    cudaGetSymbolAddress((void**)&Wt,   g_Wt);
    cudaGetSymbolAddress((void**)&bias, g_bias);
    cudaGetSymbolAddress((void**)&Qn,   g_Qn);
    cudaGetSymbolAddress((void**)&Sn,   g_Sn);

    cudaFuncSetAttribute(proj_kernel,
                         cudaFuncAttributeMaxDynamicSharedMemorySize, PSMEM);
    cudaFuncSetAttribute(match_kernel,
                         cudaFuncAttributeMaxDynamicSharedMemorySize, SMEMB);

    // 1) fused setup: X convert (2 elems/thread) + tiled weight transpose + bias
    setup_kernel<<<NBTOT, 256>>>(query, support, head_W, head_b, cls_W, cls_b);

    // 2) projection GEMM + fused per-head L2 normalize -> fp16 Qn/Sn
    {
        dim3 grid(HH, MTOTAL / PBM);       // (3, 48) = 144 CTAs
        proj_kernel<<<grid, 512, PSMEM>>>(X, Wt, bias, Qn, Sn);
    }
    // 3) match GEMM (2 M-tiles/CTA) + fused aux cls GEMM
    {
        dim3 grid(NS / BN, NQ / (2 * BM) + 1);   // (16, 17); last y-row = aux
        match_kernel<<<grid, 256, SMEMB>>>(Qn, Sn, out_match, 2,
                                           X + (size_t)NQ * DD, Wt + (size_t)NH * DD,
                                           bias + NH, out_preds, NS / BM);
    }
}